// round 8
// baseline (speedup 1.0000x reference)
#include <cuda_runtime.h>
#include <math.h>
#include <stdint.h>

// Problem constants
#define B_  4
#define S_  256
#define V_  64
#define H_  128
#define NH_ 8
#define DH_ 16
#define LP1_ 11
#define NL_ 3
#define BT_ (B_ * S_)          // 1024
#define ZSZ (BT_ * V_ * H_)

// Scratch (device globals)
__device__ float g_adj[V_ * V_ * LP1_];
__device__ float g_zA[ZSZ];
__device__ float g_qb[ZSZ];
__device__ float g_kb[ZSZ];
__device__ float g_vb[ZSZ];
__device__ float g_ob[ZSZ];

// ---------------------------------------------------------------------------
// f32x2 packed helpers (base sm_100+ PTX; NOT arch-'a'-gated)
// ---------------------------------------------------------------------------
__device__ __forceinline__ void fma2(unsigned long long& d,
                                     unsigned long long a, unsigned long long b) {
    asm("fma.rn.f32x2 %0, %1, %2, %0;" : "+l"(d) : "l"(a), "l"(b));
}
__device__ __forceinline__ unsigned long long dup2(float x) {
    unsigned long long r;
    asm("mov.b64 %0, {%1, %1};" : "=l"(r) : "r"(__float_as_uint(x)));
    return r;
}
__device__ __forceinline__ float lo2(unsigned long long v) {
    return __uint_as_float((uint32_t)v);
}
__device__ __forceinline__ float hi2(unsigned long long v) {
    return __uint_as_float((uint32_t)(v >> 32));
}

// ---------------------------------------------------------------------------
// Kernel 0: adj = sigmoid(adjacency_logits)
// ---------------------------------------------------------------------------
__global__ void sigmoid_kernel(const float* __restrict__ logits) {
    int i = blockIdx.x * 256 + threadIdx.x;
    if (i < V_ * V_ * LP1_) g_adj[i] = 1.0f / (1.0f + __expf(-logits[i]));
}

// ---------------------------------------------------------------------------
// Kernel 1: causal input (f32x2 in the h-expansion loop)
// ---------------------------------------------------------------------------
#define CAU_XW   0
#define CAU_ASM  (CAU_XW + LP1_ * 64)
#define CAU_BL   (CAU_ASM + 64 * 65)
#define CAU_VE   (CAU_BL + 64 * 12)
#define CAU_TE   (CAU_VE + 64 * 128)
#define CAU_SMEM ((CAU_TE + LP1_ * 128) * 4)

__global__ void causal_kernel(const float* __restrict__ x,
                              const float* __restrict__ var_emb,
                              const float* __restrict__ temp_emb,
                              float* __restrict__ zout) {
    extern __shared__ __align__(16) float cs[];
    float* xw  = cs + CAU_XW;
    float* Asm = cs + CAU_ASM;
    float* Bl  = cs + CAU_BL;
    float* ve  = cs + CAU_VE;
    float* te  = cs + CAU_TE;

    int bt = blockIdx.x;
    int b = bt / S_;
    int t = bt % S_;
    int tid = threadIdx.x;

    for (int e = tid; e < LP1_ * 64; e += 256) {
        int l = e >> 6, s2 = e & 63;
        int tt = t - l;
        xw[l * 64 + s2] = (tt >= 0) ? x[(b * S_ + tt) * V_ + s2] : 0.0f;
    }
    for (int e = tid; e < 64 * 128 / 4; e += 256)
        ((float4*)ve)[e] = ((const float4*)var_emb)[e];
    for (int e = tid; e < LP1_ * 128 / 4; e += 256)
        ((float4*)te)[e] = ((const float4*)temp_emb)[e];
    __syncthreads();

    for (int e = tid; e < 64 * 64; e += 256) {
        int i = e >> 6, s2 = e & 63;
        const float* ap = g_adj + (s2 * V_ + i) * LP1_;
        float acc = 0.0f;
#pragma unroll
        for (int l = 0; l < LP1_; l++) acc += xw[l * 64 + s2] * ap[l];
        Asm[i * 65 + s2] = acc;
    }
    for (int e = tid; e < 64 * LP1_; e += 256) {
        int i = e / LP1_, l = e % LP1_;
        float acc = 0.0f;
        for (int s2 = 0; s2 < 64; s2++)
            acc += xw[l * 64 + s2] * g_adj[(s2 * V_ + i) * LP1_ + l];
        Bl[i * 12 + l] = acc;
    }
    __syncthreads();

    int i = tid >> 2, q = tid & 3;
    unsigned long long acc2[8][2];
#pragma unroll
    for (int j = 0; j < 8; j++) { acc2[j][0] = 0ull; acc2[j][1] = 0ull; }

    for (int s2 = 0; s2 < 64; s2++) {
        unsigned long long ad = dup2(Asm[i * 65 + s2]);
        const float* vr = ve + s2 * 128 + q * 4;
#pragma unroll
        for (int j = 0; j < 8; j++) {
            ulonglong2 vv = *(const ulonglong2*)(vr + j * 16);
            fma2(acc2[j][0], ad, vv.x);
            fma2(acc2[j][1], ad, vv.y);
        }
    }
#pragma unroll
    for (int l = 0; l < LP1_; l++) {
        unsigned long long bd = dup2(Bl[i * 12 + l]);
        const float* tr = te + l * 128 + q * 4;
#pragma unroll
        for (int j = 0; j < 8; j++) {
            ulonglong2 vv = *(const ulonglong2*)(tr + j * 16);
            fma2(acc2[j][0], bd, vv.x);
            fma2(acc2[j][1], bd, vv.y);
        }
    }
    float* zr = zout + ((size_t)i * BT_ + bt) * H_ + q * 4;
#pragma unroll
    for (int j = 0; j < 8; j++)
        *(float4*)(zr + j * 16) = make_float4(lo2(acc2[j][0]), hi2(acc2[j][0]),
                                              lo2(acc2[j][1]), hi2(acc2[j][1]));
}

// ---------------------------------------------------------------------------
// Shared GEMM compute: 32-k chunk, f32x2 accumulators paired over rows.
// acc2[r2][j]: rows (ty*8+2*r2, +1), cols (j<4 ? tx*4+j : 64+tx*4+j-4)
// ---------------------------------------------------------------------------
#define AP_ 132

__device__ __forceinline__ void gemm_compute2(const float* __restrict__ Ab,
                                              const float* __restrict__ Wb,
                                              unsigned long long acc2[4][8],
                                              int ty, int tx) {
#pragma unroll 8
    for (int kk = 0; kk < 32; kk++) {
        ulonglong2 a01 = *(const ulonglong2*)(Ab + kk * AP_ + ty * 8);
        ulonglong2 a23 = *(const ulonglong2*)(Ab + kk * AP_ + ty * 8 + 4);
        float4 b0 = *(const float4*)(Wb + kk * 128 + tx * 4);
        float4 b1 = *(const float4*)(Wb + kk * 128 + 64 + tx * 4);
        float bb[8] = {b0.x, b0.y, b0.z, b0.w, b1.x, b1.y, b1.z, b1.w};
#pragma unroll
        for (int j = 0; j < 8; j++) {
            unsigned long long bd = dup2(bb[j]);
            fma2(acc2[0][j], a01.x, bd);
            fma2(acc2[1][j], a01.y, bd);
            fma2(acc2[2][j], a23.x, bd);
            fma2(acc2[3][j], a23.y, bd);
        }
    }
}
__device__ __forceinline__ float acc_get(const unsigned long long acc2[4][8],
                                         int i, int j) {
    return (i & 1) ? hi2(acc2[i >> 1][j]) : lo2(acc2[i >> 1][j]);
}

// ---------------------------------------------------------------------------
// Kernel 2: MEGA — mech0..2 (Linear+LN+GELU) + Q/K/V projections, one launch.
// Block = (bt-tile of 128, v). Activations stay in smem (Zt, transposed [k][m]).
// smem: Zt 128*132 floats + Wbuf 2*32*128 floats = 100352 B  -> 2 CTAs/SM
// ---------------------------------------------------------------------------
#define MEGA_SMEM ((128 * AP_ + 2 * 32 * 128) * 4)

__global__ __launch_bounds__(256, 2) void mega_kernel(
    const float* __restrict__ zin,
    const float* __restrict__ mech_W, const float* __restrict__ mech_b,
    const float* __restrict__ ln_g, const float* __restrict__ ln_b,
    const float* __restrict__ Wq, const float* __restrict__ Wk,
    const float* __restrict__ Wv,
    const float* __restrict__ bq, const float* __restrict__ bk,
    const float* __restrict__ bv,
    float* __restrict__ qb, float* __restrict__ kb, float* __restrict__ vb) {
    extern __shared__ __align__(16) float ms[];
    float* Zt   = ms;                // [128 k][132]
    float* Wbuf = ms + 128 * AP_;    // [2][32][128]

    int tid = threadIdx.x;
    int v = blockIdx.y;
    int bt0 = blockIdx.x * 128;
    int ty = tid >> 4, tx = tid & 15;

    // load input tile transposed into Zt
    const float* inp = zin + ((size_t)v * BT_ + bt0) * H_;
    for (int task = tid; task < 128 * 32; task += 256) {
        int r = task >> 5, c4 = task & 31;
        float4 a = *(const float4*)(inp + (size_t)r * H_ + c4 * 4);
        Zt[(c4 * 4 + 0) * AP_ + r] = a.x;
        Zt[(c4 * 4 + 1) * AP_ + r] = a.y;
        Zt[(c4 * 4 + 2) * AP_ + r] = a.z;
        Zt[(c4 * 4 + 3) * AP_ + r] = a.w;
    }
    __syncthreads();

    for (int layer = 0; layer < 6; layer++) {
        const float* W;
        const float* bias;
        if (layer < 3) {
            W = mech_W + ((size_t)v * NL_ + layer) * H_ * H_;
            bias = mech_b + ((size_t)v * NL_ + layer) * H_;
        } else if (layer == 3) { W = Wq + (size_t)v * H_ * H_; bias = bq + (size_t)v * H_; }
        else if   (layer == 4) { W = Wk + (size_t)v * H_ * H_; bias = bk + (size_t)v * H_; }
        else                   { W = Wv + (size_t)v * H_ * H_; bias = bv + (size_t)v * H_; }

        unsigned long long acc2[4][8];
#pragma unroll
        for (int i = 0; i < 4; i++)
#pragma unroll
            for (int j = 0; j < 8; j++) acc2[i][j] = 0ull;

        float4 lw[4];
        // stage chunk 0
#pragma unroll
        for (int t = 0; t < 4; t++) {
            int idx = tid + t * 256;
            int wr = idx >> 5, wc = idx & 31;
            lw[t] = *(const float4*)(W + (size_t)wr * H_ + wc * 4);
        }
#pragma unroll
        for (int t = 0; t < 4; t++) {
            int idx = tid + t * 256;
            int wr = idx >> 5, wc = idx & 31;
            *(float4*)(Wbuf + wr * 128 + wc * 4) = lw[t];
        }
        __syncthreads();

        for (int c = 0; c < 4; c++) {
            if (c < 3) {
                int k0 = (c + 1) * 32;
#pragma unroll
                for (int t = 0; t < 4; t++) {
                    int idx = tid + t * 256;
                    int wr = idx >> 5, wc = idx & 31;
                    lw[t] = *(const float4*)(W + (size_t)(k0 + wr) * H_ + wc * 4);
                }
            }
            gemm_compute2(Zt + c * 32 * AP_, Wbuf + (c & 1) * 4096, acc2, ty, tx);
            if (c < 3) {
                float* wd = Wbuf + ((c + 1) & 1) * 4096;
#pragma unroll
                for (int t = 0; t < 4; t++) {
                    int idx = tid + t * 256;
                    int wr = idx >> 5, wc = idx & 31;
                    *(float4*)(wd + wr * 128 + wc * 4) = lw[t];
                }
                __syncthreads();
            }
        }
        __syncthreads();  // all reads of Zt/Wbuf done before epilogue writes

        float4 bv0 = *(const float4*)(bias + tx * 4);
        float4 bv1 = *(const float4*)(bias + 64 + tx * 4);
        float bb[8] = {bv0.x, bv0.y, bv0.z, bv0.w, bv1.x, bv1.y, bv1.z, bv1.w};

        if (layer < 3) {
            const float* g  = ln_g + ((size_t)v * NL_ + layer) * H_;
            const float* nb = ln_b + ((size_t)v * NL_ + layer) * H_;
            float4 g0 = *(const float4*)(g + tx * 4);
            float4 g1 = *(const float4*)(g + 64 + tx * 4);
            float4 n0 = *(const float4*)(nb + tx * 4);
            float4 n1 = *(const float4*)(nb + 64 + tx * 4);
            float gv[8] = {g0.x, g0.y, g0.z, g0.w, g1.x, g1.y, g1.z, g1.w};
            float nv[8] = {n0.x, n0.y, n0.z, n0.w, n1.x, n1.y, n1.z, n1.w};
#pragma unroll
            for (int i = 0; i < 8; i++) {
                float vals[8];
                float s = 0.0f;
#pragma unroll
                for (int j = 0; j < 8; j++) {
                    vals[j] = acc_get(acc2, i, j) + bb[j];
                    s += vals[j];
                }
                s += __shfl_xor_sync(0xffffffffu, s, 8);
                s += __shfl_xor_sync(0xffffffffu, s, 4);
                s += __shfl_xor_sync(0xffffffffu, s, 2);
                s += __shfl_xor_sync(0xffffffffu, s, 1);
                float mu = s * (1.0f / H_);
                float sq = 0.0f;
#pragma unroll
                for (int j = 0; j < 8; j++) { vals[j] -= mu; sq += vals[j] * vals[j]; }
                sq += __shfl_xor_sync(0xffffffffu, sq, 8);
                sq += __shfl_xor_sync(0xffffffffu, sq, 4);
                sq += __shfl_xor_sync(0xffffffffu, sq, 2);
                sq += __shfl_xor_sync(0xffffffffu, sq, 1);
                float inv = rsqrtf(sq * (1.0f / H_) + 1e-5f);
#pragma unroll
                for (int j = 0; j < 8; j++) {
                    float t2 = vals[j] * inv * gv[j] + nv[j];
                    t2 = t2 * 0.5f * (1.0f + erff(t2 * 0.70710678118654752f));
                    int col = (j < 4) ? (tx * 4 + j) : (64 + tx * 4 + j - 4);
                    Zt[col * AP_ + ty * 8 + i] = t2;
                }
            }
            __syncthreads();
        } else {
            float* out = (layer == 3) ? qb : (layer == 4) ? kb : vb;
            float* orow = out + ((size_t)v * BT_ + bt0 + ty * 8) * H_;
#pragma unroll
            for (int i = 0; i < 8; i++) {
                float4 o0 = make_float4(acc_get(acc2, i, 0) + bb[0],
                                        acc_get(acc2, i, 1) + bb[1],
                                        acc_get(acc2, i, 2) + bb[2],
                                        acc_get(acc2, i, 3) + bb[3]);
                float4 o1 = make_float4(acc_get(acc2, i, 4) + bb[4],
                                        acc_get(acc2, i, 5) + bb[5],
                                        acc_get(acc2, i, 6) + bb[6],
                                        acc_get(acc2, i, 7) + bb[7]);
                *(float4*)(orow + (size_t)i * H_ + tx * 4) = o0;
                *(float4*)(orow + (size_t)i * H_ + 64 + tx * 4) = o1;
            }
        }
    }
}

// ---------------------------------------------------------------------------
// Kernel 2b: Wo GEMM + fused output head (f32x2 compute)
// ---------------------------------------------------------------------------
#define ABUF (32 * AP_)
#define WBUF (32 * 128)
#define GEMM_SMEM ((2 * ABUF + 2 * WBUF) * 4)

__global__ __launch_bounds__(256, 2) void wo_head_kernel(
    const float* __restrict__ in, const float* __restrict__ Wo,
    const float* __restrict__ bo,
    const float* __restrict__ OW, const float* __restrict__ OB,
    float* __restrict__ PRED) {
    extern __shared__ __align__(16) float sm[];
    float* Ast = sm;
    float* Wsm = sm + 2 * ABUF;

    int tid = threadIdx.x;
    int v = blockIdx.y;
    int bt0 = blockIdx.x * 128;
    const float* W = Wo + (size_t)v * H_ * H_;
    const float* inp = in + ((size_t)v * BT_ + bt0) * H_;
    int ty = tid >> 4, tx = tid & 15;

    unsigned long long acc2[4][8];
#pragma unroll
    for (int i = 0; i < 4; i++)
#pragma unroll
        for (int j = 0; j < 8; j++) acc2[i][j] = 0ull;

    float4 la[4], lw[4];
#pragma unroll
    for (int t = 0; t < 4; t++) {
        int idx = tid + t * 256;
        int r = idx >> 3, c4 = idx & 7;
        la[t] = *(const float4*)(inp + (size_t)r * H_ + c4 * 4);
        int wr = idx >> 5, wc = idx & 31;
        lw[t] = *(const float4*)(W + (size_t)wr * H_ + wc * 4);
    }
#pragma unroll
    for (int t = 0; t < 4; t++) {
        int idx = tid + t * 256;
        int r = idx >> 3, c4 = idx & 7;
        Ast[(c4 * 4 + 0) * AP_ + r] = la[t].x;
        Ast[(c4 * 4 + 1) * AP_ + r] = la[t].y;
        Ast[(c4 * 4 + 2) * AP_ + r] = la[t].z;
        Ast[(c4 * 4 + 3) * AP_ + r] = la[t].w;
        int wr = idx >> 5, wc = idx & 31;
        *(float4*)(Wsm + wr * 128 + wc * 4) = lw[t];
    }
    __syncthreads();

    for (int c = 0; c < 4; c++) {
        if (c < 3) {
            int k0 = (c + 1) * 32;
#pragma unroll
            for (int t = 0; t < 4; t++) {
                int idx = tid + t * 256;
                int r = idx >> 3, c4 = idx & 7;
                la[t] = *(const float4*)(inp + (size_t)r * H_ + k0 + c4 * 4);
                int wr = idx >> 5, wc = idx & 31;
                lw[t] = *(const float4*)(W + (size_t)(k0 + wr) * H_ + wc * 4);
            }
        }
        gemm_compute2(Ast + (c & 1) * ABUF, Wsm + (c & 1) * WBUF, acc2, ty, tx);
        if (c < 3) {
            float* ad = Ast + ((c + 1) & 1) * ABUF;
            float* wd = Wsm + ((c + 1) & 1) * WBUF;
#pragma unroll
            for (int t = 0; t < 4; t++) {
                int idx = tid + t * 256;
                int r = idx >> 3, c4 = idx & 7;
                ad[(c4 * 4 + 0) * AP_ + r] = la[t].x;
                ad[(c4 * 4 + 1) * AP_ + r] = la[t].y;
                ad[(c4 * 4 + 2) * AP_ + r] = la[t].z;
                ad[(c4 * 4 + 3) * AP_ + r] = la[t].w;
                int wr = idx >> 5, wc = idx & 31;
                *(float4*)(wd + wr * 128 + wc * 4) = lw[t];
            }
            __syncthreads();
        }
    }

    const float* bias = bo + (size_t)v * H_;
    float4 bv0 = *(const float4*)(bias + tx * 4);
    float4 bv1 = *(const float4*)(bias + 64 + tx * 4);
    float bb[8] = {bv0.x, bv0.y, bv0.z, bv0.w, bv1.x, bv1.y, bv1.z, bv1.w};
    float4 w0 = *(const float4*)(OW + (size_t)v * H_ + tx * 4);
    float4 w1 = *(const float4*)(OW + (size_t)v * H_ + 64 + tx * 4);
    float ow[8] = {w0.x, w0.y, w0.z, w0.w, w1.x, w1.y, w1.z, w1.w};
    float ob = OB[v];
#pragma unroll
    for (int i = 0; i < 8; i++) {
        float s = 0.0f;
#pragma unroll
        for (int j = 0; j < 8; j++)
            s += (acc_get(acc2, i, j) + bb[j]) * ow[j];
        s += __shfl_xor_sync(0xffffffffu, s, 8);
        s += __shfl_xor_sync(0xffffffffu, s, 4);
        s += __shfl_xor_sync(0xffffffffu, s, 2);
        s += __shfl_xor_sync(0xffffffffu, s, 1);
        if (tx == 0) PRED[(size_t)(bt0 + ty * 8 + i) * V_ + v] = s + ob;
    }
}

// ---------------------------------------------------------------------------
// Kernel 3: attention (R6 structure; AV loop uses f32x2)
// ---------------------------------------------------------------------------
#define KTP 260
#define ATTN_SMEM ((S_ * DH_ + 2 * DH_ * KTP + 8 * 4 * KTP) * 4)

__global__ __launch_bounds__(256, 2) void attn_kernel(
        const float* __restrict__ qg,
        const float* __restrict__ kg,
        const float* __restrict__ vg,
        float* __restrict__ og) {
    int id = blockIdx.x;
    int n  = id % NH_;
    int vv = (id / NH_) % V_;
    int b  = id / (NH_ * V_);
    int tid = threadIdx.x;

    extern __shared__ __align__(16) float asm_[];
    float* qs = asm_;
    float* kT = qs + S_ * DH_;
    float* vT = kT + DH_ * KTP;
    float* ps = vT + DH_ * KTP;

    size_t base = ((size_t)vv * BT_ + b * S_) * H_ + n * DH_;

    for (int e = tid; e < S_ * DH_; e += 256) {
        int t = e >> 4, d = e & 15;
        size_t g = base + (size_t)t * H_ + d;
        qs[t * DH_ + d] = qg[g];
        kT[d * KTP + t] = kg[g];
        vT[d * KTP + t] = vg[g];
    }
    __syncthreads();

    int w = tid >> 5, lane = tid & 31;
    float* psw = ps + w * 4 * KTP;

    for (int pass = 0; pass < 8; pass++) {
        int r0 = pass * 32 + w * 4;

        float acc[4][8];
#pragma unroll
        for (int i = 0; i < 4; i++)
#pragma unroll
            for (int j = 0; j < 8; j++) acc[i][j] = 0.0f;

#pragma unroll
        for (int d = 0; d < DH_; d++) {
            float kreg[8];
            const float* kr = kT + d * KTP + lane;
#pragma unroll
            for (int j = 0; j < 8; j++) kreg[j] = kr[j * 32];
            float q0 = qs[(r0 + 0) * DH_ + d];
            float q1 = qs[(r0 + 1) * DH_ + d];
            float q2 = qs[(r0 + 2) * DH_ + d];
            float q3 = qs[(r0 + 3) * DH_ + d];
#pragma unroll
            for (int j = 0; j < 8; j++) {
                acc[0][j] += q0 * kreg[j];
                acc[1][j] += q1 * kreg[j];
                acc[2][j] += q2 * kreg[j];
                acc[3][j] += q3 * kreg[j];
            }
        }

        float invs[4];
#pragma unroll
        for (int i = 0; i < 4; i++) {
            float m = acc[i][0];
#pragma unroll
            for (int j = 1; j < 8; j++) m = fmaxf(m, acc[i][j]);
            m *= 0.25f;
#pragma unroll
            for (int off = 16; off; off >>= 1)
                m = fmaxf(m, __shfl_xor_sync(0xffffffffu, m, off));
            float lsum = 0.0f;
            float p[8];
#pragma unroll
            for (int j = 0; j < 8; j++) {
                p[j] = __expf(acc[i][j] * 0.25f - m);
                lsum += p[j];
            }
#pragma unroll
            for (int off = 16; off; off >>= 1)
                lsum += __shfl_xor_sync(0xffffffffu, lsum, off);
            invs[i] = 1.0f / lsum;
            float* prow = psw + i * KTP + lane;
#pragma unroll
            for (int j = 0; j < 8; j++) prow[j * 32] = p[j];
        }
        __syncwarp();

        int d = lane & 15;
        int half = lane >> 4;
        const float* vrow = vT + d * KTP + half * 128;
        const float* p0 = psw + 0 * KTP + half * 128;
        const float* p1 = psw + 1 * KTP + half * 128;
        const float* p2 = psw + 2 * KTP + half * 128;
        const float* p3 = psw + 3 * KTP + half * 128;
        unsigned long long oa0 = 0ull, ob0 = 0ull, oa1 = 0ull, ob1 = 0ull;
        unsigned long long oa2 = 0ull, ob2 = 0ull, oa3 = 0ull, ob3 = 0ull;
#pragma unroll 8
        for (int it = 0; it < 32; it++) {
            ulonglong2 vv4 = *(const ulonglong2*)(vrow + it * 4);
            ulonglong2 a0 = *(const ulonglong2*)(p0 + it * 4);
            ulonglong2 a1 = *(const ulonglong2*)(p1 + it * 4);
            ulonglong2 a2 = *(const ulonglong2*)(p2 + it * 4);
            ulonglong2 a3 = *(const ulonglong2*)(p3 + it * 4);
            fma2(oa0, a0.x, vv4.x); fma2(ob0, a0.y, vv4.y);
            fma2(oa1, a1.x, vv4.x); fma2(ob1, a1.y, vv4.y);
            fma2(oa2, a2.x, vv4.x); fma2(ob2, a2.y, vv4.y);
            fma2(oa3, a3.x, vv4.x); fma2(ob3, a3.y, vv4.y);
        }
        float o0 = lo2(oa0) + hi2(oa0) + lo2(ob0) + hi2(ob0);
        float o1 = lo2(oa1) + hi2(oa1) + lo2(ob1) + hi2(ob1);
        float o2 = lo2(oa2) + hi2(oa2) + lo2(ob2) + hi2(ob2);
        float o3 = lo2(oa3) + hi2(oa3) + lo2(ob3) + hi2(ob3);
        o0 += __shfl_xor_sync(0xffffffffu, o0, 16);
        o1 += __shfl_xor_sync(0xffffffffu, o1, 16);
        o2 += __shfl_xor_sync(0xffffffffu, o2, 16);
        o3 += __shfl_xor_sync(0xffffffffu, o3, 16);
        if (lane < 16) {
            og[base + (size_t)(r0 + 0) * H_ + d] = o0 * invs[0];
            og[base + (size_t)(r0 + 1) * H_ + d] = o1 * invs[1];
            og[base + (size_t)(r0 + 2) * H_ + d] = o2 * invs[2];
            og[base + (size_t)(r0 + 3) * H_ + d] = o3 * invs[3];
        }
        __syncwarp();
    }
}

// ---------------------------------------------------------------------------
// Launch
// ---------------------------------------------------------------------------
extern "C" void kernel_launch(void* const* d_in, const int* in_sizes, int n_in,
                              void* d_out, int out_size) {
    const float* x       = (const float*)d_in[0];
    const float* adj_l   = (const float*)d_in[1];
    const float* var_emb = (const float*)d_in[2];
    const float* temp_emb= (const float*)d_in[3];
    const float* mech_W  = (const float*)d_in[4];
    const float* mech_b  = (const float*)d_in[5];
    const float* ln_g    = (const float*)d_in[6];
    const float* ln_b    = (const float*)d_in[7];
    const float* Wq      = (const float*)d_in[8];
    const float* Wk      = (const float*)d_in[9];
    const float* Wv      = (const float*)d_in[10];
    const float* Wo      = (const float*)d_in[11];
    const float* bq      = (const float*)d_in[12];
    const float* bk      = (const float*)d_in[13];
    const float* bv      = (const float*)d_in[14];
    const float* bo      = (const float*)d_in[15];
    const float* out_W   = (const float*)d_in[16];
    const float* out_b   = (const float*)d_in[17];
    float* pred = (float*)d_out;

    float *zA, *qb, *kb, *vb, *ob;
    cudaGetSymbolAddress((void**)&zA, g_zA);
    cudaGetSymbolAddress((void**)&qb, g_qb);
    cudaGetSymbolAddress((void**)&kb, g_kb);
    cudaGetSymbolAddress((void**)&vb, g_vb);
    cudaGetSymbolAddress((void**)&ob, g_ob);

    cudaFuncSetAttribute((const void*)mega_kernel,
                         cudaFuncAttributeMaxDynamicSharedMemorySize, MEGA_SMEM);
    cudaFuncSetAttribute((const void*)wo_head_kernel,
                         cudaFuncAttributeMaxDynamicSharedMemorySize, GEMM_SMEM);
    cudaFuncSetAttribute((const void*)causal_kernel,
                         cudaFuncAttributeMaxDynamicSharedMemorySize, CAU_SMEM);
    cudaFuncSetAttribute((const void*)attn_kernel,
                         cudaFuncAttributeMaxDynamicSharedMemorySize, ATTN_SMEM);

    // 0. sigmoid(adjacency)
    sigmoid_kernel<<<(V_ * V_ * LP1_ + 255) / 256, 256>>>(adj_l);

    // 1. causal input -> zA ([v][bt][h])
    causal_kernel<<<BT_, 256, CAU_SMEM>>>(x, var_emb, temp_emb, zA);

    // 2. mega: mech x3 + QKV, activations resident in smem
    dim3 mgrid(BT_ / 128, V_);
    mega_kernel<<<mgrid, 256, MEGA_SMEM>>>(zA,
        mech_W, mech_b, ln_g, ln_b, Wq, Wk, Wv, bq, bk, bv, qb, kb, vb);

    // 3. attention -> ob
    attn_kernel<<<B_ * V_ * NH_, 256, ATTN_SMEM>>>(qb, kb, vb, ob);

    // 4. Wo + output head -> pred
    wo_head_kernel<<<mgrid, 256, GEMM_SMEM>>>(ob, Wo, bo, out_W, out_b, pred);
}

// round 9
// speedup vs baseline: 1.3662x; 1.3662x over previous
#include <cuda_runtime.h>
#include <cuda_bf16.h>
#include <math.h>
#include <stdint.h>

// Problem constants
#define B_  4
#define S_  256
#define V_  64
#define H_  128
#define NH_ 8
#define DH_ 16
#define LP1_ 11
#define NL_ 3
#define BT_ (B_ * S_)          // 1024
#define ZSZ (BT_ * V_ * H_)

// Scratch (device globals)
__device__ float g_adj[V_ * V_ * LP1_];
__device__ float g_zA[ZSZ];
__device__ float g_qb[ZSZ];
__device__ float g_kb[ZSZ];
__device__ float g_vb[ZSZ];
__device__ float g_ob[ZSZ];
// Pre-split weights: [pass 0..6][v] -> {hi[128][136], lo[128][136]} bf16, B-layout [n][k]
#define WCROW 136
#define WCBLK (2 * 128 * WCROW)      // bf16 elements per (pass,v)
__device__ __align__(128) __nv_bfloat16 g_Wc[7 * V_ * WCBLK];

extern __shared__ char SM[];

// ---------------------------------------------------------------------------
// mma.sync / ldmatrix helpers (sm_80+ baseline PTX, legal on sm_103)
// ---------------------------------------------------------------------------
__device__ __forceinline__ uint32_t smem_u32(const void* p) {
    uint32_t a;
    asm("{ .reg .u64 t; cvta.to.shared.u64 t, %1; cvt.u32.u64 %0, t; }"
        : "=r"(a) : "l"(p));
    return a;
}
__device__ __forceinline__ void ldsm4(uint32_t& r0, uint32_t& r1,
                                      uint32_t& r2, uint32_t& r3, uint32_t addr) {
    asm volatile("ldmatrix.sync.aligned.m8n8.x4.shared.b16 {%0,%1,%2,%3}, [%4];"
                 : "=r"(r0), "=r"(r1), "=r"(r2), "=r"(r3) : "r"(addr));
}
__device__ __forceinline__ void mma16816(float* c, const uint32_t a[4],
                                         uint32_t b0, uint32_t b1) {
    asm volatile(
        "mma.sync.aligned.m16n8k16.row.col.f32.bf16.bf16.f32 "
        "{%0,%1,%2,%3}, {%4,%5,%6,%7}, {%8,%9}, {%0,%1,%2,%3};"
        : "+f"(c[0]), "+f"(c[1]), "+f"(c[2]), "+f"(c[3])
        : "r"(a[0]), "r"(a[1]), "r"(a[2]), "r"(a[3]), "r"(b0), "r"(b1));
}

// ---------------------------------------------------------------------------
// Kernel 0: adj = sigmoid(adjacency_logits)
// ---------------------------------------------------------------------------
__global__ void sigmoid_kernel(const float* __restrict__ logits) {
    int i = blockIdx.x * 256 + threadIdx.x;
    if (i < V_ * V_ * LP1_) g_adj[i] = 1.0f / (1.0f + __expf(-logits[i]));
}

// ---------------------------------------------------------------------------
// Kernel P: split weights into bf16 hi/lo, transposed to B-layout [n][k], pad 136.
// One block per (pass, v). smem: Wt[128][132] fp32 = 67584 B.
// ---------------------------------------------------------------------------
#define PREP_SMEM (128 * 132 * 4)
__global__ void prep_w_kernel(const float* __restrict__ mech_W,
                              const float* __restrict__ Wq,
                              const float* __restrict__ Wk,
                              const float* __restrict__ Wv,
                              const float* __restrict__ Wo) {
    float* Wt = (float*)SM;
    int pv = blockIdx.x;
    int pass = pv >> 6, v = pv & 63;
    const float* src;
    if (pass < 3)       src = mech_W + ((size_t)v * NL_ + pass) * H_ * H_;
    else if (pass == 3) src = Wq + (size_t)v * H_ * H_;
    else if (pass == 4) src = Wk + (size_t)v * H_ * H_;
    else if (pass == 5) src = Wv + (size_t)v * H_ * H_;
    else                src = Wo + (size_t)v * H_ * H_;

    int tid = threadIdx.x;
    for (int i = tid; i < 128 * 32; i += 256) {
        int r = i >> 5, c4 = i & 31;
        float4 a = *(const float4*)(src + (size_t)r * H_ + c4 * 4);
        *(float4*)(Wt + r * 132 + c4 * 4) = a;
    }
    __syncthreads();

    __nv_bfloat16* dhi = g_Wc + (size_t)pv * WCBLK;
    __nv_bfloat16* dlo = dhi + 128 * WCROW;
    for (int task = tid; task < 128 * 64; task += 256) {
        int n = task >> 6, kp = task & 63;
        float w0 = Wt[(2 * kp) * 132 + n];
        float w1 = Wt[(2 * kp + 1) * 132 + n];
        __nv_bfloat16 h0 = __float2bfloat16(w0), h1 = __float2bfloat16(w1);
        float r0 = w0 - __bfloat162float(h0), r1 = w1 - __bfloat162float(h1);
        *(__nv_bfloat162*)(dhi + n * WCROW + 2 * kp) = __halves2bfloat162(h0, h1);
        *(__nv_bfloat162*)(dlo + n * WCROW + 2 * kp) =
            __halves2bfloat162(__float2bfloat16(r0), __float2bfloat16(r1));
    }
}

// ---------------------------------------------------------------------------
// Kernel 1: causal input (R6 scalar version)
// ---------------------------------------------------------------------------
#define CAU_XW   0
#define CAU_ASM  (CAU_XW + LP1_ * 64)
#define CAU_BL   (CAU_ASM + 64 * 65)
#define CAU_VE   (CAU_BL + 64 * 12)
#define CAU_TE   (CAU_VE + 64 * 128)
#define CAU_SMEM ((CAU_TE + LP1_ * 128) * 4)

__global__ void causal_kernel(const float* __restrict__ x,
                              const float* __restrict__ var_emb,
                              const float* __restrict__ temp_emb,
                              float* __restrict__ zout) {
    float* cs = (float*)SM;
    float* xw  = cs + CAU_XW;
    float* Asm = cs + CAU_ASM;
    float* Bl  = cs + CAU_BL;
    float* ve  = cs + CAU_VE;
    float* te  = cs + CAU_TE;

    int bt = blockIdx.x;
    int b = bt / S_;
    int t = bt % S_;
    int tid = threadIdx.x;

    for (int e = tid; e < LP1_ * 64; e += 256) {
        int l = e >> 6, s2 = e & 63;
        int tt = t - l;
        xw[l * 64 + s2] = (tt >= 0) ? x[(b * S_ + tt) * V_ + s2] : 0.0f;
    }
    for (int e = tid; e < 64 * 128 / 4; e += 256)
        ((float4*)ve)[e] = ((const float4*)var_emb)[e];
    for (int e = tid; e < LP1_ * 128 / 4; e += 256)
        ((float4*)te)[e] = ((const float4*)temp_emb)[e];
    __syncthreads();

    for (int e = tid; e < 64 * 64; e += 256) {
        int i = e >> 6, s2 = e & 63;
        const float* ap = g_adj + (s2 * V_ + i) * LP1_;
        float acc = 0.0f;
#pragma unroll
        for (int l = 0; l < LP1_; l++) acc += xw[l * 64 + s2] * ap[l];
        Asm[i * 65 + s2] = acc;
    }
    for (int e = tid; e < 64 * LP1_; e += 256) {
        int i = e / LP1_, l = e % LP1_;
        float acc = 0.0f;
        for (int s2 = 0; s2 < 64; s2++)
            acc += xw[l * 64 + s2] * g_adj[(s2 * V_ + i) * LP1_ + l];
        Bl[i * 12 + l] = acc;
    }
    __syncthreads();

    int i = tid >> 2, q = tid & 3;
    float4 acc[8];
#pragma unroll
    for (int j = 0; j < 8; j++) acc[j] = make_float4(0.f, 0.f, 0.f, 0.f);

    for (int s2 = 0; s2 < 64; s2++) {
        float a = Asm[i * 65 + s2];
        const float* vr = ve + s2 * 128 + q * 4;
#pragma unroll
        for (int j = 0; j < 8; j++) {
            float4 vv = *(const float4*)(vr + j * 16);
            acc[j].x += a * vv.x; acc[j].y += a * vv.y;
            acc[j].z += a * vv.z; acc[j].w += a * vv.w;
        }
    }
#pragma unroll
    for (int l = 0; l < LP1_; l++) {
        float bl = Bl[i * 12 + l];
        const float* tr = te + l * 128 + q * 4;
#pragma unroll
        for (int j = 0; j < 8; j++) {
            float4 vv = *(const float4*)(tr + j * 16);
            acc[j].x += bl * vv.x; acc[j].y += bl * vv.y;
            acc[j].z += bl * vv.z; acc[j].w += bl * vv.w;
        }
    }
    float* zr = zout + ((size_t)i * BT_ + bt) * H_ + q * 4;
#pragma unroll
    for (int j = 0; j < 8; j++) *(float4*)(zr + j * 16) = acc[j];
}

// ---------------------------------------------------------------------------
// Kernel 2: tensor-core GEMM via mma.sync bf16, 3-term hi/lo split.
// Block = (128 bt-rows, v [, z]).  256 thr = 8 warps, warp grid 4m x 2n.
// smem bytes: Ahi 34816 | Alo 34816 | Bhi 34816 | Blo 34816 = 139264.
// Dsm (fp32 128x132 = 67584) aliases Ahi+Alo after the k-loop.
// MODE 0: +bias (QKV via z)   MODE 1: +bias,LN,GELU   MODE 2: +bias, out-head
// ---------------------------------------------------------------------------
#define APITCH 272               // bytes per 128-elem bf16 row (136 elems)
#define OFF_AHI 0
#define OFF_ALO 34816
#define OFF_BHI 69632
#define OFF_BLO 104448
#define MMA_SMEM 139264
#define DPITCH 132

template <int MODE>
__global__ __launch_bounds__(256) void gemm_mma(
    const float* __restrict__ in, int passbase,
    const float* __restrict__ Bi0, const float* __restrict__ Bi1,
    const float* __restrict__ Bi2, int bstride,
    const float* __restrict__ G, const float* __restrict__ NB,
    float* O0, float* O1, float* O2,
    const float* __restrict__ OW, const float* __restrict__ OB,
    float* PRED) {
    char* smc = SM;
    uint32_t sb = smem_u32(smc);
    int tid = threadIdx.x;
    int v = blockIdx.y;
    int bt0 = blockIdx.x * 128;
    int z = blockIdx.z;

    const float* bias = (z == 0 ? Bi0 : (z == 1 ? Bi1 : Bi2)) + (size_t)v * bstride;
    float* out = (z == 0 ? O0 : (z == 1 ? O1 : O2));

    // --- stage A: fp32 -> bf16 hi/lo ---
    const float* inp = in + ((size_t)v * BT_ + bt0) * H_;
    for (int i = tid; i < 128 * 32; i += 256) {
        int r = i >> 5, c4 = i & 31;
        float4 a = *(const float4*)(inp + (size_t)r * H_ + c4 * 4);
        __nv_bfloat16 h0 = __float2bfloat16(a.x), h1 = __float2bfloat16(a.y);
        __nv_bfloat16 h2 = __float2bfloat16(a.z), h3 = __float2bfloat16(a.w);
        __nv_bfloat162 hp0 = __halves2bfloat162(h0, h1);
        __nv_bfloat162 hp1 = __halves2bfloat162(h2, h3);
        __nv_bfloat162 lp0 = __halves2bfloat162(
            __float2bfloat16(a.x - __bfloat162float(h0)),
            __float2bfloat16(a.y - __bfloat162float(h1)));
        __nv_bfloat162 lp1 = __halves2bfloat162(
            __float2bfloat16(a.z - __bfloat162float(h2)),
            __float2bfloat16(a.w - __bfloat162float(h3)));
        uint32_t off = (uint32_t)r * APITCH + c4 * 8;
        *(uint2*)(smc + OFF_AHI + off) =
            make_uint2(*(uint32_t*)&hp0, *(uint32_t*)&hp1);
        *(uint2*)(smc + OFF_ALO + off) =
            make_uint2(*(uint32_t*)&lp0, *(uint32_t*)&lp1);
    }
    // --- stage B: copy pre-split weight image (hi, then lo) ---
    {
        const uint4* wsrc = (const uint4*)(g_Wc + (size_t)((passbase + z) * V_ + v) * WCBLK);
        uint4* wdst = (uint4*)(smc + OFF_BHI);
        for (int i = tid; i < 4352; i += 256) wdst[i] = wsrc[i];
    }
    __syncthreads();

    // --- mma mainloop ---
    int wid = tid >> 5, lane = tid & 31;
    int wm = wid & 3, wn = wid >> 2;           // warp tile: rows wm*32, cols wn*64
    int lr = lane & 7, lsel = (lane >> 3) & 1, khalf = lane >> 4;

    // ldmatrix address offsets (bytes, within a tile base)
    uint32_t aoff[2], boff[4];
#pragma unroll
    for (int mt = 0; mt < 2; mt++)
        aoff[mt] = (uint32_t)(wm * 32 + mt * 16 + lr + lsel * 8) * APITCH + khalf * 16;
#pragma unroll
    for (int q = 0; q < 4; q++)
        boff[q] = (uint32_t)(wn * 64 + q * 16 + lr + khalf * 8) * APITCH + lsel * 16;

    float c[2][8][4];
#pragma unroll
    for (int mt = 0; mt < 2; mt++)
#pragma unroll
        for (int nt = 0; nt < 8; nt++)
#pragma unroll
            for (int e = 0; e < 4; e++) c[mt][nt][e] = 0.0f;

#pragma unroll
    for (int s = 0; s < 8; s++) {
        uint32_t kb = 32u * s;
        uint32_t ah[2][4], al[2][4];
#pragma unroll
        for (int mt = 0; mt < 2; mt++) {
            ldsm4(ah[mt][0], ah[mt][1], ah[mt][2], ah[mt][3],
                  sb + OFF_AHI + aoff[mt] + kb);
            ldsm4(al[mt][0], al[mt][1], al[mt][2], al[mt][3],
                  sb + OFF_ALO + aoff[mt] + kb);
        }
#pragma unroll
        for (int q = 0; q < 4; q++) {
            uint32_t bh[4], bl[4];
            ldsm4(bh[0], bh[1], bh[2], bh[3], sb + OFF_BHI + boff[q] + kb);
            ldsm4(bl[0], bl[1], bl[2], bl[3], sb + OFF_BLO + boff[q] + kb);
#pragma unroll
            for (int mt = 0; mt < 2; mt++) {
                mma16816(c[mt][2 * q + 0], ah[mt], bh[0], bh[1]);
                mma16816(c[mt][2 * q + 1], ah[mt], bh[2], bh[3]);
                mma16816(c[mt][2 * q + 0], ah[mt], bl[0], bl[1]);
                mma16816(c[mt][2 * q + 1], ah[mt], bl[2], bl[3]);
                mma16816(c[mt][2 * q + 0], al[mt], bh[0], bh[1]);
                mma16816(c[mt][2 * q + 1], al[mt], bh[2], bh[3]);
            }
        }
    }
    __syncthreads();   // A/B smem dead; Dsm aliases it

    // --- stage D to smem ---
    float* Dsm = (float*)smc;
    {
        int g = lane >> 2, tg = lane & 3;
#pragma unroll
        for (int mt = 0; mt < 2; mt++) {
            int r = wm * 32 + mt * 16 + g;
#pragma unroll
            for (int nt = 0; nt < 8; nt++) {
                int col = wn * 64 + nt * 8 + 2 * tg;
                *(float2*)(Dsm + r * DPITCH + col) =
                    make_float2(c[mt][nt][0], c[mt][nt][1]);
                *(float2*)(Dsm + (r + 8) * DPITCH + col) =
                    make_float2(c[mt][nt][2], c[mt][nt][3]);
            }
        }
    }
    __syncthreads();

    // --- epilogue ---
    if (MODE == 0) {
        for (int i = tid; i < 128 * 32; i += 256) {
            int r = i >> 5, c4 = i & 31;
            float4 d = *(float4*)(Dsm + r * DPITCH + c4 * 4);
            float4 b4 = *(const float4*)(bias + c4 * 4);
            d.x += b4.x; d.y += b4.y; d.z += b4.z; d.w += b4.w;
            *(float4*)(out + ((size_t)v * BT_ + bt0 + r) * H_ + c4 * 4) = d;
        }
    } else if (MODE == 1) {
        const float* g  = G  + (size_t)v * bstride;
        const float* nb = NB + (size_t)v * bstride;
        float4 b4 = *(const float4*)(bias + lane * 4);
        float4 g4 = *(const float4*)(g + lane * 4);
        float4 n4 = *(const float4*)(nb + lane * 4);
        float* orowbase = out + ((size_t)v * BT_ + bt0) * H_;
        for (int r = wid * 16; r < wid * 16 + 16; r++) {
            float4 vals = *(float4*)(Dsm + r * DPITCH + lane * 4);
            vals.x += b4.x; vals.y += b4.y; vals.z += b4.z; vals.w += b4.w;
            float s = vals.x + vals.y + vals.z + vals.w;
#pragma unroll
            for (int off = 16; off; off >>= 1) s += __shfl_xor_sync(~0u, s, off);
            float mu = s * (1.0f / H_);
            float d0 = vals.x - mu, d1 = vals.y - mu, d2 = vals.z - mu, d3 = vals.w - mu;
            float sq = d0 * d0 + d1 * d1 + d2 * d2 + d3 * d3;
#pragma unroll
            for (int off = 16; off; off >>= 1) sq += __shfl_xor_sync(~0u, sq, off);
            float inv = rsqrtf(sq * (1.0f / H_) + 1e-5f);
            float y0 = d0 * inv * g4.x + n4.x;
            float y1 = d1 * inv * g4.y + n4.y;
            float y2 = d2 * inv * g4.z + n4.z;
            float y3 = d3 * inv * g4.w + n4.w;
            y0 = y0 * 0.5f * (1.0f + erff(y0 * 0.70710678118654752f));
            y1 = y1 * 0.5f * (1.0f + erff(y1 * 0.70710678118654752f));
            y2 = y2 * 0.5f * (1.0f + erff(y2 * 0.70710678118654752f));
            y3 = y3 * 0.5f * (1.0f + erff(y3 * 0.70710678118654752f));
            *(float4*)(orowbase + (size_t)r * H_ + lane * 4) =
                make_float4(y0, y1, y2, y3);
        }
    } else {  // MODE 2: fused output head
        float4 b4 = *(const float4*)(bias + lane * 4);
        float4 w4 = *(const float4*)(OW + (size_t)v * H_ + lane * 4);
        float ob = OB[v];
        for (int r = wid * 16; r < wid * 16 + 16; r++) {
            float4 vals = *(float4*)(Dsm + r * DPITCH + lane * 4);
            float s = (vals.x + b4.x) * w4.x + (vals.y + b4.y) * w4.y
                    + (vals.z + b4.z) * w4.z + (vals.w + b4.w) * w4.w;
#pragma unroll
            for (int off = 16; off; off >>= 1) s += __shfl_xor_sync(~0u, s, off);
            if (lane == 0) PRED[(size_t)(bt0 + r) * V_ + v] = s + ob;
        }
    }
}

// ---------------------------------------------------------------------------
// Kernel 3: attention (R6 scalar version, conflict-free)
// ---------------------------------------------------------------------------
#define KTP 260
#define ATTN_SMEM ((S_ * DH_ + 2 * DH_ * KTP + 8 * 4 * KTP) * 4)

__global__ __launch_bounds__(256, 2) void attn_kernel(
        const float* __restrict__ qg,
        const float* __restrict__ kg,
        const float* __restrict__ vg,
        float* __restrict__ og) {
    float* asm_ = (float*)SM;
    int id = blockIdx.x;
    int n  = id % NH_;
    int vv = (id / NH_) % V_;
    int b  = id / (NH_ * V_);
    int tid = threadIdx.x;

    float* qs = asm_;
    float* kT = qs + S_ * DH_;
    float* vT = kT + DH_ * KTP;
    float* ps = vT + DH_ * KTP;

    size_t base = ((size_t)vv * BT_ + b * S_) * H_ + n * DH_;

    for (int e = tid; e < S_ * DH_; e += 256) {
        int t = e >> 4, d = e & 15;
        size_t g = base + (size_t)t * H_ + d;
        qs[t * DH_ + d] = qg[g];
        kT[d * KTP + t] = kg[g];
        vT[d * KTP + t] = vg[g];
    }
    __syncthreads();

    int w = tid >> 5, lane = tid & 31;
    float* psw = ps + w * 4 * KTP;

    for (int pass = 0; pass < 8; pass++) {
        int r0 = pass * 32 + w * 4;

        float acc[4][8];
#pragma unroll
        for (int i = 0; i < 4; i++)
#pragma unroll
            for (int j = 0; j < 8; j++) acc[i][j] = 0.0f;

#pragma unroll
        for (int d = 0; d < DH_; d++) {
            float kreg[8];
            const float* kr = kT + d * KTP + lane;
#pragma unroll
            for (int j = 0; j < 8; j++) kreg[j] = kr[j * 32];
            float q0 = qs[(r0 + 0) * DH_ + d];
            float q1 = qs[(r0 + 1) * DH_ + d];
            float q2 = qs[(r0 + 2) * DH_ + d];
            float q3 = qs[(r0 + 3) * DH_ + d];
#pragma unroll
            for (int j = 0; j < 8; j++) {
                acc[0][j] += q0 * kreg[j];
                acc[1][j] += q1 * kreg[j];
                acc[2][j] += q2 * kreg[j];
                acc[3][j] += q3 * kreg[j];
            }
        }

        float invs[4];
#pragma unroll
        for (int i = 0; i < 4; i++) {
            float m = acc[i][0];
#pragma unroll
            for (int j = 1; j < 8; j++) m = fmaxf(m, acc[i][j]);
            m *= 0.25f;
#pragma unroll
            for (int off = 16; off; off >>= 1)
                m = fmaxf(m, __shfl_xor_sync(0xffffffffu, m, off));
            float lsum = 0.0f;
            float p[8];
#pragma unroll
            for (int j = 0; j < 8; j++) {
                p[j] = __expf(acc[i][j] * 0.25f - m);
                lsum += p[j];
            }
#pragma unroll
            for (int off = 16; off; off >>= 1)
                lsum += __shfl_xor_sync(0xffffffffu, lsum, off);
            invs[i] = 1.0f / lsum;
            float* prow = psw + i * KTP + lane;
#pragma unroll
            for (int j = 0; j < 8; j++) prow[j * 32] = p[j];
        }
        __syncwarp();

        int d = lane & 15;
        int half = lane >> 4;
        const float* vrow = vT + d * KTP + half * 128;
        const float* p0 = psw + 0 * KTP + half * 128;
        const float* p1 = psw + 1 * KTP + half * 128;
        const float* p2 = psw + 2 * KTP + half * 128;
        const float* p3 = psw + 3 * KTP + half * 128;
        float o0 = 0.f, o1 = 0.f, o2 = 0.f, o3 = 0.f;
#pragma unroll 8
        for (int it = 0; it < 32; it++) {
            float4 vv4 = *(const float4*)(vrow + it * 4);
            float4 a0 = *(const float4*)(p0 + it * 4);
            float4 a1 = *(const float4*)(p1 + it * 4);
            float4 a2 = *(const float4*)(p2 + it * 4);
            float4 a3 = *(const float4*)(p3 + it * 4);
            o0 += a0.x * vv4.x + a0.y * vv4.y + a0.z * vv4.z + a0.w * vv4.w;
            o1 += a1.x * vv4.x + a1.y * vv4.y + a1.z * vv4.z + a1.w * vv4.w;
            o2 += a2.x * vv4.x + a2.y * vv4.y + a2.z * vv4.z + a2.w * vv4.w;
            o3 += a3.x * vv4.x + a3.y * vv4.y + a3.z * vv4.z + a3.w * vv4.w;
        }
        o0 += __shfl_xor_sync(0xffffffffu, o0, 16);
        o1 += __shfl_xor_sync(0xffffffffu, o1, 16);
        o2 += __shfl_xor_sync(0xffffffffu, o2, 16);
        o3 += __shfl_xor_sync(0xffffffffu, o3, 16);
        if (lane < 16) {
            og[base + (size_t)(r0 + 0) * H_ + d] = o0 * invs[0];
            og[base + (size_t)(r0 + 1) * H_ + d] = o1 * invs[1];
            og[base + (size_t)(r0 + 2) * H_ + d] = o2 * invs[2];
            og[base + (size_t)(r0 + 3) * H_ + d] = o3 * invs[3];
        }
        __syncwarp();
    }
}

// ---------------------------------------------------------------------------
// Launch
// ---------------------------------------------------------------------------
extern "C" void kernel_launch(void* const* d_in, const int* in_sizes, int n_in,
                              void* d_out, int out_size) {
    const float* x       = (const float*)d_in[0];
    const float* adj_l   = (const float*)d_in[1];
    const float* var_emb = (const float*)d_in[2];
    const float* temp_emb= (const float*)d_in[3];
    const float* mech_W  = (const float*)d_in[4];
    const float* mech_b  = (const float*)d_in[5];
    const float* ln_g    = (const float*)d_in[6];
    const float* ln_b    = (const float*)d_in[7];
    const float* Wq      = (const float*)d_in[8];
    const float* Wk      = (const float*)d_in[9];
    const float* Wv      = (const float*)d_in[10];
    const float* Wo      = (const float*)d_in[11];
    const float* bq      = (const float*)d_in[12];
    const float* bk      = (const float*)d_in[13];
    const float* bv      = (const float*)d_in[14];
    const float* bo      = (const float*)d_in[15];
    const float* out_W   = (const float*)d_in[16];
    const float* out_b   = (const float*)d_in[17];
    float* pred = (float*)d_out;

    float *zA, *qb, *kb, *vb, *ob;
    cudaGetSymbolAddress((void**)&zA, g_zA);
    cudaGetSymbolAddress((void**)&qb, g_qb);
    cudaGetSymbolAddress((void**)&kb, g_kb);
    cudaGetSymbolAddress((void**)&vb, g_vb);
    cudaGetSymbolAddress((void**)&ob, g_ob);

    cudaFuncSetAttribute((const void*)gemm_mma<0>,
                         cudaFuncAttributeMaxDynamicSharedMemorySize, MMA_SMEM);
    cudaFuncSetAttribute((const void*)gemm_mma<1>,
                         cudaFuncAttributeMaxDynamicSharedMemorySize, MMA_SMEM);
    cudaFuncSetAttribute((const void*)gemm_mma<2>,
                         cudaFuncAttributeMaxDynamicSharedMemorySize, MMA_SMEM);
    cudaFuncSetAttribute((const void*)prep_w_kernel,
                         cudaFuncAttributeMaxDynamicSharedMemorySize, PREP_SMEM);
    cudaFuncSetAttribute((const void*)causal_kernel,
                         cudaFuncAttributeMaxDynamicSharedMemorySize, CAU_SMEM);
    cudaFuncSetAttribute((const void*)attn_kernel,
                         cudaFuncAttributeMaxDynamicSharedMemorySize, ATTN_SMEM);

    // 0. sigmoid + weight split (independent of causal)
    sigmoid_kernel<<<(V_ * V_ * LP1_ + 255) / 256, 256>>>(adj_l);
    prep_w_kernel<<<7 * V_, 256, PREP_SMEM>>>(mech_W, Wq, Wk, Wv, Wo);

    // 1. causal input -> zA  ([v][bt][h])
    causal_kernel<<<BT_, 256, CAU_SMEM>>>(x, var_emb, temp_emb, zA);

    // 2. mech layers (tensor cores): Linear -> LN -> GELU
    dim3 ggrid(BT_ / 128, V_, 1);
    const int BS = NL_ * H_;
    gemm_mma<1><<<ggrid, 256, MMA_SMEM>>>(zA, 0,
        mech_b + 0 * H_, nullptr, nullptr, BS, ln_g + 0 * H_, ln_b + 0 * H_,
        ob, nullptr, nullptr, nullptr, nullptr, nullptr);
    gemm_mma<1><<<ggrid, 256, MMA_SMEM>>>(ob, 1,
        mech_b + 1 * H_, nullptr, nullptr, BS, ln_g + 1 * H_, ln_b + 1 * H_,
        zA, nullptr, nullptr, nullptr, nullptr, nullptr);
    gemm_mma<1><<<ggrid, 256, MMA_SMEM>>>(zA, 2,
        mech_b + 2 * H_, nullptr, nullptr, BS, ln_g + 2 * H_, ln_b + 2 * H_,
        ob, nullptr, nullptr, nullptr, nullptr, nullptr);

    // 3. Q/K/V projections, one launch (z -> pass 3..5)
    dim3 qkvgrid(BT_ / 128, V_, 3);
    gemm_mma<0><<<qkvgrid, 256, MMA_SMEM>>>(ob, 3,
        bq, bk, bv, H_, nullptr, nullptr,
        qb, kb, vb, nullptr, nullptr, nullptr);

    // 4. attention -> zA
    attn_kernel<<<B_ * V_ * NH_, 256, ATTN_SMEM>>>(qb, kb, vb, zA);

    // 5. Wo + fused output head -> pred (pass 6)
    gemm_mma<2><<<ggrid, 256, MMA_SMEM>>>(zA, 6,
        bo, nullptr, nullptr, H_, nullptr, nullptr,
        nullptr, nullptr, nullptr, out_W, out_b, pred);
}

// round 10
// speedup vs baseline: 1.8631x; 1.3638x over previous
#include <cuda_runtime.h>
#include <cuda_bf16.h>
#include <math.h>
#include <stdint.h>

// Problem constants
#define B_  4
#define S_  256
#define V_  64
#define H_  128
#define NH_ 8
#define DH_ 16
#define LP1_ 11
#define NL_ 3
#define BT_ (B_ * S_)          // 1024
#define ZSZ (BT_ * V_ * H_)

// Scratch (device globals)
__device__ float g_adj[V_ * V_ * LP1_];
__device__ float g_zA[ZSZ];
__device__ float g_qb[ZSZ];
__device__ float g_kb[ZSZ];
__device__ float g_vb[ZSZ];
__device__ float g_ob[ZSZ];

extern __shared__ char SM[];

// ---------------------------------------------------------------------------
// mma.sync / ldmatrix helpers (sm_80+ baseline PTX; proven correct in R9)
// ---------------------------------------------------------------------------
__device__ __forceinline__ uint32_t smem_u32(const void* p) {
    uint32_t a;
    asm("{ .reg .u64 t; cvta.to.shared.u64 t, %1; cvt.u32.u64 %0, t; }"
        : "=r"(a) : "l"(p));
    return a;
}
__device__ __forceinline__ void ldsm4(uint32_t& r0, uint32_t& r1,
                                      uint32_t& r2, uint32_t& r3, uint32_t addr) {
    asm volatile("ldmatrix.sync.aligned.m8n8.x4.shared.b16 {%0,%1,%2,%3}, [%4];"
                 : "=r"(r0), "=r"(r1), "=r"(r2), "=r"(r3) : "r"(addr));
}
__device__ __forceinline__ void mma16816(float* c, const uint32_t a[4],
                                         uint32_t b0, uint32_t b1) {
    asm volatile(
        "mma.sync.aligned.m16n8k16.row.col.f32.bf16.bf16.f32 "
        "{%0,%1,%2,%3}, {%4,%5,%6,%7}, {%8,%9}, {%0,%1,%2,%3};"
        : "+f"(c[0]), "+f"(c[1]), "+f"(c[2]), "+f"(c[3])
        : "r"(a[0]), "r"(a[1]), "r"(a[2]), "r"(a[3]), "r"(b0), "r"(b1));
}
// split a float2 into packed bf16 hi and lo (residual) pairs
__device__ __forceinline__ void split2(float x, float y,
                                       uint32_t& hi, uint32_t& lo) {
    __nv_bfloat162 h = __floats2bfloat162_rn(x, y);
    float rx = x - __bfloat162float(h.x);
    float ry = y - __bfloat162float(h.y);
    __nv_bfloat162 l = __floats2bfloat162_rn(rx, ry);
    hi = *(uint32_t*)&h;
    lo = *(uint32_t*)&l;
}

// ---------------------------------------------------------------------------
// Kernel 0: adj = sigmoid(adjacency_logits)
// ---------------------------------------------------------------------------
__global__ void sigmoid_kernel(const float* __restrict__ logits) {
    int i = blockIdx.x * 256 + threadIdx.x;
    if (i < V_ * V_ * LP1_) g_adj[i] = 1.0f / (1.0f + __expf(-logits[i]));
}

// ---------------------------------------------------------------------------
// Kernel 1: causal input (R6 proven)
// ---------------------------------------------------------------------------
#define CAU_XW   0
#define CAU_ASM  (CAU_XW + LP1_ * 64)
#define CAU_BL   (CAU_ASM + 64 * 65)
#define CAU_VE   (CAU_BL + 64 * 12)
#define CAU_TE   (CAU_VE + 64 * 128)
#define CAU_SMEM ((CAU_TE + LP1_ * 128) * 4)

__global__ void causal_kernel(const float* __restrict__ x,
                              const float* __restrict__ var_emb,
                              const float* __restrict__ temp_emb,
                              float* __restrict__ zout) {
    float* cs = (float*)SM;
    float* xw  = cs + CAU_XW;
    float* Asm = cs + CAU_ASM;
    float* Bl  = cs + CAU_BL;
    float* ve  = cs + CAU_VE;
    float* te  = cs + CAU_TE;

    int bt = blockIdx.x;
    int b = bt / S_;
    int t = bt % S_;
    int tid = threadIdx.x;

    for (int e = tid; e < LP1_ * 64; e += 256) {
        int l = e >> 6, s2 = e & 63;
        int tt = t - l;
        xw[l * 64 + s2] = (tt >= 0) ? x[(b * S_ + tt) * V_ + s2] : 0.0f;
    }
    for (int e = tid; e < 64 * 128 / 4; e += 256)
        ((float4*)ve)[e] = ((const float4*)var_emb)[e];
    for (int e = tid; e < LP1_ * 128 / 4; e += 256)
        ((float4*)te)[e] = ((const float4*)temp_emb)[e];
    __syncthreads();

    for (int e = tid; e < 64 * 64; e += 256) {
        int i = e >> 6, s2 = e & 63;
        const float* ap = g_adj + (s2 * V_ + i) * LP1_;
        float acc = 0.0f;
#pragma unroll
        for (int l = 0; l < LP1_; l++) acc += xw[l * 64 + s2] * ap[l];
        Asm[i * 65 + s2] = acc;
    }
    for (int e = tid; e < 64 * LP1_; e += 256) {
        int i = e / LP1_, l = e % LP1_;
        float acc = 0.0f;
        for (int s2 = 0; s2 < 64; s2++)
            acc += xw[l * 64 + s2] * g_adj[(s2 * V_ + i) * LP1_ + l];
        Bl[i * 12 + l] = acc;
    }
    __syncthreads();

    int i = tid >> 2, q = tid & 3;
    float4 acc[8];
#pragma unroll
    for (int j = 0; j < 8; j++) acc[j] = make_float4(0.f, 0.f, 0.f, 0.f);

    for (int s2 = 0; s2 < 64; s2++) {
        float a = Asm[i * 65 + s2];
        const float* vr = ve + s2 * 128 + q * 4;
#pragma unroll
        for (int j = 0; j < 8; j++) {
            float4 vv = *(const float4*)(vr + j * 16);
            acc[j].x += a * vv.x; acc[j].y += a * vv.y;
            acc[j].z += a * vv.z; acc[j].w += a * vv.w;
        }
    }
#pragma unroll
    for (int l = 0; l < LP1_; l++) {
        float bl = Bl[i * 12 + l];
        const float* tr = te + l * 128 + q * 4;
#pragma unroll
        for (int j = 0; j < 8; j++) {
            float4 vv = *(const float4*)(tr + j * 16);
            acc[j].x += bl * vv.x; acc[j].y += bl * vv.y;
            acc[j].z += bl * vv.z; acc[j].w += bl * vv.w;
        }
    }
    float* zr = zout + ((size_t)i * BT_ + bt) * H_ + q * 4;
#pragma unroll
    for (int j = 0; j < 8; j++) *(float4*)(zr + j * 16) = acc[j];
}

// ---------------------------------------------------------------------------
// Kernel 2: per-variable scalar GEMM (R6 proven, 67.6us/launch)
// ---------------------------------------------------------------------------
#define AP_ 132
#define ABUF (32 * AP_)
#define WBUF (32 * 128)
#define GEMM_SMEM ((2 * ABUF + 2 * WBUF) * 4)

__device__ __forceinline__ void gemm_compute(const float* __restrict__ Ab,
                                             const float* __restrict__ Wb,
                                             float acc[8][8], int ty, int tx) {
#pragma unroll 8
    for (int kk = 0; kk < 32; kk++) {
        float4 a0 = *(const float4*)(Ab + kk * AP_ + ty * 8);
        float4 a1 = *(const float4*)(Ab + kk * AP_ + ty * 8 + 4);
        float4 b0 = *(const float4*)(Wb + kk * 128 + tx * 4);
        float4 b1 = *(const float4*)(Wb + kk * 128 + 64 + tx * 4);
        float a[8] = {a0.x, a0.y, a0.z, a0.w, a1.x, a1.y, a1.z, a1.w};
        float bb[8] = {b0.x, b0.y, b0.z, b0.w, b1.x, b1.y, b1.z, b1.w};
#pragma unroll
        for (int i = 0; i < 8; i++)
#pragma unroll
            for (int j = 0; j < 8; j++) acc[i][j] += a[i] * bb[j];
    }
}

template <int MODE>
__global__ __launch_bounds__(256, 2) void gemm2(
    const float* __restrict__ in,
    const float* __restrict__ W0, const float* __restrict__ W1,
    const float* __restrict__ W2,
    const float* __restrict__ Bi0, const float* __restrict__ Bi1,
    const float* __restrict__ Bi2,
    const float* __restrict__ G, const float* __restrict__ NB,
    float* O0, float* O1, float* O2,
    const float* __restrict__ OW, const float* __restrict__ OB,
    float* PRED, int wstride, int bstride) {
    float* sm = (float*)SM;
    float* Ast = sm;
    float* Wsm = sm + 2 * ABUF;

    int tid = threadIdx.x;
    int v = blockIdx.y;
    int bt0 = blockIdx.x * 128;
    int z = blockIdx.z;

    const float* W    = (z == 0 ? W0 : (z == 1 ? W1 : W2)) + (size_t)v * wstride;
    const float* bias = (z == 0 ? Bi0 : (z == 1 ? Bi1 : Bi2)) + (size_t)v * bstride;
    float* out        = (z == 0 ? O0 : (z == 1 ? O1 : O2));
    const float* inp = in + ((size_t)v * BT_ + bt0) * H_;

    int ty = tid >> 4, tx = tid & 15;

    float acc[8][8];
#pragma unroll
    for (int i = 0; i < 8; i++)
#pragma unroll
        for (int j = 0; j < 8; j++) acc[i][j] = 0.0f;

    float4 la[4], lw[4];
#pragma unroll
    for (int t = 0; t < 4; t++) {
        int idx = tid + t * 256;
        int r = idx >> 3, c4 = idx & 7;
        la[t] = *(const float4*)(inp + (size_t)r * H_ + c4 * 4);
        int wr = idx >> 5, wc = idx & 31;
        lw[t] = *(const float4*)(W + wr * H_ + wc * 4);
    }
#pragma unroll
    for (int t = 0; t < 4; t++) {
        int idx = tid + t * 256;
        int r = idx >> 3, c4 = idx & 7;
        Ast[(c4 * 4 + 0) * AP_ + r] = la[t].x;
        Ast[(c4 * 4 + 1) * AP_ + r] = la[t].y;
        Ast[(c4 * 4 + 2) * AP_ + r] = la[t].z;
        Ast[(c4 * 4 + 3) * AP_ + r] = la[t].w;
        int wr = idx >> 5, wc = idx & 31;
        *(float4*)(Wsm + wr * 128 + wc * 4) = lw[t];
    }
    __syncthreads();

    for (int c = 0; c < 4; c++) {
        if (c < 3) {
            int k0 = (c + 1) * 32;
#pragma unroll
            for (int t = 0; t < 4; t++) {
                int idx = tid + t * 256;
                int r = idx >> 3, c4 = idx & 7;
                la[t] = *(const float4*)(inp + (size_t)r * H_ + k0 + c4 * 4);
                int wr = idx >> 5, wc = idx & 31;
                lw[t] = *(const float4*)(W + (k0 + wr) * H_ + wc * 4);
            }
        }
        gemm_compute(Ast + (c & 1) * ABUF, Wsm + (c & 1) * WBUF, acc, ty, tx);
        if (c < 3) {
            float* ad = Ast + ((c + 1) & 1) * ABUF;
            float* wd = Wsm + ((c + 1) & 1) * WBUF;
#pragma unroll
            for (int t = 0; t < 4; t++) {
                int idx = tid + t * 256;
                int r = idx >> 3, c4 = idx & 7;
                ad[(c4 * 4 + 0) * AP_ + r] = la[t].x;
                ad[(c4 * 4 + 1) * AP_ + r] = la[t].y;
                ad[(c4 * 4 + 2) * AP_ + r] = la[t].z;
                ad[(c4 * 4 + 3) * AP_ + r] = la[t].w;
                int wr = idx >> 5, wc = idx & 31;
                *(float4*)(wd + wr * 128 + wc * 4) = lw[t];
            }
            __syncthreads();
        }
    }

    float4 bv0 = *(const float4*)(bias + tx * 4);
    float4 bv1 = *(const float4*)(bias + 64 + tx * 4);
    float bb[8] = {bv0.x, bv0.y, bv0.z, bv0.w, bv1.x, bv1.y, bv1.z, bv1.w};

    if (MODE == 0) {
        float* orow = out + ((size_t)v * BT_ + bt0 + ty * 8) * H_;
#pragma unroll
        for (int i = 0; i < 8; i++) {
            float4 o0 = make_float4(acc[i][0] + bb[0], acc[i][1] + bb[1],
                                    acc[i][2] + bb[2], acc[i][3] + bb[3]);
            float4 o1 = make_float4(acc[i][4] + bb[4], acc[i][5] + bb[5],
                                    acc[i][6] + bb[6], acc[i][7] + bb[7]);
            *(float4*)(orow + (size_t)i * H_ + tx * 4) = o0;
            *(float4*)(orow + (size_t)i * H_ + 64 + tx * 4) = o1;
        }
    } else if (MODE == 1) {
        const float* g  = G  + (size_t)v * bstride;
        const float* nb = NB + (size_t)v * bstride;
        float4 g0 = *(const float4*)(g + tx * 4);
        float4 g1 = *(const float4*)(g + 64 + tx * 4);
        float4 n0 = *(const float4*)(nb + tx * 4);
        float4 n1 = *(const float4*)(nb + 64 + tx * 4);
        float gv[8] = {g0.x, g0.y, g0.z, g0.w, g1.x, g1.y, g1.z, g1.w};
        float nv[8] = {n0.x, n0.y, n0.z, n0.w, n1.x, n1.y, n1.z, n1.w};
        float* orow = out + ((size_t)v * BT_ + bt0 + ty * 8) * H_;
#pragma unroll
        for (int i = 0; i < 8; i++) {
            float vals[8];
            float s = 0.0f;
#pragma unroll
            for (int j = 0; j < 8; j++) { vals[j] = acc[i][j] + bb[j]; s += vals[j]; }
            s += __shfl_xor_sync(0xffffffffu, s, 8);
            s += __shfl_xor_sync(0xffffffffu, s, 4);
            s += __shfl_xor_sync(0xffffffffu, s, 2);
            s += __shfl_xor_sync(0xffffffffu, s, 1);
            float mu = s * (1.0f / H_);
            float sq = 0.0f;
#pragma unroll
            for (int j = 0; j < 8; j++) { vals[j] -= mu; sq += vals[j] * vals[j]; }
            sq += __shfl_xor_sync(0xffffffffu, sq, 8);
            sq += __shfl_xor_sync(0xffffffffu, sq, 4);
            sq += __shfl_xor_sync(0xffffffffu, sq, 2);
            sq += __shfl_xor_sync(0xffffffffu, sq, 1);
            float inv = rsqrtf(sq * (1.0f / H_) + 1e-5f);
            float y[8];
#pragma unroll
            for (int j = 0; j < 8; j++) {
                float t2 = vals[j] * inv * gv[j] + nv[j];
                y[j] = t2 * 0.5f * (1.0f + erff(t2 * 0.70710678118654752f));
            }
            *(float4*)(orow + (size_t)i * H_ + tx * 4) =
                make_float4(y[0], y[1], y[2], y[3]);
            *(float4*)(orow + (size_t)i * H_ + 64 + tx * 4) =
                make_float4(y[4], y[5], y[6], y[7]);
        }
    } else {
        float4 w0 = *(const float4*)(OW + (size_t)v * H_ + tx * 4);
        float4 w1 = *(const float4*)(OW + (size_t)v * H_ + 64 + tx * 4);
        float ow[8] = {w0.x, w0.y, w0.z, w0.w, w1.x, w1.y, w1.z, w1.w};
        float ob = OB[v];
#pragma unroll
        for (int i = 0; i < 8; i++) {
            float s = 0.0f;
#pragma unroll
            for (int j = 0; j < 8; j++) s += (acc[i][j] + bb[j]) * ow[j];
            s += __shfl_xor_sync(0xffffffffu, s, 8);
            s += __shfl_xor_sync(0xffffffffu, s, 4);
            s += __shfl_xor_sync(0xffffffffu, s, 2);
            s += __shfl_xor_sync(0xffffffffu, s, 1);
            if (tx == 0) PRED[(size_t)(bt0 + ty * 8 + i) * V_ + v] = s + ob;
        }
    }
}

// ---------------------------------------------------------------------------
// Kernel 3: tensor-core attention. Block = (b, v, head-pair); 8 warps.
// Warp = (head-half hh, 64 q-rows). 4 strips of 16 q-rows per warp.
// K[key][d] bf16 hi/lo pitch 48B; V^T[d][key] hi/lo pitch 528B (ldsm conflict-free).
// Q fragments loaded directly from gmem. S-accum fragment == A-operand of P.V.
// ---------------------------------------------------------------------------
#define AKHI 0
#define AKLO 24576
#define AVHI 49152
#define AVLO 66048
#define ATT_SMEM 82944
#define KHEAD 12288       // bytes per head of K (256*48)
#define VHEAD 8448        // bytes per head of V^T (16*528)

__global__ __launch_bounds__(256, 1) void attn_mma(
        const float* __restrict__ qg,
        const float* __restrict__ kg,
        const float* __restrict__ vg,
        float* __restrict__ og) {
    char* smc = SM;
    uint32_t sb = smem_u32(smc);
    int id = blockIdx.x;
    int hp = id & 3;                 // head pair: heads hp*2, hp*2+1
    int vv = (id >> 2) & 63;
    int b  = id >> 8;
    int tid = threadIdx.x;

    size_t vbase = ((size_t)vv * BT_ + b * S_) * H_;

    // --- stage K and V^T (bf16 hi/lo) for both heads of the pair ---
    for (int i = tid; i < 8192; i += 256) {
        int col = i & 31;            // hh*16 + d
        int key = i >> 5;
        int hh = col >> 4, d = col & 15;
        size_t gidx = vbase + (size_t)key * H_ + hp * 32 + col;
        float kv = kg[gidx];
        __nv_bfloat16 kh = __float2bfloat16(kv);
        __nv_bfloat16 kl = __float2bfloat16(kv - __bfloat162float(kh));
        *(__nv_bfloat16*)(smc + AKHI + hh * KHEAD + key * 48 + d * 2) = kh;
        *(__nv_bfloat16*)(smc + AKLO + hh * KHEAD + key * 48 + d * 2) = kl;
        float vvv = vg[gidx];
        __nv_bfloat16 vh = __float2bfloat16(vvv);
        __nv_bfloat16 vl = __float2bfloat16(vvv - __bfloat162float(vh));
        *(__nv_bfloat16*)(smc + AVHI + hh * VHEAD + d * 528 + key * 2) = vh;
        *(__nv_bfloat16*)(smc + AVLO + hh * VHEAD + d * 528 + key * 2) = vl;
    }
    __syncthreads();

    int wid = tid >> 5, lane = tid & 31;
    int hh = wid >> 2, wq = wid & 3;
    int g = lane >> 2, tg = lane & 3;
    int lr = lane & 7, lsel = (lane >> 3) & 1, khalf = lane >> 4;

    const float* qbase = qg + vbase + hp * 32 + hh * 16;
    float* obase = og + vbase + hp * 32 + hh * 16;

    uint32_t kbh = sb + AKHI + hh * KHEAD;
    uint32_t kbl = sb + AKLO + hh * KHEAD;
    uint32_t vbh = sb + AVHI + hh * VHEAD;
    uint32_t vbl = sb + AVLO + hh * VHEAD;
    uint32_t krow = (uint32_t)(lr + khalf * 8) * 48 + lsel * 16;
    uint32_t vrow = (uint32_t)(lr + khalf * 8) * 528 + lsel * 16;

    for (int s = 0; s < 4; s++) {
        int q0 = wq * 64 + s * 16;

        // Q fragments direct from gmem
        uint32_t ah[4], al[4];
        {
            float2 f0 = *(const float2*)(qbase + (size_t)(q0 + g) * H_ + 2 * tg);
            float2 f1 = *(const float2*)(qbase + (size_t)(q0 + g + 8) * H_ + 2 * tg);
            float2 f2 = *(const float2*)(qbase + (size_t)(q0 + g) * H_ + 8 + 2 * tg);
            float2 f3 = *(const float2*)(qbase + (size_t)(q0 + g + 8) * H_ + 8 + 2 * tg);
            split2(f0.x, f0.y, ah[0], al[0]);
            split2(f1.x, f1.y, ah[1], al[1]);
            split2(f2.x, f2.y, ah[2], al[2]);
            split2(f3.x, f3.y, ah[3], al[3]);
        }

        // QK^T: S[16 q][256 keys] in fragments c[kt][8]
        float c[16][8];
#pragma unroll
        for (int kt = 0; kt < 16; kt++)
#pragma unroll
            for (int e = 0; e < 8; e++) c[kt][e] = 0.0f;

#pragma unroll
        for (int kt = 0; kt < 16; kt++) {
            uint32_t bh[4], bl[4];
            ldsm4(bh[0], bh[1], bh[2], bh[3], kbh + kt * 768 + krow);
            ldsm4(bl[0], bl[1], bl[2], bl[3], kbl + kt * 768 + krow);
            mma16816(c[kt], ah, bh[0], bh[1]);
            mma16816(c[kt] + 4, ah, bh[2], bh[3]);
            mma16816(c[kt], ah, bl[0], bl[1]);
            mma16816(c[kt] + 4, ah, bl[2], bl[3]);
            mma16816(c[kt], al, bh[0], bh[1]);
            mma16816(c[kt] + 4, al, bh[2], bh[3]);
        }

        // softmax (rows g and g+8; quad lanes share a row)
        float mA = -1e30f, mB = -1e30f;
#pragma unroll
        for (int kt = 0; kt < 16; kt++) {
#pragma unroll
            for (int t = 0; t < 2; t++) {
                mA = fmaxf(mA, fmaxf(c[kt][t * 4 + 0], c[kt][t * 4 + 1]));
                mB = fmaxf(mB, fmaxf(c[kt][t * 4 + 2], c[kt][t * 4 + 3]));
            }
        }
        mA = fmaxf(mA, __shfl_xor_sync(0xffffffffu, mA, 1));
        mA = fmaxf(mA, __shfl_xor_sync(0xffffffffu, mA, 2));
        mB = fmaxf(mB, __shfl_xor_sync(0xffffffffu, mB, 1));
        mB = fmaxf(mB, __shfl_xor_sync(0xffffffffu, mB, 2));
        mA *= 0.25f;
        mB *= 0.25f;
        float sA = 0.0f, sB = 0.0f;
#pragma unroll
        for (int kt = 0; kt < 16; kt++) {
#pragma unroll
            for (int t = 0; t < 2; t++) {
                float p0 = __expf(c[kt][t * 4 + 0] * 0.25f - mA);
                float p1 = __expf(c[kt][t * 4 + 1] * 0.25f - mA);
                float p2 = __expf(c[kt][t * 4 + 2] * 0.25f - mB);
                float p3 = __expf(c[kt][t * 4 + 3] * 0.25f - mB);
                c[kt][t * 4 + 0] = p0; c[kt][t * 4 + 1] = p1;
                c[kt][t * 4 + 2] = p2; c[kt][t * 4 + 3] = p3;
                sA += p0 + p1;
                sB += p2 + p3;
            }
        }
        sA += __shfl_xor_sync(0xffffffffu, sA, 1);
        sA += __shfl_xor_sync(0xffffffffu, sA, 2);
        sB += __shfl_xor_sync(0xffffffffu, sB, 1);
        sB += __shfl_xor_sync(0xffffffffu, sB, 2);
        float invA = 1.0f / sA, invB = 1.0f / sB;

        // P.V: accumulate o[16 q][16 d]
        float o[8];
#pragma unroll
        for (int e = 0; e < 8; e++) o[e] = 0.0f;

#pragma unroll
        for (int kt = 0; kt < 16; kt++) {
            uint32_t ph[4], pl[4];
            split2(c[kt][0], c[kt][1], ph[0], pl[0]);
            split2(c[kt][2], c[kt][3], ph[1], pl[1]);
            split2(c[kt][4], c[kt][5], ph[2], pl[2]);
            split2(c[kt][6], c[kt][7], ph[3], pl[3]);
            uint32_t vh[4], vl[4];
            ldsm4(vh[0], vh[1], vh[2], vh[3], vbh + vrow + kt * 32);
            ldsm4(vl[0], vl[1], vl[2], vl[3], vbl + vrow + kt * 32);
            mma16816(o, ph, vh[0], vh[1]);
            mma16816(o + 4, ph, vh[2], vh[3]);
            mma16816(o, ph, vl[0], vl[1]);
            mma16816(o + 4, ph, vl[2], vl[3]);
            mma16816(o, pl, vh[0], vh[1]);
            mma16816(o + 4, pl, vh[2], vh[3]);
        }

        // store (normalize by row sums)
        *(float2*)(obase + (size_t)(q0 + g) * H_ + 2 * tg) =
            make_float2(o[0] * invA, o[1] * invA);
        *(float2*)(obase + (size_t)(q0 + g + 8) * H_ + 2 * tg) =
            make_float2(o[2] * invB, o[3] * invB);
        *(float2*)(obase + (size_t)(q0 + g) * H_ + 8 + 2 * tg) =
            make_float2(o[4] * invA, o[5] * invA);
        *(float2*)(obase + (size_t)(q0 + g + 8) * H_ + 8 + 2 * tg) =
            make_float2(o[6] * invB, o[7] * invB);
    }
}

// ---------------------------------------------------------------------------
// Launch
// ---------------------------------------------------------------------------
extern "C" void kernel_launch(void* const* d_in, const int* in_sizes, int n_in,
                              void* d_out, int out_size) {
    const float* x       = (const float*)d_in[0];
    const float* adj_l   = (const float*)d_in[1];
    const float* var_emb = (const float*)d_in[2];
    const float* temp_emb= (const float*)d_in[3];
    const float* mech_W  = (const float*)d_in[4];
    const float* mech_b  = (const float*)d_in[5];
    const float* ln_g    = (const float*)d_in[6];
    const float* ln_b    = (const float*)d_in[7];
    const float* Wq      = (const float*)d_in[8];
    const float* Wk      = (const float*)d_in[9];
    const float* Wv      = (const float*)d_in[10];
    const float* Wo      = (const float*)d_in[11];
    const float* bq      = (const float*)d_in[12];
    const float* bk      = (const float*)d_in[13];
    const float* bv      = (const float*)d_in[14];
    const float* bo      = (const float*)d_in[15];
    const float* out_W   = (const float*)d_in[16];
    const float* out_b   = (const float*)d_in[17];
    float* pred = (float*)d_out;

    float *zA, *qb, *kb, *vb, *ob;
    cudaGetSymbolAddress((void**)&zA, g_zA);
    cudaGetSymbolAddress((void**)&qb, g_qb);
    cudaGetSymbolAddress((void**)&kb, g_kb);
    cudaGetSymbolAddress((void**)&vb, g_vb);
    cudaGetSymbolAddress((void**)&ob, g_ob);

    cudaFuncSetAttribute((const void*)gemm2<0>,
                         cudaFuncAttributeMaxDynamicSharedMemorySize, GEMM_SMEM);
    cudaFuncSetAttribute((const void*)gemm2<1>,
                         cudaFuncAttributeMaxDynamicSharedMemorySize, GEMM_SMEM);
    cudaFuncSetAttribute((const void*)gemm2<2>,
                         cudaFuncAttributeMaxDynamicSharedMemorySize, GEMM_SMEM);
    cudaFuncSetAttribute((const void*)causal_kernel,
                         cudaFuncAttributeMaxDynamicSharedMemorySize, CAU_SMEM);
    cudaFuncSetAttribute((const void*)attn_mma,
                         cudaFuncAttributeMaxDynamicSharedMemorySize, ATT_SMEM);

    // 0. sigmoid(adjacency)
    sigmoid_kernel<<<(V_ * V_ * LP1_ + 255) / 256, 256>>>(adj_l);

    // 1. causal input -> zA  ([v][bt][h])
    causal_kernel<<<BT_, 256, CAU_SMEM>>>(x, var_emb, temp_emb, zA);

    // 2. mech layers: Linear -> LN -> GELU  (scalar GEMM, proven)
    dim3 ggrid(BT_ / 128, V_, 1);
    const int WS = NL_ * H_ * H_, BS = NL_ * H_;
    gemm2<1><<<ggrid, 256, GEMM_SMEM>>>(zA,
        mech_W + 0 * H_ * H_, nullptr, nullptr,
        mech_b + 0 * H_, nullptr, nullptr,
        ln_g + 0 * H_, ln_b + 0 * H_,
        ob, nullptr, nullptr, nullptr, nullptr, nullptr, WS, BS);
    gemm2<1><<<ggrid, 256, GEMM_SMEM>>>(ob,
        mech_W + 1 * H_ * H_, nullptr, nullptr,
        mech_b + 1 * H_, nullptr, nullptr,
        ln_g + 1 * H_, ln_b + 1 * H_,
        zA, nullptr, nullptr, nullptr, nullptr, nullptr, WS, BS);
    gemm2<1><<<ggrid, 256, GEMM_SMEM>>>(zA,
        mech_W + 2 * H_ * H_, nullptr, nullptr,
        mech_b + 2 * H_, nullptr, nullptr,
        ln_g + 2 * H_, ln_b + 2 * H_,
        ob, nullptr, nullptr, nullptr, nullptr, nullptr, WS, BS);

    // 3. Q/K/V projections, one launch (blockIdx.z selects)
    dim3 qkvgrid(BT_ / 128, V_, 3);
    gemm2<0><<<qkvgrid, 256, GEMM_SMEM>>>(ob,
        Wq, Wk, Wv, bq, bk, bv, nullptr, nullptr,
        qb, kb, vb, nullptr, nullptr, nullptr, H_ * H_, H_);

    // 4. tensor-core attention -> zA
    attn_mma<<<B_ * V_ * NH_ / 2, 256, ATT_SMEM>>>(qb, kb, vb, zA);

    // 5. Wo + fused output head -> pred
    gemm2<2><<<ggrid, 256, GEMM_SMEM>>>(zA,
        Wo, nullptr, nullptr, bo, nullptr, nullptr, nullptr, nullptr,
        nullptr, nullptr, nullptr, out_W, out_b, pred, H_ * H_, H_);
}

// round 11
// speedup vs baseline: 2.2543x; 1.2099x over previous
#include <cuda_runtime.h>
#include <cuda_bf16.h>
#include <math.h>
#include <stdint.h>

// Problem constants
#define B_  4
#define S_  256
#define V_  64
#define H_  128
#define NH_ 8
#define DH_ 16
#define LP1_ 11
#define NL_ 3
#define BT_ (B_ * S_)          // 1024
#define ZSZ (BT_ * V_ * H_)

// Scratch (device globals)
__device__ float g_adj[V_ * V_ * LP1_];
__device__ float g_zA[ZSZ];
__device__ float g_qb[ZSZ];
__device__ float g_kb[ZSZ];
__device__ float g_vb[ZSZ];
__device__ float g_ob[ZSZ];
// Pre-split weights: [pass 0..6][v][chunk 0..3][hi|lo] 10240-byte smem images
// (B-layout [n][k-chunk32], bf16, row pitch 80 bytes)
#define WIMG   10240
#define WVBLK  (4 * 2 * WIMG)    // 81920 bytes per (pass,v)
__device__ __align__(128) char g_Wc[7 * V_ * WVBLK];

extern __shared__ char SM[];

// ---------------------------------------------------------------------------
// mma.sync / ldmatrix helpers (validated R9/R10)
// ---------------------------------------------------------------------------
__device__ __forceinline__ uint32_t smem_u32(const void* p) {
    uint32_t a;
    asm("{ .reg .u64 t; cvta.to.shared.u64 t, %1; cvt.u32.u64 %0, t; }"
        : "=r"(a) : "l"(p));
    return a;
}
__device__ __forceinline__ void ldsm4(uint32_t& r0, uint32_t& r1,
                                      uint32_t& r2, uint32_t& r3, uint32_t addr) {
    asm volatile("ldmatrix.sync.aligned.m8n8.x4.shared.b16 {%0,%1,%2,%3}, [%4];"
                 : "=r"(r0), "=r"(r1), "=r"(r2), "=r"(r3) : "r"(addr));
}
__device__ __forceinline__ void mma16816(float* c, const uint32_t a[4],
                                         uint32_t b0, uint32_t b1) {
    asm volatile(
        "mma.sync.aligned.m16n8k16.row.col.f32.bf16.bf16.f32 "
        "{%0,%1,%2,%3}, {%4,%5,%6,%7}, {%8,%9}, {%0,%1,%2,%3};"
        : "+f"(c[0]), "+f"(c[1]), "+f"(c[2]), "+f"(c[3])
        : "r"(a[0]), "r"(a[1]), "r"(a[2]), "r"(a[3]), "r"(b0), "r"(b1));
}
__device__ __forceinline__ void split2(float x, float y,
                                       uint32_t& hi, uint32_t& lo) {
    __nv_bfloat162 h = __floats2bfloat162_rn(x, y);
    float rx = x - __bfloat162float(h.x);
    float ry = y - __bfloat162float(h.y);
    __nv_bfloat162 l = __floats2bfloat162_rn(rx, ry);
    hi = *(uint32_t*)&h;
    lo = *(uint32_t*)&l;
}

// ---------------------------------------------------------------------------
// Kernel 0: adj = sigmoid(adjacency_logits)
// ---------------------------------------------------------------------------
__global__ void sigmoid_kernel(const float* __restrict__ logits) {
    int i = blockIdx.x * 256 + threadIdx.x;
    if (i < V_ * V_ * LP1_) g_adj[i] = 1.0f / (1.0f + __expf(-logits[i]));
}

// ---------------------------------------------------------------------------
// Kernel P: split weights into per-chunk bf16 hi/lo smem images.
// One block per (pass, v). smem: Wt[128][132] fp32.
// ---------------------------------------------------------------------------
#define PREP_SMEM (128 * 132 * 4)
__global__ void prep_w_kernel(const float* __restrict__ mech_W,
                              const float* __restrict__ Wq,
                              const float* __restrict__ Wk,
                              const float* __restrict__ Wv,
                              const float* __restrict__ Wo) {
    float* Wt = (float*)SM;
    int pv = blockIdx.x;
    int pass = pv >> 6, v = pv & 63;
    const float* src;
    if (pass < 3)       src = mech_W + ((size_t)v * NL_ + pass) * H_ * H_;
    else if (pass == 3) src = Wq + (size_t)v * H_ * H_;
    else if (pass == 4) src = Wk + (size_t)v * H_ * H_;
    else if (pass == 5) src = Wv + (size_t)v * H_ * H_;
    else                src = Wo + (size_t)v * H_ * H_;

    int tid = threadIdx.x;
    for (int i = tid; i < 128 * 32; i += 256) {
        int r = i >> 5, c4 = i & 31;
        float4 a = *(const float4*)(src + (size_t)r * H_ + c4 * 4);
        *(float4*)(Wt + r * 132 + c4 * 4) = a;
    }
    __syncthreads();

    char* img = g_Wc + (size_t)pv * WVBLK;
    for (int task = tid; task < 4 * 128 * 16; task += 256) {
        int ch = task >> 11;
        int rem = task & 2047;
        int n = rem >> 4, kk2 = rem & 15;
        int k = ch * 32 + kk2 * 2;
        float w0 = Wt[k * 132 + n];
        float w1 = Wt[(k + 1) * 132 + n];
        uint32_t hi, lo;
        split2(w0, w1, hi, lo);
        *(uint32_t*)(img + (ch * 2 + 0) * WIMG + n * 80 + kk2 * 4) = hi;
        *(uint32_t*)(img + (ch * 2 + 1) * WIMG + n * 80 + kk2 * 4) = lo;
    }
}

// ---------------------------------------------------------------------------
// Kernel 1: causal input (R6 proven)
// ---------------------------------------------------------------------------
#define CAU_XW   0
#define CAU_ASM  (CAU_XW + LP1_ * 64)
#define CAU_BL   (CAU_ASM + 64 * 65)
#define CAU_VE   (CAU_BL + 64 * 12)
#define CAU_TE   (CAU_VE + 64 * 128)
#define CAU_SMEM ((CAU_TE + LP1_ * 128) * 4)

__global__ void causal_kernel(const float* __restrict__ x,
                              const float* __restrict__ var_emb,
                              const float* __restrict__ temp_emb,
                              float* __restrict__ zout) {
    float* cs = (float*)SM;
    float* xw  = cs + CAU_XW;
    float* Asm = cs + CAU_ASM;
    float* Bl  = cs + CAU_BL;
    float* ve  = cs + CAU_VE;
    float* te  = cs + CAU_TE;

    int bt = blockIdx.x;
    int b = bt / S_;
    int t = bt % S_;
    int tid = threadIdx.x;

    for (int e = tid; e < LP1_ * 64; e += 256) {
        int l = e >> 6, s2 = e & 63;
        int tt = t - l;
        xw[l * 64 + s2] = (tt >= 0) ? x[(b * S_ + tt) * V_ + s2] : 0.0f;
    }
    for (int e = tid; e < 64 * 128 / 4; e += 256)
        ((float4*)ve)[e] = ((const float4*)var_emb)[e];
    for (int e = tid; e < LP1_ * 128 / 4; e += 256)
        ((float4*)te)[e] = ((const float4*)temp_emb)[e];
    __syncthreads();

    for (int e = tid; e < 64 * 64; e += 256) {
        int i = e >> 6, s2 = e & 63;
        const float* ap = g_adj + (s2 * V_ + i) * LP1_;
        float acc = 0.0f;
#pragma unroll
        for (int l = 0; l < LP1_; l++) acc += xw[l * 64 + s2] * ap[l];
        Asm[i * 65 + s2] = acc;
    }
    for (int e = tid; e < 64 * LP1_; e += 256) {
        int i = e / LP1_, l = e % LP1_;
        float acc = 0.0f;
        for (int s2 = 0; s2 < 64; s2++)
            acc += xw[l * 64 + s2] * g_adj[(s2 * V_ + i) * LP1_ + l];
        Bl[i * 12 + l] = acc;
    }
    __syncthreads();

    int i = tid >> 2, q = tid & 3;
    float4 acc[8];
#pragma unroll
    for (int j = 0; j < 8; j++) acc[j] = make_float4(0.f, 0.f, 0.f, 0.f);

    for (int s2 = 0; s2 < 64; s2++) {
        float a = Asm[i * 65 + s2];
        const float* vr = ve + s2 * 128 + q * 4;
#pragma unroll
        for (int j = 0; j < 8; j++) {
            float4 vv = *(const float4*)(vr + j * 16);
            acc[j].x += a * vv.x; acc[j].y += a * vv.y;
            acc[j].z += a * vv.z; acc[j].w += a * vv.w;
        }
    }
#pragma unroll
    for (int l = 0; l < LP1_; l++) {
        float bl = Bl[i * 12 + l];
        const float* tr = te + l * 128 + q * 4;
#pragma unroll
        for (int j = 0; j < 8; j++) {
            float4 vv = *(const float4*)(tr + j * 16);
            acc[j].x += bl * vv.x; acc[j].y += bl * vv.y;
            acc[j].z += bl * vv.z; acc[j].w += bl * vv.w;
        }
    }
    float* zr = zout + ((size_t)i * BT_ + bt) * H_ + q * 4;
#pragma unroll
    for (int j = 0; j < 8; j++) *(float4*)(zr + j * 16) = acc[j];
}

// ---------------------------------------------------------------------------
// Kernel 2: GEMM via mma.sync, v2. Warp = 16 rows x 128 cols (c[16][4]).
// K streamed in 4 chunks of 32; smem 40KB single-buffered; occ 2.
// Register epilogue: MODE 0 bias / MODE 1 bias+LN+GELU / MODE 2 bias+out-head.
// ---------------------------------------------------------------------------
#define GAP 80
#define GA_HI 0
#define GA_LO 10240
#define GB_HI 20480
#define GB_LO 30720
#define G2_SMEM 40960

template <int MODE>
__global__ __launch_bounds__(256, 2) void gemm_mma2(
    const float* __restrict__ in, int passbase,
    const float* __restrict__ Bi0, const float* __restrict__ Bi1,
    const float* __restrict__ Bi2, int bstride,
    const float* __restrict__ G, const float* __restrict__ NB,
    float* O0, float* O1, float* O2,
    const float* __restrict__ OW, const float* __restrict__ OB,
    float* PRED) {
    char* smc = SM;
    uint32_t sb = smem_u32(smc);
    int tid = threadIdx.x;
    int v = blockIdx.y;
    int bt0 = blockIdx.x * 128;
    int z = blockIdx.z;

    const float* bias = (z == 0 ? Bi0 : (z == 1 ? Bi1 : Bi2)) + (size_t)v * bstride;
    float* out = (z == 0 ? O0 : (z == 1 ? O1 : O2));
    const float* inp = in + ((size_t)v * BT_ + bt0) * H_;
    const uint4* wimg = (const uint4*)(g_Wc + (size_t)((passbase + z) * V_ + v) * WVBLK);

    int wid = tid >> 5, lane = tid & 31;
    int g = lane >> 2, tg = lane & 3;
    int lr = lane & 7, lsel = (lane >> 3) & 1, khalf = lane >> 4;
    uint32_t aoff = (uint32_t)(wid * 16 + lr + lsel * 8) * GAP + khalf * 16;

    float c[16][4];
#pragma unroll
    for (int nt = 0; nt < 16; nt++)
#pragma unroll
        for (int e = 0; e < 4; e++) c[nt][e] = 0.0f;

    for (int ch = 0; ch < 4; ch++) {
        // stage A chunk: fp32 -> bf16 hi/lo, pitch-80 rows
#pragma unroll
        for (int t = 0; t < 4; t++) {
            int idx = tid + t * 256;
            int r = idx >> 3, c4 = idx & 7;
            float4 a = *(const float4*)(inp + (size_t)r * H_ + ch * 32 + c4 * 4);
            uint32_t h0, l0, h1, l1;
            split2(a.x, a.y, h0, l0);
            split2(a.z, a.w, h1, l1);
            *(uint2*)(smc + GA_HI + r * GAP + c4 * 8) = make_uint2(h0, h1);
            *(uint2*)(smc + GA_LO + r * GAP + c4 * 8) = make_uint2(l0, l1);
        }
        // copy B chunk images (hi, lo contiguous: 1280 uint4)
        {
            const uint4* src = wimg + ch * 1280;
            uint4* dst = (uint4*)(smc + GB_HI);
            for (int i = tid; i < 1280; i += 256) dst[i] = src[i];
        }
        __syncthreads();

#pragma unroll
        for (int sub = 0; sub < 2; sub++) {
            uint32_t ah[4], al[4];
            ldsm4(ah[0], ah[1], ah[2], ah[3], sb + GA_HI + aoff + sub * 32);
            ldsm4(al[0], al[1], al[2], al[3], sb + GA_LO + aoff + sub * 32);
#pragma unroll
            for (int bq = 0; bq < 8; bq++) {
                uint32_t bo = (uint32_t)(bq * 16 + lr + khalf * 8) * GAP
                            + lsel * 16 + sub * 32;
                uint32_t bh[4], bl[4];
                ldsm4(bh[0], bh[1], bh[2], bh[3], sb + GB_HI + bo);
                ldsm4(bl[0], bl[1], bl[2], bl[3], sb + GB_LO + bo);
                mma16816(c[2 * bq + 0], ah, bh[0], bh[1]);
                mma16816(c[2 * bq + 1], ah, bh[2], bh[3]);
                mma16816(c[2 * bq + 0], ah, bl[0], bl[1]);
                mma16816(c[2 * bq + 1], ah, bl[2], bl[3]);
                mma16816(c[2 * bq + 0], al, bh[0], bh[1]);
                mma16816(c[2 * bq + 1], al, bh[2], bh[3]);
            }
        }
        __syncthreads();
    }

    // rows owned by this lane: r0 (frag e0,e1), r1 = r0+8 (frag e2,e3)
    int r0 = bt0 + wid * 16 + g;

    if (MODE == 0) {
        float* ob0 = out + ((size_t)v * BT_ + r0) * H_;
        float* ob1 = ob0 + 8 * H_;
#pragma unroll
        for (int nt = 0; nt < 16; nt++) {
            float2 b2 = __ldg((const float2*)(bias + nt * 8 + 2 * tg));
            *(float2*)(ob0 + nt * 8 + 2 * tg) =
                make_float2(c[nt][0] + b2.x, c[nt][1] + b2.y);
            *(float2*)(ob1 + nt * 8 + 2 * tg) =
                make_float2(c[nt][2] + b2.x, c[nt][3] + b2.y);
        }
    } else if (MODE == 1) {
        const float* gg = G  + (size_t)v * bstride;
        const float* nb = NB + (size_t)v * bstride;
        float sA = 0.0f, sB = 0.0f;
#pragma unroll
        for (int nt = 0; nt < 16; nt++) {
            float2 b2 = __ldg((const float2*)(bias + nt * 8 + 2 * tg));
            c[nt][0] += b2.x; c[nt][1] += b2.y;
            c[nt][2] += b2.x; c[nt][3] += b2.y;
            sA += c[nt][0] + c[nt][1];
            sB += c[nt][2] + c[nt][3];
        }
        sA += __shfl_xor_sync(~0u, sA, 1); sA += __shfl_xor_sync(~0u, sA, 2);
        sB += __shfl_xor_sync(~0u, sB, 1); sB += __shfl_xor_sync(~0u, sB, 2);
        float muA = sA * (1.0f / H_), muB = sB * (1.0f / H_);
        float qA = 0.0f, qB = 0.0f;
#pragma unroll
        for (int nt = 0; nt < 16; nt++) {
            c[nt][0] -= muA; c[nt][1] -= muA;
            c[nt][2] -= muB; c[nt][3] -= muB;
            qA += c[nt][0] * c[nt][0] + c[nt][1] * c[nt][1];
            qB += c[nt][2] * c[nt][2] + c[nt][3] * c[nt][3];
        }
        qA += __shfl_xor_sync(~0u, qA, 1); qA += __shfl_xor_sync(~0u, qA, 2);
        qB += __shfl_xor_sync(~0u, qB, 1); qB += __shfl_xor_sync(~0u, qB, 2);
        float ivA = rsqrtf(qA * (1.0f / H_) + 1e-5f);
        float ivB = rsqrtf(qB * (1.0f / H_) + 1e-5f);
        float* ob0 = out + ((size_t)v * BT_ + r0) * H_;
        float* ob1 = ob0 + 8 * H_;
#pragma unroll
        for (int nt = 0; nt < 16; nt++) {
            float2 g2 = __ldg((const float2*)(gg + nt * 8 + 2 * tg));
            float2 n2 = __ldg((const float2*)(nb + nt * 8 + 2 * tg));
            float y0 = c[nt][0] * ivA * g2.x + n2.x;
            float y1 = c[nt][1] * ivA * g2.y + n2.y;
            float y2 = c[nt][2] * ivB * g2.x + n2.x;
            float y3 = c[nt][3] * ivB * g2.y + n2.y;
            y0 = y0 * 0.5f * (1.0f + erff(y0 * 0.70710678118654752f));
            y1 = y1 * 0.5f * (1.0f + erff(y1 * 0.70710678118654752f));
            y2 = y2 * 0.5f * (1.0f + erff(y2 * 0.70710678118654752f));
            y3 = y3 * 0.5f * (1.0f + erff(y3 * 0.70710678118654752f));
            *(float2*)(ob0 + nt * 8 + 2 * tg) = make_float2(y0, y1);
            *(float2*)(ob1 + nt * 8 + 2 * tg) = make_float2(y2, y3);
        }
    } else {  // MODE 2: fused output head
        const float* ow = OW + (size_t)v * H_;
        float s0 = 0.0f, s1 = 0.0f;
#pragma unroll
        for (int nt = 0; nt < 16; nt++) {
            float2 b2 = __ldg((const float2*)(bias + nt * 8 + 2 * tg));
            float2 w2 = __ldg((const float2*)(ow + nt * 8 + 2 * tg));
            s0 += (c[nt][0] + b2.x) * w2.x + (c[nt][1] + b2.y) * w2.y;
            s1 += (c[nt][2] + b2.x) * w2.x + (c[nt][3] + b2.y) * w2.y;
        }
        s0 += __shfl_xor_sync(~0u, s0, 1); s0 += __shfl_xor_sync(~0u, s0, 2);
        s1 += __shfl_xor_sync(~0u, s1, 1); s1 += __shfl_xor_sync(~0u, s1, 2);
        if (tg == 0) {
            float ob = OB[v];
            PRED[(size_t)r0 * V_ + v] = s0 + ob;
            PRED[(size_t)(r0 + 8) * V_ + v] = s1 + ob;
        }
    }
}

// ---------------------------------------------------------------------------
// Kernel 3: tensor-core attention, online-softmax over 4 key-chunks of 64.
// Block = (b, v, head-pair); 8 warps; warp = (head-half, 64 q rows), 4 strips.
// Score regs per strip: c4_[4][8] = 32 (was 128) -> occ 2.
// ---------------------------------------------------------------------------
#define AKHI 0
#define AKLO 24576
#define AVHI 49152
#define AVLO 66048
#define ATT_SMEM 82944
#define KHEAD 12288
#define VHEAD 8448

__global__ __launch_bounds__(256, 2) void attn_mma(
        const float* __restrict__ qg,
        const float* __restrict__ kg,
        const float* __restrict__ vg,
        float* __restrict__ og) {
    char* smc = SM;
    uint32_t sb = smem_u32(smc);
    int id = blockIdx.x;
    int hp = id & 3;
    int vv = (id >> 2) & 63;
    int b  = id >> 8;
    int tid = threadIdx.x;

    size_t vbase = ((size_t)vv * BT_ + b * S_) * H_;

    for (int i = tid; i < 8192; i += 256) {
        int col = i & 31;
        int key = i >> 5;
        int hh = col >> 4, d = col & 15;
        size_t gidx = vbase + (size_t)key * H_ + hp * 32 + col;
        float kv = kg[gidx];
        __nv_bfloat16 kh = __float2bfloat16(kv);
        __nv_bfloat16 kl = __float2bfloat16(kv - __bfloat162float(kh));
        *(__nv_bfloat16*)(smc + AKHI + hh * KHEAD + key * 48 + d * 2) = kh;
        *(__nv_bfloat16*)(smc + AKLO + hh * KHEAD + key * 48 + d * 2) = kl;
        float vvv = vg[gidx];
        __nv_bfloat16 vh = __float2bfloat16(vvv);
        __nv_bfloat16 vl = __float2bfloat16(vvv - __bfloat162float(vh));
        *(__nv_bfloat16*)(smc + AVHI + hh * VHEAD + d * 528 + key * 2) = vh;
        *(__nv_bfloat16*)(smc + AVLO + hh * VHEAD + d * 528 + key * 2) = vl;
    }
    __syncthreads();

    int wid = tid >> 5, lane = tid & 31;
    int hh = wid >> 2, wq = wid & 3;
    int g = lane >> 2, tg = lane & 3;
    int lr = lane & 7, lsel = (lane >> 3) & 1, khalf = lane >> 4;

    const float* qbase = qg + vbase + hp * 32 + hh * 16;
    float* obase = og + vbase + hp * 32 + hh * 16;

    uint32_t kbh = sb + AKHI + hh * KHEAD;
    uint32_t kbl = sb + AKLO + hh * KHEAD;
    uint32_t vbh = sb + AVHI + hh * VHEAD;
    uint32_t vbl = sb + AVLO + hh * VHEAD;
    uint32_t krow = (uint32_t)(lr + khalf * 8) * 48 + lsel * 16;
    uint32_t vrow = (uint32_t)(lr + khalf * 8) * 528 + lsel * 16;

    for (int s = 0; s < 4; s++) {
        int q0 = wq * 64 + s * 16;

        uint32_t ah[4], al[4];
        {
            float2 f0 = *(const float2*)(qbase + (size_t)(q0 + g) * H_ + 2 * tg);
            float2 f1 = *(const float2*)(qbase + (size_t)(q0 + g + 8) * H_ + 2 * tg);
            float2 f2 = *(const float2*)(qbase + (size_t)(q0 + g) * H_ + 8 + 2 * tg);
            float2 f3 = *(const float2*)(qbase + (size_t)(q0 + g + 8) * H_ + 8 + 2 * tg);
            split2(f0.x, f0.y, ah[0], al[0]);
            split2(f1.x, f1.y, ah[1], al[1]);
            split2(f2.x, f2.y, ah[2], al[2]);
            split2(f3.x, f3.y, ah[3], al[3]);
        }

        float o[8];
#pragma unroll
        for (int e = 0; e < 8; e++) o[e] = 0.0f;
        float mA = -1e30f, mB = -1e30f, sA = 0.0f, sB = 0.0f;

        for (int kc = 0; kc < 4; kc++) {
            float cc[4][8];
#pragma unroll
            for (int kt = 0; kt < 4; kt++)
#pragma unroll
                for (int e = 0; e < 8; e++) cc[kt][e] = 0.0f;

#pragma unroll
            for (int kt = 0; kt < 4; kt++) {
                int kta = kc * 4 + kt;
                uint32_t bh[4], bl[4];
                ldsm4(bh[0], bh[1], bh[2], bh[3], kbh + kta * 768 + krow);
                ldsm4(bl[0], bl[1], bl[2], bl[3], kbl + kta * 768 + krow);
                mma16816(cc[kt], ah, bh[0], bh[1]);
                mma16816(cc[kt] + 4, ah, bh[2], bh[3]);
                mma16816(cc[kt], ah, bl[0], bl[1]);
                mma16816(cc[kt] + 4, ah, bl[2], bl[3]);
                mma16816(cc[kt], al, bh[0], bh[1]);
                mma16816(cc[kt] + 4, al, bh[2], bh[3]);
            }

            // chunk max per row (quad-shared)
            float cmA = -1e30f, cmB = -1e30f;
#pragma unroll
            for (int kt = 0; kt < 4; kt++)
#pragma unroll
                for (int t = 0; t < 2; t++) {
                    cmA = fmaxf(cmA, fmaxf(cc[kt][t * 4 + 0], cc[kt][t * 4 + 1]));
                    cmB = fmaxf(cmB, fmaxf(cc[kt][t * 4 + 2], cc[kt][t * 4 + 3]));
                }
            cmA = fmaxf(cmA, __shfl_xor_sync(~0u, cmA, 1));
            cmA = fmaxf(cmA, __shfl_xor_sync(~0u, cmA, 2));
            cmB = fmaxf(cmB, __shfl_xor_sync(~0u, cmB, 1));
            cmB = fmaxf(cmB, __shfl_xor_sync(~0u, cmB, 2));
            cmA *= 0.25f; cmB *= 0.25f;
            float mnA = fmaxf(mA, cmA), mnB = fmaxf(mB, cmB);
            float fA = __expf(mA - mnA), fB = __expf(mB - mnB);
            mA = mnA; mB = mnB;
            sA *= fA; sB *= fB;
#pragma unroll
            for (int t = 0; t < 2; t++) {
                o[t * 4 + 0] *= fA; o[t * 4 + 1] *= fA;
                o[t * 4 + 2] *= fB; o[t * 4 + 3] *= fB;
            }

#pragma unroll
            for (int kt = 0; kt < 4; kt++) {
                int kta = kc * 4 + kt;
                float p[8];
#pragma unroll
                for (int t = 0; t < 2; t++) {
                    p[t * 4 + 0] = __expf(cc[kt][t * 4 + 0] * 0.25f - mA);
                    p[t * 4 + 1] = __expf(cc[kt][t * 4 + 1] * 0.25f - mA);
                    p[t * 4 + 2] = __expf(cc[kt][t * 4 + 2] * 0.25f - mB);
                    p[t * 4 + 3] = __expf(cc[kt][t * 4 + 3] * 0.25f - mB);
                    sA += p[t * 4 + 0] + p[t * 4 + 1];
                    sB += p[t * 4 + 2] + p[t * 4 + 3];
                }
                uint32_t ph[4], pl[4];
                split2(p[0], p[1], ph[0], pl[0]);
                split2(p[2], p[3], ph[1], pl[1]);
                split2(p[4], p[5], ph[2], pl[2]);
                split2(p[6], p[7], ph[3], pl[3]);
                uint32_t vh[4], vl[4];
                ldsm4(vh[0], vh[1], vh[2], vh[3], vbh + vrow + kta * 32);
                ldsm4(vl[0], vl[1], vl[2], vl[3], vbl + vrow + kta * 32);
                mma16816(o, ph, vh[0], vh[1]);
                mma16816(o + 4, ph, vh[2], vh[3]);
                mma16816(o, ph, vl[0], vl[1]);
                mma16816(o + 4, ph, vl[2], vl[3]);
                mma16816(o, pl, vh[0], vh[1]);
                mma16816(o + 4, pl, vh[2], vh[3]);
            }
        }

        sA += __shfl_xor_sync(~0u, sA, 1);
        sA += __shfl_xor_sync(~0u, sA, 2);
        sB += __shfl_xor_sync(~0u, sB, 1);
        sB += __shfl_xor_sync(~0u, sB, 2);
        float invA = 1.0f / sA, invB = 1.0f / sB;

        *(float2*)(obase + (size_t)(q0 + g) * H_ + 2 * tg) =
            make_float2(o[0] * invA, o[1] * invA);
        *(float2*)(obase + (size_t)(q0 + g + 8) * H_ + 2 * tg) =
            make_float2(o[2] * invB, o[3] * invB);
        *(float2*)(obase + (size_t)(q0 + g) * H_ + 8 + 2 * tg) =
            make_float2(o[4] * invA, o[5] * invA);
        *(float2*)(obase + (size_t)(q0 + g + 8) * H_ + 8 + 2 * tg) =
            make_float2(o[6] * invB, o[7] * invB);
    }
}

// ---------------------------------------------------------------------------
// Launch
// ---------------------------------------------------------------------------
extern "C" void kernel_launch(void* const* d_in, const int* in_sizes, int n_in,
                              void* d_out, int out_size) {
    const float* x       = (const float*)d_in[0];
    const float* adj_l   = (const float*)d_in[1];
    const float* var_emb = (const float*)d_in[2];
    const float* temp_emb= (const float*)d_in[3];
    const float* mech_W  = (const float*)d_in[4];
    const float* mech_b  = (const float*)d_in[5];
    const float* ln_g    = (const float*)d_in[6];
    const float* ln_b    = (const float*)d_in[7];
    const float* Wq      = (const float*)d_in[8];
    const float* Wk      = (const float*)d_in[9];
    const float* Wv      = (const float*)d_in[10];
    const float* Wo      = (const float*)d_in[11];
    const float* bq      = (const float*)d_in[12];
    const float* bk      = (const float*)d_in[13];
    const float* bv      = (const float*)d_in[14];
    const float* bo      = (const float*)d_in[15];
    const float* out_W   = (const float*)d_in[16];
    const float* out_b   = (const float*)d_in[17];
    float* pred = (float*)d_out;

    float *zA, *qb, *kb, *vb, *ob;
    cudaGetSymbolAddress((void**)&zA, g_zA);
    cudaGetSymbolAddress((void**)&qb, g_qb);
    cudaGetSymbolAddress((void**)&kb, g_kb);
    cudaGetSymbolAddress((void**)&vb, g_vb);
    cudaGetSymbolAddress((void**)&ob, g_ob);

    cudaFuncSetAttribute((const void*)gemm_mma2<0>,
                         cudaFuncAttributeMaxDynamicSharedMemorySize, G2_SMEM);
    cudaFuncSetAttribute((const void*)gemm_mma2<1>,
                         cudaFuncAttributeMaxDynamicSharedMemorySize, G2_SMEM);
    cudaFuncSetAttribute((const void*)gemm_mma2<2>,
                         cudaFuncAttributeMaxDynamicSharedMemorySize, G2_SMEM);
    cudaFuncSetAttribute((const void*)prep_w_kernel,
                         cudaFuncAttributeMaxDynamicSharedMemorySize, PREP_SMEM);
    cudaFuncSetAttribute((const void*)causal_kernel,
                         cudaFuncAttributeMaxDynamicSharedMemorySize, CAU_SMEM);
    cudaFuncSetAttribute((const void*)attn_mma,
                         cudaFuncAttributeMaxDynamicSharedMemorySize, ATT_SMEM);

    // 0. sigmoid + weight split
    sigmoid_kernel<<<(V_ * V_ * LP1_ + 255) / 256, 256>>>(adj_l);
    prep_w_kernel<<<7 * V_, 256, PREP_SMEM>>>(mech_W, Wq, Wk, Wv, Wo);

    // 1. causal input -> zA  ([v][bt][h])
    causal_kernel<<<BT_, 256, CAU_SMEM>>>(x, var_emb, temp_emb, zA);

    // 2. mech layers: Linear -> LN -> GELU (tensor cores)
    dim3 ggrid(BT_ / 128, V_, 1);
    const int BS = NL_ * H_;
    gemm_mma2<1><<<ggrid, 256, G2_SMEM>>>(zA, 0,
        mech_b + 0 * H_, nullptr, nullptr, BS, ln_g + 0 * H_, ln_b + 0 * H_,
        ob, nullptr, nullptr, nullptr, nullptr, nullptr);
    gemm_mma2<1><<<ggrid, 256, G2_SMEM>>>(ob, 1,
        mech_b + 1 * H_, nullptr, nullptr, BS, ln_g + 1 * H_, ln_b + 1 * H_,
        zA, nullptr, nullptr, nullptr, nullptr, nullptr);
    gemm_mma2<1><<<ggrid, 256, G2_SMEM>>>(zA, 2,
        mech_b + 2 * H_, nullptr, nullptr, BS, ln_g + 2 * H_, ln_b + 2 * H_,
        ob, nullptr, nullptr, nullptr, nullptr, nullptr);

    // 3. Q/K/V projections, one launch (z -> pass 3..5)
    dim3 qkvgrid(BT_ / 128, V_, 3);
    gemm_mma2<0><<<qkvgrid, 256, G2_SMEM>>>(ob, 3,
        bq, bk, bv, H_, nullptr, nullptr,
        qb, kb, vb, nullptr, nullptr, nullptr);

    // 4. tensor-core attention -> zA
    attn_mma<<<B_ * V_ * NH_ / 2, 256, ATT_SMEM>>>(qb, kb, vb, zA);

    // 5. Wo + fused output head -> pred (pass 6)
    gemm_mma2<2><<<ggrid, 256, G2_SMEM>>>(zA, 6,
        bo, nullptr, nullptr, H_, nullptr, nullptr,
        nullptr, nullptr, nullptr, out_W, out_b, pred);
}

// round 13
// speedup vs baseline: 2.2984x; 1.0196x over previous
#include <cuda_runtime.h>
#include <cuda_bf16.h>
#include <math.h>
#include <stdint.h>

// Problem constants
#define B_  4
#define S_  256
#define V_  64
#define H_  128
#define NH_ 8
#define DH_ 16
#define LP1_ 11
#define NL_ 3
#define BT_ (B_ * S_)          // 1024
#define ZSZ (BT_ * V_ * H_)

// Scratch (device globals)
__device__ float g_adj[V_ * V_ * LP1_];
__device__ float g_zA[ZSZ];
__device__ float g_qb[ZSZ];
__device__ float g_kb[ZSZ];
__device__ float g_vb[ZSZ];
__device__ float g_ob[ZSZ];
// Pre-split weights: [pass 0..6][v][chunk 0..3][hi|lo] 10240-byte smem images
#define WIMG   10240
#define WVBLK  (4 * 2 * WIMG)    // 81920 bytes per (pass,v)
__device__ __align__(128) char g_Wc[7 * V_ * WVBLK];

extern __shared__ char SM[];

// ---------------------------------------------------------------------------
// mma.sync / ldmatrix helpers (validated R9-R11)
// ---------------------------------------------------------------------------
__device__ __forceinline__ uint32_t smem_u32(const void* p) {
    uint32_t a;
    asm("{ .reg .u64 t; cvta.to.shared.u64 t, %1; cvt.u32.u64 %0, t; }"
        : "=r"(a) : "l"(p));
    return a;
}
__device__ __forceinline__ void ldsm4(uint32_t& r0, uint32_t& r1,
                                      uint32_t& r2, uint32_t& r3, uint32_t addr) {
    asm volatile("ldmatrix.sync.aligned.m8n8.x4.shared.b16 {%0,%1,%2,%3}, [%4];"
                 : "=r"(r0), "=r"(r1), "=r"(r2), "=r"(r3) : "r"(addr));
}
__device__ __forceinline__ void mma16816(float* c, const uint32_t a[4],
                                         uint32_t b0, uint32_t b1) {
    asm volatile(
        "mma.sync.aligned.m16n8k16.row.col.f32.bf16.bf16.f32 "
        "{%0,%1,%2,%3}, {%4,%5,%6,%7}, {%8,%9}, {%0,%1,%2,%3};"
        : "+f"(c[0]), "+f"(c[1]), "+f"(c[2]), "+f"(c[3])
        : "r"(a[0]), "r"(a[1]), "r"(a[2]), "r"(a[3]), "r"(b0), "r"(b1));
}
__device__ __forceinline__ void split2(float x, float y,
                                       uint32_t& hi, uint32_t& lo) {
    __nv_bfloat162 h = __floats2bfloat162_rn(x, y);
    float rx = x - __bfloat162float(h.x);
    float ry = y - __bfloat162float(h.y);
    __nv_bfloat162 l = __floats2bfloat162_rn(rx, ry);
    hi = *(uint32_t*)&h;
    lo = *(uint32_t*)&l;
}

// ---------------------------------------------------------------------------
// Kernel 0: adj = sigmoid(adjacency_logits)
// ---------------------------------------------------------------------------
__global__ void sigmoid_kernel(const float* __restrict__ logits) {
    int i = blockIdx.x * 256 + threadIdx.x;
    if (i < V_ * V_ * LP1_) g_adj[i] = 1.0f / (1.0f + __expf(-logits[i]));
}

// ---------------------------------------------------------------------------
// Kernel P: split weights into per-chunk bf16 hi/lo smem images.
// ---------------------------------------------------------------------------
#define PREP_SMEM (128 * 132 * 4)
__global__ void prep_w_kernel(const float* __restrict__ mech_W,
                              const float* __restrict__ Wq,
                              const float* __restrict__ Wk,
                              const float* __restrict__ Wv,
                              const float* __restrict__ Wo) {
    float* Wt = (float*)SM;
    int pv = blockIdx.x;
    int pass = pv >> 6, v = pv & 63;
    const float* src;
    if (pass < 3)       src = mech_W + ((size_t)v * NL_ + pass) * H_ * H_;
    else if (pass == 3) src = Wq + (size_t)v * H_ * H_;
    else if (pass == 4) src = Wk + (size_t)v * H_ * H_;
    else if (pass == 5) src = Wv + (size_t)v * H_ * H_;
    else                src = Wo + (size_t)v * H_ * H_;

    int tid = threadIdx.x;
    for (int i = tid; i < 128 * 32; i += 256) {
        int r = i >> 5, c4 = i & 31;
        float4 a = *(const float4*)(src + (size_t)r * H_ + c4 * 4);
        *(float4*)(Wt + r * 132 + c4 * 4) = a;
    }
    __syncthreads();

    char* img = g_Wc + (size_t)pv * WVBLK;
    for (int task = tid; task < 4 * 128 * 16; task += 256) {
        int ch = task >> 11;
        int rem = task & 2047;
        int n = rem >> 4, kk2 = rem & 15;
        int k = ch * 32 + kk2 * 2;
        float w0 = Wt[k * 132 + n];
        float w1 = Wt[(k + 1) * 132 + n];
        uint32_t hi, lo;
        split2(w0, w1, hi, lo);
        *(uint32_t*)(img + (ch * 2 + 0) * WIMG + n * 80 + kk2 * 4) = hi;
        *(uint32_t*)(img + (ch * 2 + 1) * WIMG + n * 80 + kk2 * 4) = lo;
    }
}

// ---------------------------------------------------------------------------
// Kernel 1: causal input (R6 proven)
// ---------------------------------------------------------------------------
#define CAU_XW   0
#define CAU_ASM  (CAU_XW + LP1_ * 64)
#define CAU_BL   (CAU_ASM + 64 * 65)
#define CAU_VE   (CAU_BL + 64 * 12)
#define CAU_TE   (CAU_VE + 64 * 128)
#define CAU_SMEM ((CAU_TE + LP1_ * 128) * 4)

__global__ void causal_kernel(const float* __restrict__ x,
                              const float* __restrict__ var_emb,
                              const float* __restrict__ temp_emb,
                              float* __restrict__ zout) {
    float* cs = (float*)SM;
    float* xw  = cs + CAU_XW;
    float* Asm = cs + CAU_ASM;
    float* Bl  = cs + CAU_BL;
    float* ve  = cs + CAU_VE;
    float* te  = cs + CAU_TE;

    int bt = blockIdx.x;
    int b = bt / S_;
    int t = bt % S_;
    int tid = threadIdx.x;

    for (int e = tid; e < LP1_ * 64; e += 256) {
        int l = e >> 6, s2 = e & 63;
        int tt = t - l;
        xw[l * 64 + s2] = (tt >= 0) ? x[(b * S_ + tt) * V_ + s2] : 0.0f;
    }
    for (int e = tid; e < 64 * 128 / 4; e += 256)
        ((float4*)ve)[e] = ((const float4*)var_emb)[e];
    for (int e = tid; e < LP1_ * 128 / 4; e += 256)
        ((float4*)te)[e] = ((const float4*)temp_emb)[e];
    __syncthreads();

    for (int e = tid; e < 64 * 64; e += 256) {
        int i = e >> 6, s2 = e & 63;
        const float* ap = g_adj + (s2 * V_ + i) * LP1_;
        float acc = 0.0f;
#pragma unroll
        for (int l = 0; l < LP1_; l++) acc += xw[l * 64 + s2] * ap[l];
        Asm[i * 65 + s2] = acc;
    }
    for (int e = tid; e < 64 * LP1_; e += 256) {
        int i = e / LP1_, l = e % LP1_;
        float acc = 0.0f;
        for (int s2 = 0; s2 < 64; s2++)
            acc += xw[l * 64 + s2] * g_adj[(s2 * V_ + i) * LP1_ + l];
        Bl[i * 12 + l] = acc;
    }
    __syncthreads();

    int i = tid >> 2, q = tid & 3;
    float4 acc[8];
#pragma unroll
    for (int j = 0; j < 8; j++) acc[j] = make_float4(0.f, 0.f, 0.f, 0.f);

    for (int s2 = 0; s2 < 64; s2++) {
        float a = Asm[i * 65 + s2];
        const float* vr = ve + s2 * 128 + q * 4;
#pragma unroll
        for (int j = 0; j < 8; j++) {
            float4 vv = *(const float4*)(vr + j * 16);
            acc[j].x += a * vv.x; acc[j].y += a * vv.y;
            acc[j].z += a * vv.z; acc[j].w += a * vv.w;
        }
    }
#pragma unroll
    for (int l = 0; l < LP1_; l++) {
        float bl = Bl[i * 12 + l];
        const float* tr = te + l * 128 + q * 4;
#pragma unroll
        for (int j = 0; j < 8; j++) {
            float4 vv = *(const float4*)(tr + j * 16);
            acc[j].x += bl * vv.x; acc[j].y += bl * vv.y;
            acc[j].z += bl * vv.z; acc[j].w += bl * vv.w;
        }
    }
    float* zr = zout + ((size_t)i * BT_ + bt) * H_ + q * 4;
#pragma unroll
    for (int j = 0; j < 8; j++) *(float4*)(zr + j * 16) = acc[j];
}

// ---------------------------------------------------------------------------
// Kernel 2: MEGA mma — mech0..2 (+LN+GELU) then Q/K/V, activations resident
// in smem as bf16 hi/lo chunk images (same layout the mma path consumes).
// Block = (128 bt-rows, v). smem: Z 81920 + W 20480 = 102400 -> occ 2.
// ---------------------------------------------------------------------------
#define GAP 80
#define MZ_HI 0
#define MZ_LO 40960
#define MW_HI 81920
#define MW_LO 92160
#define MEGA_SMEM 102400

__global__ __launch_bounds__(256, 2) void mega_mma(
    const float* __restrict__ zin,
    const float* __restrict__ mech_b,
    const float* __restrict__ ln_g, const float* __restrict__ ln_b,
    const float* __restrict__ bq, const float* __restrict__ bk,
    const float* __restrict__ bv,
    float* __restrict__ qb, float* __restrict__ kb, float* __restrict__ vb) {
    char* smc = SM;
    uint32_t sb = smem_u32(smc);
    int tid = threadIdx.x;
    int v = blockIdx.y;
    int bt0 = blockIdx.x * 128;

    int wid = tid >> 5, lane = tid & 31;
    int g = lane >> 2, tg = lane & 3;
    int lr = lane & 7, lsel = (lane >> 3) & 1, khalf = lane >> 4;
    uint32_t aoff = (uint32_t)(wid * 16 + lr + lsel * 8) * GAP + khalf * 16;
    int r0 = wid * 16 + g;   // lane's row pair: r0, r0+8 (within tile)

    // --- initial staging: zA (fp32) -> bf16 hi/lo chunk images ---
    const float* inp = zin + ((size_t)v * BT_ + bt0) * H_;
#pragma unroll 4
    for (int t = 0; t < 16; t++) {
        int idx = tid + t * 256;
        int r = idx >> 5, c4 = idx & 31;
        float4 a = *(const float4*)(inp + (size_t)r * H_ + c4 * 4);
        uint32_t h0, l0, h1, l1;
        split2(a.x, a.y, h0, l0);
        split2(a.z, a.w, h1, l1);
        uint32_t off = (uint32_t)(c4 >> 3) * WIMG + r * GAP + (c4 & 7) * 8;
        *(uint2*)(smc + MZ_HI + off) = make_uint2(h0, h1);
        *(uint2*)(smc + MZ_LO + off) = make_uint2(l0, l1);
    }
    __syncthreads();

    for (int layer = 0; layer < 6; layer++) {
        const uint4* wimg = (const uint4*)(g_Wc + (size_t)(layer * V_ + v) * WVBLK);

        float c[16][4];
#pragma unroll
        for (int nt = 0; nt < 16; nt++)
#pragma unroll
            for (int e = 0; e < 4; e++) c[nt][e] = 0.0f;

        for (int ch = 0; ch < 4; ch++) {
            // copy W chunk image (hi 640 uint4 + lo 640)
            const uint4* src = wimg + ch * 1280;
            uint4* dst = (uint4*)(smc + MW_HI);
            for (int i = tid; i < 1280; i += 256) dst[i] = src[i];
            __syncthreads();   // also orders prev-layer epilogue Z writes

            uint32_t azh = sb + MZ_HI + ch * WIMG;
            uint32_t azl = sb + MZ_LO + ch * WIMG;
#pragma unroll
            for (int sub = 0; sub < 2; sub++) {
                uint32_t ah[4], al[4];
                ldsm4(ah[0], ah[1], ah[2], ah[3], azh + aoff + sub * 32);
                ldsm4(al[0], al[1], al[2], al[3], azl + aoff + sub * 32);
#pragma unroll
                for (int bq8 = 0; bq8 < 8; bq8++) {
                    uint32_t bo = (uint32_t)(bq8 * 16 + lr + khalf * 8) * GAP
                                + lsel * 16 + sub * 32;
                    uint32_t bh[4], bl[4];
                    ldsm4(bh[0], bh[1], bh[2], bh[3], sb + MW_HI + bo);
                    ldsm4(bl[0], bl[1], bl[2], bl[3], sb + MW_LO + bo);
                    mma16816(c[2 * bq8 + 0], ah, bh[0], bh[1]);
                    mma16816(c[2 * bq8 + 1], ah, bh[2], bh[3]);
                    mma16816(c[2 * bq8 + 0], ah, bl[0], bl[1]);
                    mma16816(c[2 * bq8 + 1], ah, bl[2], bl[3]);
                    mma16816(c[2 * bq8 + 0], al, bh[0], bh[1]);
                    mma16816(c[2 * bq8 + 1], al, bh[2], bh[3]);
                }
            }
            __syncthreads();   // W buffer reuse next chunk
        }

        if (layer < 3) {
            // bias + LN + GELU, write back into Z chunk images
            const float* bias = mech_b + ((size_t)v * NL_ + layer) * H_;
            const float* gg = ln_g + ((size_t)v * NL_ + layer) * H_;
            const float* nb = ln_b + ((size_t)v * NL_ + layer) * H_;
            float sA = 0.0f, sB = 0.0f;
#pragma unroll
            for (int nt = 0; nt < 16; nt++) {
                float2 b2 = __ldg((const float2*)(bias + nt * 8 + 2 * tg));
                c[nt][0] += b2.x; c[nt][1] += b2.y;
                c[nt][2] += b2.x; c[nt][3] += b2.y;
                sA += c[nt][0] + c[nt][1];
                sB += c[nt][2] + c[nt][3];
            }
            sA += __shfl_xor_sync(~0u, sA, 1); sA += __shfl_xor_sync(~0u, sA, 2);
            sB += __shfl_xor_sync(~0u, sB, 1); sB += __shfl_xor_sync(~0u, sB, 2);
            float muA = sA * (1.0f / H_), muB = sB * (1.0f / H_);
            float qA = 0.0f, qB = 0.0f;
#pragma unroll
            for (int nt = 0; nt < 16; nt++) {
                c[nt][0] -= muA; c[nt][1] -= muA;
                c[nt][2] -= muB; c[nt][3] -= muB;
                qA += c[nt][0] * c[nt][0] + c[nt][1] * c[nt][1];
                qB += c[nt][2] * c[nt][2] + c[nt][3] * c[nt][3];
            }
            qA += __shfl_xor_sync(~0u, qA, 1); qA += __shfl_xor_sync(~0u, qA, 2);
            qB += __shfl_xor_sync(~0u, qB, 1); qB += __shfl_xor_sync(~0u, qB, 2);
            float ivA = rsqrtf(qA * (1.0f / H_) + 1e-5f);
            float ivB = rsqrtf(qB * (1.0f / H_) + 1e-5f);
#pragma unroll
            for (int nt = 0; nt < 16; nt++) {
                float2 g2 = __ldg((const float2*)(gg + nt * 8 + 2 * tg));
                float2 n2 = __ldg((const float2*)(nb + nt * 8 + 2 * tg));
                float y0 = c[nt][0] * ivA * g2.x + n2.x;
                float y1 = c[nt][1] * ivA * g2.y + n2.y;
                float y2 = c[nt][2] * ivB * g2.x + n2.x;
                float y3 = c[nt][3] * ivB * g2.y + n2.y;
                y0 = y0 * 0.5f * (1.0f + erff(y0 * 0.70710678118654752f));
                y1 = y1 * 0.5f * (1.0f + erff(y1 * 0.70710678118654752f));
                y2 = y2 * 0.5f * (1.0f + erff(y2 * 0.70710678118654752f));
                y3 = y3 * 0.5f * (1.0f + erff(y3 * 0.70710678118654752f));
                uint32_t hiA, loA, hiB, loB;
                split2(y0, y1, hiA, loA);
                split2(y2, y3, hiB, loB);
                uint32_t addr = (uint32_t)(nt >> 2) * WIMG + r0 * GAP
                              + ((nt & 3) * 4 + tg) * 4;
                *(uint32_t*)(smc + MZ_HI + addr) = hiA;
                *(uint32_t*)(smc + MZ_LO + addr) = loA;
                *(uint32_t*)(smc + MZ_HI + addr + 8 * GAP) = hiB;
                *(uint32_t*)(smc + MZ_LO + addr + 8 * GAP) = loB;
            }
            // next layer's post-W-copy sync orders these writes
        } else {
            const float* bias = (layer == 3 ? bq : layer == 4 ? bk : bv)
                              + (size_t)v * H_;
            float* out = (layer == 3 ? qb : layer == 4 ? kb : vb);
            float* ob0 = out + ((size_t)v * BT_ + bt0 + r0) * H_;
            float* ob1 = ob0 + 8 * H_;
#pragma unroll
            for (int nt = 0; nt < 16; nt++) {
                float2 b2 = __ldg((const float2*)(bias + nt * 8 + 2 * tg));
                *(float2*)(ob0 + nt * 8 + 2 * tg) =
                    make_float2(c[nt][0] + b2.x, c[nt][1] + b2.y);
                *(float2*)(ob1 + nt * 8 + 2 * tg) =
                    make_float2(c[nt][2] + b2.x, c[nt][3] + b2.y);
            }
        }
    }
}

// ---------------------------------------------------------------------------
// Kernel 2b: Wo GEMM + fused output head (gemm_mma2 MODE 2, R11 proven)
// ---------------------------------------------------------------------------
#define GB_HI 20480
#define GB_LO 30720
#define G2_SMEM 40960

__global__ __launch_bounds__(256, 2) void wo_head_mma(
    const float* __restrict__ in,
    const float* __restrict__ bo,
    const float* __restrict__ OW, const float* __restrict__ OB,
    float* __restrict__ PRED) {
    char* smc = SM;
    uint32_t sb = smem_u32(smc);
    int tid = threadIdx.x;
    int v = blockIdx.y;
    int bt0 = blockIdx.x * 128;

    const float* bias = bo + (size_t)v * H_;
    const float* inp = in + ((size_t)v * BT_ + bt0) * H_;
    const uint4* wimg = (const uint4*)(g_Wc + (size_t)(6 * V_ + v) * WVBLK);

    int wid = tid >> 5, lane = tid & 31;
    int g = lane >> 2, tg = lane & 3;
    int lr = lane & 7, lsel = (lane >> 3) & 1, khalf = lane >> 4;
    uint32_t aoff = (uint32_t)(wid * 16 + lr + lsel * 8) * GAP + khalf * 16;

    float c[16][4];
#pragma unroll
    for (int nt = 0; nt < 16; nt++)
#pragma unroll
        for (int e = 0; e < 4; e++) c[nt][e] = 0.0f;

    for (int ch = 0; ch < 4; ch++) {
#pragma unroll
        for (int t = 0; t < 4; t++) {
            int idx = tid + t * 256;
            int r = idx >> 3, c4 = idx & 7;
            float4 a = *(const float4*)(inp + (size_t)r * H_ + ch * 32 + c4 * 4);
            uint32_t h0, l0, h1, l1;
            split2(a.x, a.y, h0, l0);
            split2(a.z, a.w, h1, l1);
            *(uint2*)(smc + r * GAP + c4 * 8) = make_uint2(h0, h1);
            *(uint2*)(smc + 10240 + r * GAP + c4 * 8) = make_uint2(l0, l1);
        }
        {
            const uint4* src = wimg + ch * 1280;
            uint4* dst = (uint4*)(smc + GB_HI);
            for (int i = tid; i < 1280; i += 256) dst[i] = src[i];
        }
        __syncthreads();

#pragma unroll
        for (int sub = 0; sub < 2; sub++) {
            uint32_t ah[4], al[4];
            ldsm4(ah[0], ah[1], ah[2], ah[3], sb + aoff + sub * 32);
            ldsm4(al[0], al[1], al[2], al[3], sb + 10240 + aoff + sub * 32);
#pragma unroll
            for (int bq8 = 0; bq8 < 8; bq8++) {
                uint32_t bo2 = (uint32_t)(bq8 * 16 + lr + khalf * 8) * GAP
                             + lsel * 16 + sub * 32;
                uint32_t bh[4], bl[4];
                ldsm4(bh[0], bh[1], bh[2], bh[3], sb + GB_HI + bo2);
                ldsm4(bl[0], bl[1], bl[2], bl[3], sb + GB_LO + bo2);
                mma16816(c[2 * bq8 + 0], ah, bh[0], bh[1]);
                mma16816(c[2 * bq8 + 1], ah, bh[2], bh[3]);
                mma16816(c[2 * bq8 + 0], ah, bl[0], bl[1]);
                mma16816(c[2 * bq8 + 1], ah, bl[2], bl[3]);
                mma16816(c[2 * bq8 + 0], al, bh[0], bh[1]);
                mma16816(c[2 * bq8 + 1], al, bh[2], bh[3]);
            }
        }
        __syncthreads();
    }

    int r0 = bt0 + wid * 16 + g;
    const float* ow = OW + (size_t)v * H_;
    float s0 = 0.0f, s1 = 0.0f;
#pragma unroll
    for (int nt = 0; nt < 16; nt++) {
        float2 b2 = __ldg((const float2*)(bias + nt * 8 + 2 * tg));
        float2 w2 = __ldg((const float2*)(ow + nt * 8 + 2 * tg));
        s0 += (c[nt][0] + b2.x) * w2.x + (c[nt][1] + b2.y) * w2.y;
        s1 += (c[nt][2] + b2.x) * w2.x + (c[nt][3] + b2.y) * w2.y;
    }
    s0 += __shfl_xor_sync(~0u, s0, 1); s0 += __shfl_xor_sync(~0u, s0, 2);
    s1 += __shfl_xor_sync(~0u, s1, 1); s1 += __shfl_xor_sync(~0u, s1, 2);
    if (tg == 0) {
        float obv = OB[v];
        PRED[(size_t)r0 * V_ + v] = s0 + obv;
        PRED[(size_t)(r0 + 8) * V_ + v] = s1 + obv;
    }
}

// ---------------------------------------------------------------------------
// Kernel 3: tensor-core attention, online softmax (R11 proven)
// ---------------------------------------------------------------------------
#define AKHI 0
#define AKLO 24576
#define AVHI 49152
#define AVLO 66048
#define ATT_SMEM 82944
#define KHEAD 12288
#define VHEAD 8448

__global__ __launch_bounds__(256, 2) void attn_mma(
        const float* __restrict__ qg,
        const float* __restrict__ kg,
        const float* __restrict__ vg,
        float* __restrict__ og) {
    char* smc = SM;
    uint32_t sb = smem_u32(smc);
    int id = blockIdx.x;
    int hp = id & 3;
    int vv = (id >> 2) & 63;
    int b  = id >> 8;
    int tid = threadIdx.x;

    size_t vbase = ((size_t)vv * BT_ + b * S_) * H_;

    for (int i = tid; i < 8192; i += 256) {
        int col = i & 31;
        int key = i >> 5;
        int hh = col >> 4, d = col & 15;
        size_t gidx = vbase + (size_t)key * H_ + hp * 32 + col;
        float kv = kg[gidx];
        __nv_bfloat16 kh = __float2bfloat16(kv);
        __nv_bfloat16 kl = __float2bfloat16(kv - __bfloat162float(kh));
        *(__nv_bfloat16*)(smc + AKHI + hh * KHEAD + key * 48 + d * 2) = kh;
        *(__nv_bfloat16*)(smc + AKLO + hh * KHEAD + key * 48 + d * 2) = kl;
        float vvv = vg[gidx];
        __nv_bfloat16 vh = __float2bfloat16(vvv);
        __nv_bfloat16 vl = __float2bfloat16(vvv - __bfloat162float(vh));
        *(__nv_bfloat16*)(smc + AVHI + hh * VHEAD + d * 528 + key * 2) = vh;
        *(__nv_bfloat16*)(smc + AVLO + hh * VHEAD + d * 528 + key * 2) = vl;
    }
    __syncthreads();

    int wid = tid >> 5, lane = tid & 31;
    int hh = wid >> 2, wq = wid & 3;
    int g = lane >> 2, tg = lane & 3;
    int lr = lane & 7, lsel = (lane >> 3) & 1, khalf = lane >> 4;

    const float* qbase = qg + vbase + hp * 32 + hh * 16;
    float* obase = og + vbase + hp * 32 + hh * 16;

    uint32_t kbh = sb + AKHI + hh * KHEAD;
    uint32_t kbl = sb + AKLO + hh * KHEAD;
    uint32_t vbh = sb + AVHI + hh * VHEAD;
    uint32_t vbl = sb + AVLO + hh * VHEAD;
    uint32_t krow = (uint32_t)(lr + khalf * 8) * 48 + lsel * 16;
    uint32_t vrow = (uint32_t)(lr + khalf * 8) * 528 + lsel * 16;

    for (int s = 0; s < 4; s++) {
        int q0 = wq * 64 + s * 16;

        uint32_t ah[4], al[4];
        {
            float2 f0 = *(const float2*)(qbase + (size_t)(q0 + g) * H_ + 2 * tg);
            float2 f1 = *(const float2*)(qbase + (size_t)(q0 + g + 8) * H_ + 2 * tg);
            float2 f2 = *(const float2*)(qbase + (size_t)(q0 + g) * H_ + 8 + 2 * tg);
            float2 f3 = *(const float2*)(qbase + (size_t)(q0 + g + 8) * H_ + 8 + 2 * tg);
            split2(f0.x, f0.y, ah[0], al[0]);
            split2(f1.x, f1.y, ah[1], al[1]);
            split2(f2.x, f2.y, ah[2], al[2]);
            split2(f3.x, f3.y, ah[3], al[3]);
        }

        float o[8];
#pragma unroll
        for (int e = 0; e < 8; e++) o[e] = 0.0f;
        float mA = -1e30f, mB = -1e30f, sA = 0.0f, sB = 0.0f;

        for (int kc = 0; kc < 4; kc++) {
            float cc[4][8];
#pragma unroll
            for (int kt = 0; kt < 4; kt++)
#pragma unroll
                for (int e = 0; e < 8; e++) cc[kt][e] = 0.0f;

#pragma unroll
            for (int kt = 0; kt < 4; kt++) {
                int kta = kc * 4 + kt;
                uint32_t bh[4], bl[4];
                ldsm4(bh[0], bh[1], bh[2], bh[3], kbh + kta * 768 + krow);
                ldsm4(bl[0], bl[1], bl[2], bl[3], kbl + kta * 768 + krow);
                mma16816(cc[kt], ah, bh[0], bh[1]);
                mma16816(cc[kt] + 4, ah, bh[2], bh[3]);
                mma16816(cc[kt], ah, bl[0], bl[1]);
                mma16816(cc[kt] + 4, ah, bl[2], bl[3]);
                mma16816(cc[kt], al, bh[0], bh[1]);
                mma16816(cc[kt] + 4, al, bh[2], bh[3]);
            }

            float cmA = -1e30f, cmB = -1e30f;
#pragma unroll
            for (int kt = 0; kt < 4; kt++)
#pragma unroll
                for (int t = 0; t < 2; t++) {
                    cmA = fmaxf(cmA, fmaxf(cc[kt][t * 4 + 0], cc[kt][t * 4 + 1]));
                    cmB = fmaxf(cmB, fmaxf(cc[kt][t * 4 + 2], cc[kt][t * 4 + 3]));
                }
            cmA = fmaxf(cmA, __shfl_xor_sync(~0u, cmA, 1));
            cmA = fmaxf(cmA, __shfl_xor_sync(~0u, cmA, 2));
            cmB = fmaxf(cmB, __shfl_xor_sync(~0u, cmB, 1));
            cmB = fmaxf(cmB, __shfl_xor_sync(~0u, cmB, 2));
            cmA *= 0.25f; cmB *= 0.25f;
            float mnA = fmaxf(mA, cmA), mnB = fmaxf(mB, cmB);
            float fA = __expf(mA - mnA), fB = __expf(mB - mnB);
            mA = mnA; mB = mnB;
            sA *= fA; sB *= fB;
#pragma unroll
            for (int t = 0; t < 2; t++) {
                o[t * 4 + 0] *= fA; o[t * 4 + 1] *= fA;
                o[t * 4 + 2] *= fB; o[t * 4 + 3] *= fB;
            }

#pragma unroll
            for (int kt = 0; kt < 4; kt++) {
                int kta = kc * 4 + kt;
                float p[8];
#pragma unroll
                for (int t = 0; t < 2; t++) {
                    p[t * 4 + 0] = __expf(cc[kt][t * 4 + 0] * 0.25f - mA);
                    p[t * 4 + 1] = __expf(cc[kt][t * 4 + 1] * 0.25f - mA);
                    p[t * 4 + 2] = __expf(cc[kt][t * 4 + 2] * 0.25f - mB);
                    p[t * 4 + 3] = __expf(cc[kt][t * 4 + 3] * 0.25f - mB);
                    sA += p[t * 4 + 0] + p[t * 4 + 1];
                    sB += p[t * 4 + 2] + p[t * 4 + 3];
                }
                uint32_t ph[4], pl[4];
                split2(p[0], p[1], ph[0], pl[0]);
                split2(p[2], p[3], ph[1], pl[1]);
                split2(p[4], p[5], ph[2], pl[2]);
                split2(p[6], p[7], ph[3], pl[3]);
                uint32_t vh[4], vl[4];
                ldsm4(vh[0], vh[1], vh[2], vh[3], vbh + vrow + kta * 32);
                ldsm4(vl[0], vl[1], vl[2], vl[3], vbl + vrow + kta * 32);
                mma16816(o, ph, vh[0], vh[1]);
                mma16816(o + 4, ph, vh[2], vh[3]);
                mma16816(o, ph, vl[0], vl[1]);
                mma16816(o + 4, ph, vl[2], vl[3]);
                mma16816(o, pl, vh[0], vh[1]);
                mma16816(o + 4, pl, vh[2], vh[3]);
            }
        }

        sA += __shfl_xor_sync(~0u, sA, 1);
        sA += __shfl_xor_sync(~0u, sA, 2);
        sB += __shfl_xor_sync(~0u, sB, 1);
        sB += __shfl_xor_sync(~0u, sB, 2);
        float invA = 1.0f / sA, invB = 1.0f / sB;

        *(float2*)(obase + (size_t)(q0 + g) * H_ + 2 * tg) =
            make_float2(o[0] * invA, o[1] * invA);
        *(float2*)(obase + (size_t)(q0 + g + 8) * H_ + 2 * tg) =
            make_float2(o[2] * invB, o[3] * invB);
        *(float2*)(obase + (size_t)(q0 + g) * H_ + 8 + 2 * tg) =
            make_float2(o[4] * invA, o[5] * invA);
        *(float2*)(obase + (size_t)(q0 + g + 8) * H_ + 8 + 2 * tg) =
            make_float2(o[6] * invB, o[7] * invB);
    }
}

// ---------------------------------------------------------------------------
// Launch
// ---------------------------------------------------------------------------
extern "C" void kernel_launch(void* const* d_in, const int* in_sizes, int n_in,
                              void* d_out, int out_size) {
    const float* x       = (const float*)d_in[0];
    const float* adj_l   = (const float*)d_in[1];
    const float* var_emb = (const float*)d_in[2];
    const float* temp_emb= (const float*)d_in[3];
    const float* mech_W  = (const float*)d_in[4];
    const float* mech_b  = (const float*)d_in[5];
    const float* ln_g    = (const float*)d_in[6];
    const float* ln_b    = (const float*)d_in[7];
    const float* Wq      = (const float*)d_in[8];
    const float* Wk      = (const float*)d_in[9];
    const float* Wv      = (const float*)d_in[10];
    const float* Wo      = (const float*)d_in[11];
    const float* bq      = (const float*)d_in[12];
    const float* bk      = (const float*)d_in[13];
    const float* bv      = (const float*)d_in[14];
    const float* bo      = (const float*)d_in[15];
    const float* out_W   = (const float*)d_in[16];
    const float* out_b   = (const float*)d_in[17];
    float* pred = (float*)d_out;

    float *zA, *qb, *kb, *vb, *ob;
    cudaGetSymbolAddress((void**)&zA, g_zA);
    cudaGetSymbolAddress((void**)&qb, g_qb);
    cudaGetSymbolAddress((void**)&kb, g_kb);
    cudaGetSymbolAddress((void**)&vb, g_vb);
    cudaGetSymbolAddress((void**)&ob, g_ob);

    cudaFuncSetAttribute((const void*)mega_mma,
                         cudaFuncAttributeMaxDynamicSharedMemorySize, MEGA_SMEM);
    cudaFuncSetAttribute((const void*)wo_head_mma,
                         cudaFuncAttributeMaxDynamicSharedMemorySize, G2_SMEM);
    cudaFuncSetAttribute((const void*)prep_w_kernel,
                         cudaFuncAttributeMaxDynamicSharedMemorySize, PREP_SMEM);
    cudaFuncSetAttribute((const void*)causal_kernel,
                         cudaFuncAttributeMaxDynamicSharedMemorySize, CAU_SMEM);
    cudaFuncSetAttribute((const void*)attn_mma,
                         cudaFuncAttributeMaxDynamicSharedMemorySize, ATT_SMEM);

    // 0. sigmoid + weight split
    sigmoid_kernel<<<(V_ * V_ * LP1_ + 255) / 256, 256>>>(adj_l);
    prep_w_kernel<<<7 * V_, 256, PREP_SMEM>>>(mech_W, Wq, Wk, Wv, Wo);

    // 1. causal input -> zA  ([v][bt][h])
    causal_kernel<<<BT_, 256, CAU_SMEM>>>(x, var_emb, temp_emb, zA);

    // 2. MEGA: mech0..2 + Q/K/V, activations resident in smem
    dim3 mgrid(BT_ / 128, V_);
    mega_mma<<<mgrid, 256, MEGA_SMEM>>>(zA, mech_b, ln_g, ln_b,
                                        bq, bk, bv, qb, kb, vb);

    // 3. tensor-core attention -> ob
    attn_mma<<<B_ * V_ * NH_ / 2, 256, ATT_SMEM>>>(qb, kb, vb, ob);

    // 4. Wo + fused output head -> pred
    wo_head_mma<<<mgrid, 256, G2_SMEM>>>(ob, bo, out_W, out_b, pred);
}

// round 14
// speedup vs baseline: 2.4270x; 1.0559x over previous
#include <cuda_runtime.h>
#include <cuda_bf16.h>
#include <math.h>
#include <stdint.h>

// Problem constants
#define B_  4
#define S_  256
#define V_  64
#define H_  128
#define NH_ 8
#define DH_ 16
#define LP1_ 11
#define NL_ 3
#define BT_ (B_ * S_)          // 1024
#define ZSZ (BT_ * V_ * H_)

// Scratch (device globals)
__device__ float g_adj[V_ * V_ * LP1_];
__device__ float g_zA[ZSZ];
__device__ float g_qb[ZSZ];
__device__ float g_kb[ZSZ];
__device__ float g_vb[ZSZ];
__device__ float g_ob[ZSZ];
// Pre-split weights: [pass 0..6][v][chunk 0..3][hi|lo] 10240-byte smem images
#define WIMG   10240
#define WVBLK  (4 * 2 * WIMG)    // 81920 bytes per (pass,v)
__device__ __align__(128) char g_Wc[7 * V_ * WVBLK];

extern __shared__ char SM[];

// ---------------------------------------------------------------------------
// mma.sync / ldmatrix helpers (validated R9-R13)
// ---------------------------------------------------------------------------
__device__ __forceinline__ uint32_t smem_u32(const void* p) {
    uint32_t a;
    asm("{ .reg .u64 t; cvta.to.shared.u64 t, %1; cvt.u32.u64 %0, t; }"
        : "=r"(a) : "l"(p));
    return a;
}
__device__ __forceinline__ void ldsm4(uint32_t& r0, uint32_t& r1,
                                      uint32_t& r2, uint32_t& r3, uint32_t addr) {
    asm volatile("ldmatrix.sync.aligned.m8n8.x4.shared.b16 {%0,%1,%2,%3}, [%4];"
                 : "=r"(r0), "=r"(r1), "=r"(r2), "=r"(r3) : "r"(addr));
}
__device__ __forceinline__ void mma16816(float* c, const uint32_t a[4],
                                         uint32_t b0, uint32_t b1) {
    asm volatile(
        "mma.sync.aligned.m16n8k16.row.col.f32.bf16.bf16.f32 "
        "{%0,%1,%2,%3}, {%4,%5,%6,%7}, {%8,%9}, {%0,%1,%2,%3};"
        : "+f"(c[0]), "+f"(c[1]), "+f"(c[2]), "+f"(c[3])
        : "r"(a[0]), "r"(a[1]), "r"(a[2]), "r"(a[3]), "r"(b0), "r"(b1));
}
__device__ __forceinline__ void split2(float x, float y,
                                       uint32_t& hi, uint32_t& lo) {
    __nv_bfloat162 h = __floats2bfloat162_rn(x, y);
    float rx = x - __bfloat162float(h.x);
    float ry = y - __bfloat162float(h.y);
    __nv_bfloat162 l = __floats2bfloat162_rn(rx, ry);
    hi = *(uint32_t*)&h;
    lo = *(uint32_t*)&l;
}

// ---------------------------------------------------------------------------
// Kernel 0: adj = sigmoid(adjacency_logits)
// ---------------------------------------------------------------------------
__global__ void sigmoid_kernel(const float* __restrict__ logits) {
    int i = blockIdx.x * 256 + threadIdx.x;
    if (i < V_ * V_ * LP1_) g_adj[i] = 1.0f / (1.0f + __expf(-logits[i]));
}

// ---------------------------------------------------------------------------
// Kernel P: split weights into per-chunk bf16 hi/lo smem images.
// ---------------------------------------------------------------------------
#define PREP_SMEM (128 * 132 * 4)
__global__ void prep_w_kernel(const float* __restrict__ mech_W,
                              const float* __restrict__ Wq,
                              const float* __restrict__ Wk,
                              const float* __restrict__ Wv,
                              const float* __restrict__ Wo) {
    float* Wt = (float*)SM;
    int pv = blockIdx.x;
    int pass = pv >> 6, v = pv & 63;
    const float* src;
    if (pass < 3)       src = mech_W + ((size_t)v * NL_ + pass) * H_ * H_;
    else if (pass == 3) src = Wq + (size_t)v * H_ * H_;
    else if (pass == 4) src = Wk + (size_t)v * H_ * H_;
    else if (pass == 5) src = Wv + (size_t)v * H_ * H_;
    else                src = Wo + (size_t)v * H_ * H_;

    int tid = threadIdx.x;
    for (int i = tid; i < 128 * 32; i += 256) {
        int r = i >> 5, c4 = i & 31;
        float4 a = *(const float4*)(src + (size_t)r * H_ + c4 * 4);
        *(float4*)(Wt + r * 132 + c4 * 4) = a;
    }
    __syncthreads();

    char* img = g_Wc + (size_t)pv * WVBLK;
    for (int task = tid; task < 4 * 128 * 16; task += 256) {
        int ch = task >> 11;
        int rem = task & 2047;
        int n = rem >> 4, kk2 = rem & 15;
        int k = ch * 32 + kk2 * 2;
        float w0 = Wt[k * 132 + n];
        float w1 = Wt[(k + 1) * 132 + n];
        uint32_t hi, lo;
        split2(w0, w1, hi, lo);
        *(uint32_t*)(img + (ch * 2 + 0) * WIMG + n * 80 + kk2 * 4) = hi;
        *(uint32_t*)(img + (ch * 2 + 1) * WIMG + n * 80 + kk2 * 4) = lo;
    }
}

// ---------------------------------------------------------------------------
// Kernel 1: causal input (R6 proven)
// ---------------------------------------------------------------------------
#define CAU_XW   0
#define CAU_ASM  (CAU_XW + LP1_ * 64)
#define CAU_BL   (CAU_ASM + 64 * 65)
#define CAU_VE   (CAU_BL + 64 * 12)
#define CAU_TE   (CAU_VE + 64 * 128)
#define CAU_SMEM ((CAU_TE + LP1_ * 128) * 4)

__global__ void causal_kernel(const float* __restrict__ x,
                              const float* __restrict__ var_emb,
                              const float* __restrict__ temp_emb,
                              float* __restrict__ zout) {
    float* cs = (float*)SM;
    float* xw  = cs + CAU_XW;
    float* Asm = cs + CAU_ASM;
    float* Bl  = cs + CAU_BL;
    float* ve  = cs + CAU_VE;
    float* te  = cs + CAU_TE;

    int bt = blockIdx.x;
    int b = bt / S_;
    int t = bt % S_;
    int tid = threadIdx.x;

    for (int e = tid; e < LP1_ * 64; e += 256) {
        int l = e >> 6, s2 = e & 63;
        int tt = t - l;
        xw[l * 64 + s2] = (tt >= 0) ? x[(b * S_ + tt) * V_ + s2] : 0.0f;
    }
    for (int e = tid; e < 64 * 128 / 4; e += 256)
        ((float4*)ve)[e] = ((const float4*)var_emb)[e];
    for (int e = tid; e < LP1_ * 128 / 4; e += 256)
        ((float4*)te)[e] = ((const float4*)temp_emb)[e];
    __syncthreads();

    for (int e = tid; e < 64 * 64; e += 256) {
        int i = e >> 6, s2 = e & 63;
        const float* ap = g_adj + (s2 * V_ + i) * LP1_;
        float acc = 0.0f;
#pragma unroll
        for (int l = 0; l < LP1_; l++) acc += xw[l * 64 + s2] * ap[l];
        Asm[i * 65 + s2] = acc;
    }
    for (int e = tid; e < 64 * LP1_; e += 256) {
        int i = e / LP1_, l = e % LP1_;
        float acc = 0.0f;
        for (int s2 = 0; s2 < 64; s2++)
            acc += xw[l * 64 + s2] * g_adj[(s2 * V_ + i) * LP1_ + l];
        Bl[i * 12 + l] = acc;
    }
    __syncthreads();

    int i = tid >> 2, q = tid & 3;
    float4 acc[8];
#pragma unroll
    for (int j = 0; j < 8; j++) acc[j] = make_float4(0.f, 0.f, 0.f, 0.f);

    for (int s2 = 0; s2 < 64; s2++) {
        float a = Asm[i * 65 + s2];
        const float* vr = ve + s2 * 128 + q * 4;
#pragma unroll
        for (int j = 0; j < 8; j++) {
            float4 vv = *(const float4*)(vr + j * 16);
            acc[j].x += a * vv.x; acc[j].y += a * vv.y;
            acc[j].z += a * vv.z; acc[j].w += a * vv.w;
        }
    }
#pragma unroll
    for (int l = 0; l < LP1_; l++) {
        float bl = Bl[i * 12 + l];
        const float* tr = te + l * 128 + q * 4;
#pragma unroll
        for (int j = 0; j < 8; j++) {
            float4 vv = *(const float4*)(tr + j * 16);
            acc[j].x += bl * vv.x; acc[j].y += bl * vv.y;
            acc[j].z += bl * vv.z; acc[j].w += bl * vv.w;
        }
    }
    float* zr = zout + ((size_t)i * BT_ + bt) * H_ + q * 4;
#pragma unroll
    for (int j = 0; j < 8; j++) *(float4*)(zr + j * 16) = acc[j];
}

// ---------------------------------------------------------------------------
// Kernel 2: MEGA mma v2 — 512 threads, 16 warps, warp = 16 rows x 64 cols.
// c[8][4] = 32 regs -> target <=64 regs, occ 2 => 32 warps/SM.
// LN uses cross-warp E[x]/E[x^2] reduction through a scratch aliasing MW.
// smem: Z 81920 + W 20480 = 102400.
// ---------------------------------------------------------------------------
#define GAP 80
#define MZ_HI 0
#define MZ_LO 40960
#define MW_HI 81920
#define MW_LO 92160
#define MEGA_SMEM 102400

__global__ __launch_bounds__(512, 2) void mega_mma(
    const float* __restrict__ zin,
    const float* __restrict__ mech_b,
    const float* __restrict__ ln_g, const float* __restrict__ ln_b,
    const float* __restrict__ bq, const float* __restrict__ bk,
    const float* __restrict__ bv,
    float* __restrict__ qb, float* __restrict__ kb, float* __restrict__ vb) {
    char* smc = SM;
    uint32_t sb = smem_u32(smc);
    int tid = threadIdx.x;
    int v = blockIdx.y;
    int bt0 = blockIdx.x * 128;

    int wid = tid >> 5, lane = tid & 31;
    int ch2 = wid >> 3;       // column half (0: cols 0-63, 1: cols 64-127)
    int rg  = wid & 7;        // row group (16 rows each)
    int g = lane >> 2, tg = lane & 3;
    int lr = lane & 7, lsel = (lane >> 3) & 1, khalf = lane >> 4;
    uint32_t aoff = (uint32_t)(rg * 16 + lr + lsel * 8) * GAP + khalf * 16;
    int r0 = rg * 16 + g;     // lane's row pair: r0, r0+8 (within tile)

    // --- initial staging: zA (fp32) -> bf16 hi/lo chunk images ---
    const float* inp = zin + ((size_t)v * BT_ + bt0) * H_;
#pragma unroll
    for (int t = 0; t < 8; t++) {
        int idx = tid + t * 512;
        int r = idx >> 5, c4 = idx & 31;
        float4 a = *(const float4*)(inp + (size_t)r * H_ + c4 * 4);
        uint32_t h0, l0, h1, l1;
        split2(a.x, a.y, h0, l0);
        split2(a.z, a.w, h1, l1);
        uint32_t off = (uint32_t)(c4 >> 3) * WIMG + r * GAP + (c4 & 7) * 8;
        *(uint2*)(smc + MZ_HI + off) = make_uint2(h0, h1);
        *(uint2*)(smc + MZ_LO + off) = make_uint2(l0, l1);
    }
    __syncthreads();

    for (int layer = 0; layer < 6; layer++) {
        const uint4* wimg = (const uint4*)(g_Wc + (size_t)(layer * V_ + v) * WVBLK);

        float c[8][4];
#pragma unroll
        for (int nt = 0; nt < 8; nt++)
#pragma unroll
            for (int e = 0; e < 4; e++) c[nt][e] = 0.0f;

        for (int ch = 0; ch < 4; ch++) {
            const uint4* src = wimg + ch * 1280;
            uint4* dst = (uint4*)(smc + MW_HI);
            for (int i = tid; i < 1280; i += 512) dst[i] = src[i];
            __syncthreads();   // also orders prev-layer epilogue Z writes

            uint32_t azh = sb + MZ_HI + ch * WIMG;
            uint32_t azl = sb + MZ_LO + ch * WIMG;
#pragma unroll
            for (int sub = 0; sub < 2; sub++) {
                uint32_t ah[4], al[4];
                ldsm4(ah[0], ah[1], ah[2], ah[3], azh + aoff + sub * 32);
                ldsm4(al[0], al[1], al[2], al[3], azl + aoff + sub * 32);
#pragma unroll
                for (int bq8 = 0; bq8 < 4; bq8++) {
                    uint32_t bo = (uint32_t)(ch2 * 64 + bq8 * 16 + lr + khalf * 8) * GAP
                                + lsel * 16 + sub * 32;
                    uint32_t bh[4], bl[4];
                    ldsm4(bh[0], bh[1], bh[2], bh[3], sb + MW_HI + bo);
                    ldsm4(bl[0], bl[1], bl[2], bl[3], sb + MW_LO + bo);
                    mma16816(c[2 * bq8 + 0], ah, bh[0], bh[1]);
                    mma16816(c[2 * bq8 + 1], ah, bh[2], bh[3]);
                    mma16816(c[2 * bq8 + 0], ah, bl[0], bl[1]);
                    mma16816(c[2 * bq8 + 1], ah, bl[2], bl[3]);
                    mma16816(c[2 * bq8 + 0], al, bh[0], bh[1]);
                    mma16816(c[2 * bq8 + 1], al, bh[2], bh[3]);
                }
            }
            __syncthreads();   // W buffer reuse next chunk
        }

        if (layer < 3) {
            const float* bias = mech_b + ((size_t)v * NL_ + layer) * H_ + ch2 * 64;
            const float* gg = ln_g + ((size_t)v * NL_ + layer) * H_ + ch2 * 64;
            const float* nb = ln_b + ((size_t)v * NL_ + layer) * H_ + ch2 * 64;

            // per-row partials over this warp's 64 cols: E-sum and E-sumsq
            float sA = 0.0f, sB = 0.0f, qA = 0.0f, qB = 0.0f;
#pragma unroll
            for (int nt = 0; nt < 8; nt++) {
                float2 b2 = __ldg((const float2*)(bias + nt * 8 + 2 * tg));
                c[nt][0] += b2.x; c[nt][1] += b2.y;
                c[nt][2] += b2.x; c[nt][3] += b2.y;
                sA += c[nt][0] + c[nt][1];
                sB += c[nt][2] + c[nt][3];
                qA += c[nt][0] * c[nt][0] + c[nt][1] * c[nt][1];
                qB += c[nt][2] * c[nt][2] + c[nt][3] * c[nt][3];
            }
            sA += __shfl_xor_sync(~0u, sA, 1); sA += __shfl_xor_sync(~0u, sA, 2);
            sB += __shfl_xor_sync(~0u, sB, 1); sB += __shfl_xor_sync(~0u, sB, 2);
            qA += __shfl_xor_sync(~0u, qA, 1); qA += __shfl_xor_sync(~0u, qA, 2);
            qB += __shfl_xor_sync(~0u, qB, 1); qB += __shfl_xor_sync(~0u, qB, 2);

            // cross-warp (column-half) combine via scratch aliasing MW region
            float2* red = (float2*)(smc + MW_HI);   // [2 halves][128 rows]
            if (tg == 0) {
                red[ch2 * 128 + r0] = make_float2(sA, qA);
                red[ch2 * 128 + r0 + 8] = make_float2(sB, qB);
            }
            __syncthreads();
            float2 oA = red[(1 - ch2) * 128 + r0];
            float2 oB = red[(1 - ch2) * 128 + r0 + 8];
            float muA = (sA + oA.x) * (1.0f / H_);
            float muB = (sB + oB.x) * (1.0f / H_);
            float vA = (qA + oA.y) * (1.0f / H_) - muA * muA;
            float vB = (qB + oB.y) * (1.0f / H_) - muB * muB;
            float ivA = rsqrtf(vA + 1e-5f);
            float ivB = rsqrtf(vB + 1e-5f);

#pragma unroll
            for (int nt = 0; nt < 8; nt++) {
                float2 g2 = __ldg((const float2*)(gg + nt * 8 + 2 * tg));
                float2 n2 = __ldg((const float2*)(nb + nt * 8 + 2 * tg));
                float y0 = (c[nt][0] - muA) * ivA * g2.x + n2.x;
                float y1 = (c[nt][1] - muA) * ivA * g2.y + n2.y;
                float y2 = (c[nt][2] - muB) * ivB * g2.x + n2.x;
                float y3 = (c[nt][3] - muB) * ivB * g2.y + n2.y;
                y0 = y0 * 0.5f * (1.0f + erff(y0 * 0.70710678118654752f));
                y1 = y1 * 0.5f * (1.0f + erff(y1 * 0.70710678118654752f));
                y2 = y2 * 0.5f * (1.0f + erff(y2 * 0.70710678118654752f));
                y3 = y3 * 0.5f * (1.0f + erff(y3 * 0.70710678118654752f));
                uint32_t hiA, loA, hiB, loB;
                split2(y0, y1, hiA, loA);
                split2(y2, y3, hiB, loB);
                int ntp = ch2 * 8 + nt;
                uint32_t addr = (uint32_t)(ntp >> 2) * WIMG + r0 * GAP
                              + ((ntp & 3) * 4 + tg) * 4;
                *(uint32_t*)(smc + MZ_HI + addr) = hiA;
                *(uint32_t*)(smc + MZ_LO + addr) = loA;
                *(uint32_t*)(smc + MZ_HI + addr + 8 * GAP) = hiB;
                *(uint32_t*)(smc + MZ_LO + addr + 8 * GAP) = loB;
            }
            __syncthreads();   // red reads + Z writes done before next W copy
        } else {
            const float* bias = (layer == 3 ? bq : layer == 4 ? bk : bv)
                              + (size_t)v * H_ + ch2 * 64;
            float* out = (layer == 3 ? qb : layer == 4 ? kb : vb);
            float* ob0 = out + ((size_t)v * BT_ + bt0 + r0) * H_ + ch2 * 64;
            float* ob1 = ob0 + 8 * H_;
#pragma unroll
            for (int nt = 0; nt < 8; nt++) {
                float2 b2 = __ldg((const float2*)(bias + nt * 8 + 2 * tg));
                *(float2*)(ob0 + nt * 8 + 2 * tg) =
                    make_float2(c[nt][0] + b2.x, c[nt][1] + b2.y);
                *(float2*)(ob1 + nt * 8 + 2 * tg) =
                    make_float2(c[nt][2] + b2.x, c[nt][3] + b2.y);
            }
        }
    }
}

// ---------------------------------------------------------------------------
// Kernel 2b: Wo GEMM + fused output head (R11/R13 proven, unchanged)
// ---------------------------------------------------------------------------
#define GB_HI 20480
#define GB_LO 30720
#define G2_SMEM 40960

__global__ __launch_bounds__(256, 2) void wo_head_mma(
    const float* __restrict__ in,
    const float* __restrict__ bo,
    const float* __restrict__ OW, const float* __restrict__ OB,
    float* __restrict__ PRED) {
    char* smc = SM;
    uint32_t sb = smem_u32(smc);
    int tid = threadIdx.x;
    int v = blockIdx.y;
    int bt0 = blockIdx.x * 128;

    const float* bias = bo + (size_t)v * H_;
    const float* inp = in + ((size_t)v * BT_ + bt0) * H_;
    const uint4* wimg = (const uint4*)(g_Wc + (size_t)(6 * V_ + v) * WVBLK);

    int wid = tid >> 5, lane = tid & 31;
    int g = lane >> 2, tg = lane & 3;
    int lr = lane & 7, lsel = (lane >> 3) & 1, khalf = lane >> 4;
    uint32_t aoff = (uint32_t)(wid * 16 + lr + lsel * 8) * GAP + khalf * 16;

    float c[16][4];
#pragma unroll
    for (int nt = 0; nt < 16; nt++)
#pragma unroll
        for (int e = 0; e < 4; e++) c[nt][e] = 0.0f;

    for (int ch = 0; ch < 4; ch++) {
#pragma unroll
        for (int t = 0; t < 4; t++) {
            int idx = tid + t * 256;
            int r = idx >> 3, c4 = idx & 7;
            float4 a = *(const float4*)(inp + (size_t)r * H_ + ch * 32 + c4 * 4);
            uint32_t h0, l0, h1, l1;
            split2(a.x, a.y, h0, l0);
            split2(a.z, a.w, h1, l1);
            *(uint2*)(smc + r * GAP + c4 * 8) = make_uint2(h0, h1);
            *(uint2*)(smc + 10240 + r * GAP + c4 * 8) = make_uint2(l0, l1);
        }
        {
            const uint4* src = wimg + ch * 1280;
            uint4* dst = (uint4*)(smc + GB_HI);
            for (int i = tid; i < 1280; i += 256) dst[i] = src[i];
        }
        __syncthreads();

#pragma unroll
        for (int sub = 0; sub < 2; sub++) {
            uint32_t ah[4], al[4];
            ldsm4(ah[0], ah[1], ah[2], ah[3], sb + aoff + sub * 32);
            ldsm4(al[0], al[1], al[2], al[3], sb + 10240 + aoff + sub * 32);
#pragma unroll
            for (int bq8 = 0; bq8 < 8; bq8++) {
                uint32_t bo2 = (uint32_t)(bq8 * 16 + lr + khalf * 8) * GAP
                             + lsel * 16 + sub * 32;
                uint32_t bh[4], bl[4];
                ldsm4(bh[0], bh[1], bh[2], bh[3], sb + GB_HI + bo2);
                ldsm4(bl[0], bl[1], bl[2], bl[3], sb + GB_LO + bo2);
                mma16816(c[2 * bq8 + 0], ah, bh[0], bh[1]);
                mma16816(c[2 * bq8 + 1], ah, bh[2], bh[3]);
                mma16816(c[2 * bq8 + 0], ah, bl[0], bl[1]);
                mma16816(c[2 * bq8 + 1], ah, bl[2], bl[3]);
                mma16816(c[2 * bq8 + 0], al, bh[0], bh[1]);
                mma16816(c[2 * bq8 + 1], al, bh[2], bh[3]);
            }
        }
        __syncthreads();
    }

    int r0 = bt0 + wid * 16 + g;
    const float* ow = OW + (size_t)v * H_;
    float s0 = 0.0f, s1 = 0.0f;
#pragma unroll
    for (int nt = 0; nt < 16; nt++) {
        float2 b2 = __ldg((const float2*)(bias + nt * 8 + 2 * tg));
        float2 w2 = __ldg((const float2*)(ow + nt * 8 + 2 * tg));
        s0 += (c[nt][0] + b2.x) * w2.x + (c[nt][1] + b2.y) * w2.y;
        s1 += (c[nt][2] + b2.x) * w2.x + (c[nt][3] + b2.y) * w2.y;
    }
    s0 += __shfl_xor_sync(~0u, s0, 1); s0 += __shfl_xor_sync(~0u, s0, 2);
    s1 += __shfl_xor_sync(~0u, s1, 1); s1 += __shfl_xor_sync(~0u, s1, 2);
    if (tg == 0) {
        float obv = OB[v];
        PRED[(size_t)r0 * V_ + v] = s0 + obv;
        PRED[(size_t)(r0 + 8) * V_ + v] = s1 + obv;
    }
}

// ---------------------------------------------------------------------------
// Kernel 3: tensor-core attention, online softmax (R11 proven, unchanged)
// ---------------------------------------------------------------------------
#define AKHI 0
#define AKLO 24576
#define AVHI 49152
#define AVLO 66048
#define ATT_SMEM 82944
#define KHEAD 12288
#define VHEAD 8448

__global__ __launch_bounds__(256, 2) void attn_mma(
        const float* __restrict__ qg,
        const float* __restrict__ kg,
        const float* __restrict__ vg,
        float* __restrict__ og) {
    char* smc = SM;
    uint32_t sb = smem_u32(smc);
    int id = blockIdx.x;
    int hp = id & 3;
    int vv = (id >> 2) & 63;
    int b  = id >> 8;
    int tid = threadIdx.x;

    size_t vbase = ((size_t)vv * BT_ + b * S_) * H_;

    for (int i = tid; i < 8192; i += 256) {
        int col = i & 31;
        int key = i >> 5;
        int hh = col >> 4, d = col & 15;
        size_t gidx = vbase + (size_t)key * H_ + hp * 32 + col;
        float kv = kg[gidx];
        __nv_bfloat16 kh = __float2bfloat16(kv);
        __nv_bfloat16 kl = __float2bfloat16(kv - __bfloat162float(kh));
        *(__nv_bfloat16*)(smc + AKHI + hh * KHEAD + key * 48 + d * 2) = kh;
        *(__nv_bfloat16*)(smc + AKLO + hh * KHEAD + key * 48 + d * 2) = kl;
        float vvv = vg[gidx];
        __nv_bfloat16 vh = __float2bfloat16(vvv);
        __nv_bfloat16 vl = __float2bfloat16(vvv - __bfloat162float(vh));
        *(__nv_bfloat16*)(smc + AVHI + hh * VHEAD + d * 528 + key * 2) = vh;
        *(__nv_bfloat16*)(smc + AVLO + hh * VHEAD + d * 528 + key * 2) = vl;
    }
    __syncthreads();

    int wid = tid >> 5, lane = tid & 31;
    int hh = wid >> 2, wq = wid & 3;
    int g = lane >> 2, tg = lane & 3;
    int lr = lane & 7, lsel = (lane >> 3) & 1, khalf = lane >> 4;

    const float* qbase = qg + vbase + hp * 32 + hh * 16;
    float* obase = og + vbase + hp * 32 + hh * 16;

    uint32_t kbh = sb + AKHI + hh * KHEAD;
    uint32_t kbl = sb + AKLO + hh * KHEAD;
    uint32_t vbh = sb + AVHI + hh * VHEAD;
    uint32_t vbl = sb + AVLO + hh * VHEAD;
    uint32_t krow = (uint32_t)(lr + khalf * 8) * 48 + lsel * 16;
    uint32_t vrow = (uint32_t)(lr + khalf * 8) * 528 + lsel * 16;

    for (int s = 0; s < 4; s++) {
        int q0 = wq * 64 + s * 16;

        uint32_t ah[4], al[4];
        {
            float2 f0 = *(const float2*)(qbase + (size_t)(q0 + g) * H_ + 2 * tg);
            float2 f1 = *(const float2*)(qbase + (size_t)(q0 + g + 8) * H_ + 2 * tg);
            float2 f2 = *(const float2*)(qbase + (size_t)(q0 + g) * H_ + 8 + 2 * tg);
            float2 f3 = *(const float2*)(qbase + (size_t)(q0 + g + 8) * H_ + 8 + 2 * tg);
            split2(f0.x, f0.y, ah[0], al[0]);
            split2(f1.x, f1.y, ah[1], al[1]);
            split2(f2.x, f2.y, ah[2], al[2]);
            split2(f3.x, f3.y, ah[3], al[3]);
        }

        float o[8];
#pragma unroll
        for (int e = 0; e < 8; e++) o[e] = 0.0f;
        float mA = -1e30f, mB = -1e30f, sA = 0.0f, sB = 0.0f;

        for (int kc = 0; kc < 4; kc++) {
            float cc[4][8];
#pragma unroll
            for (int kt = 0; kt < 4; kt++)
#pragma unroll
                for (int e = 0; e < 8; e++) cc[kt][e] = 0.0f;

#pragma unroll
            for (int kt = 0; kt < 4; kt++) {
                int kta = kc * 4 + kt;
                uint32_t bh[4], bl[4];
                ldsm4(bh[0], bh[1], bh[2], bh[3], kbh + kta * 768 + krow);
                ldsm4(bl[0], bl[1], bl[2], bl[3], kbl + kta * 768 + krow);
                mma16816(cc[kt], ah, bh[0], bh[1]);
                mma16816(cc[kt] + 4, ah, bh[2], bh[3]);
                mma16816(cc[kt], ah, bl[0], bl[1]);
                mma16816(cc[kt] + 4, ah, bl[2], bl[3]);
                mma16816(cc[kt], al, bh[0], bh[1]);
                mma16816(cc[kt] + 4, al, bh[2], bh[3]);
            }

            float cmA = -1e30f, cmB = -1e30f;
#pragma unroll
            for (int kt = 0; kt < 4; kt++)
#pragma unroll
                for (int t = 0; t < 2; t++) {
                    cmA = fmaxf(cmA, fmaxf(cc[kt][t * 4 + 0], cc[kt][t * 4 + 1]));
                    cmB = fmaxf(cmB, fmaxf(cc[kt][t * 4 + 2], cc[kt][t * 4 + 3]));
                }
            cmA = fmaxf(cmA, __shfl_xor_sync(~0u, cmA, 1));
            cmA = fmaxf(cmA, __shfl_xor_sync(~0u, cmA, 2));
            cmB = fmaxf(cmB, __shfl_xor_sync(~0u, cmB, 1));
            cmB = fmaxf(cmB, __shfl_xor_sync(~0u, cmB, 2));
            cmA *= 0.25f; cmB *= 0.25f;
            float mnA = fmaxf(mA, cmA), mnB = fmaxf(mB, cmB);
            float fA = __expf(mA - mnA), fB = __expf(mB - mnB);
            mA = mnA; mB = mnB;
            sA *= fA; sB *= fB;
#pragma unroll
            for (int t = 0; t < 2; t++) {
                o[t * 4 + 0] *= fA; o[t * 4 + 1] *= fA;
                o[t * 4 + 2] *= fB; o[t * 4 + 3] *= fB;
            }

#pragma unroll
            for (int kt = 0; kt < 4; kt++) {
                int kta = kc * 4 + kt;
                float p[8];
#pragma unroll
                for (int t = 0; t < 2; t++) {
                    p[t * 4 + 0] = __expf(cc[kt][t * 4 + 0] * 0.25f - mA);
                    p[t * 4 + 1] = __expf(cc[kt][t * 4 + 1] * 0.25f - mA);
                    p[t * 4 + 2] = __expf(cc[kt][t * 4 + 2] * 0.25f - mB);
                    p[t * 4 + 3] = __expf(cc[kt][t * 4 + 3] * 0.25f - mB);
                    sA += p[t * 4 + 0] + p[t * 4 + 1];
                    sB += p[t * 4 + 2] + p[t * 4 + 3];
                }
                uint32_t ph[4], pl[4];
                split2(p[0], p[1], ph[0], pl[0]);
                split2(p[2], p[3], ph[1], pl[1]);
                split2(p[4], p[5], ph[2], pl[2]);
                split2(p[6], p[7], ph[3], pl[3]);
                uint32_t vh[4], vl[4];
                ldsm4(vh[0], vh[1], vh[2], vh[3], vbh + vrow + kta * 32);
                ldsm4(vl[0], vl[1], vl[2], vl[3], vbl + vrow + kta * 32);
                mma16816(o, ph, vh[0], vh[1]);
                mma16816(o + 4, ph, vh[2], vh[3]);
                mma16816(o, ph, vl[0], vl[1]);
                mma16816(o + 4, ph, vl[2], vl[3]);
                mma16816(o, pl, vh[0], vh[1]);
                mma16816(o + 4, pl, vh[2], vh[3]);
            }
        }

        sA += __shfl_xor_sync(~0u, sA, 1);
        sA += __shfl_xor_sync(~0u, sA, 2);
        sB += __shfl_xor_sync(~0u, sB, 1);
        sB += __shfl_xor_sync(~0u, sB, 2);
        float invA = 1.0f / sA, invB = 1.0f / sB;

        *(float2*)(obase + (size_t)(q0 + g) * H_ + 2 * tg) =
            make_float2(o[0] * invA, o[1] * invA);
        *(float2*)(obase + (size_t)(q0 + g + 8) * H_ + 2 * tg) =
            make_float2(o[2] * invB, o[3] * invB);
        *(float2*)(obase + (size_t)(q0 + g) * H_ + 8 + 2 * tg) =
            make_float2(o[4] * invA, o[5] * invA);
        *(float2*)(obase + (size_t)(q0 + g + 8) * H_ + 8 + 2 * tg) =
            make_float2(o[6] * invB, o[7] * invB);
    }
}

// ---------------------------------------------------------------------------
// Launch
// ---------------------------------------------------------------------------
extern "C" void kernel_launch(void* const* d_in, const int* in_sizes, int n_in,
                              void* d_out, int out_size) {
    const float* x       = (const float*)d_in[0];
    const float* adj_l   = (const float*)d_in[1];
    const float* var_emb = (const float*)d_in[2];
    const float* temp_emb= (const float*)d_in[3];
    const float* mech_W  = (const float*)d_in[4];
    const float* mech_b  = (const float*)d_in[5];
    const float* ln_g    = (const float*)d_in[6];
    const float* ln_b    = (const float*)d_in[7];
    const float* Wq      = (const float*)d_in[8];
    const float* Wk      = (const float*)d_in[9];
    const float* Wv      = (const float*)d_in[10];
    const float* Wo      = (const float*)d_in[11];
    const float* bq      = (const float*)d_in[12];
    const float* bk      = (const float*)d_in[13];
    const float* bv      = (const float*)d_in[14];
    const float* bo      = (const float*)d_in[15];
    const float* out_W   = (const float*)d_in[16];
    const float* out_b   = (const float*)d_in[17];
    float* pred = (float*)d_out;

    float *zA, *qb, *kb, *vb, *ob;
    cudaGetSymbolAddress((void**)&zA, g_zA);
    cudaGetSymbolAddress((void**)&qb, g_qb);
    cudaGetSymbolAddress((void**)&kb, g_kb);
    cudaGetSymbolAddress((void**)&vb, g_vb);
    cudaGetSymbolAddress((void**)&ob, g_ob);

    cudaFuncSetAttribute((const void*)mega_mma,
                         cudaFuncAttributeMaxDynamicSharedMemorySize, MEGA_SMEM);
    cudaFuncSetAttribute((const void*)wo_head_mma,
                         cudaFuncAttributeMaxDynamicSharedMemorySize, G2_SMEM);
    cudaFuncSetAttribute((const void*)prep_w_kernel,
                         cudaFuncAttributeMaxDynamicSharedMemorySize, PREP_SMEM);
    cudaFuncSetAttribute((const void*)causal_kernel,
                         cudaFuncAttributeMaxDynamicSharedMemorySize, CAU_SMEM);
    cudaFuncSetAttribute((const void*)attn_mma,
                         cudaFuncAttributeMaxDynamicSharedMemorySize, ATT_SMEM);

    // 0. sigmoid + weight split
    sigmoid_kernel<<<(V_ * V_ * LP1_ + 255) / 256, 256>>>(adj_l);
    prep_w_kernel<<<7 * V_, 256, PREP_SMEM>>>(mech_W, Wq, Wk, Wv, Wo);

    // 1. causal input -> zA  ([v][bt][h])
    causal_kernel<<<BT_, 256, CAU_SMEM>>>(x, var_emb, temp_emb, zA);

    // 2. MEGA: mech0..2 + Q/K/V, activations resident in smem (512 threads)
    dim3 mgrid(BT_ / 128, V_);
    mega_mma<<<mgrid, 512, MEGA_SMEM>>>(zA, mech_b, ln_g, ln_b,
                                        bq, bk, bv, qb, kb, vb);

    // 3. tensor-core attention -> ob
    attn_mma<<<B_ * V_ * NH_ / 2, 256, ATT_SMEM>>>(qb, kb, vb, ob);

    // 4. Wo + fused output head -> pred
    wo_head_mma<<<mgrid, 256, G2_SMEM>>>(ob, bo, out_W, out_b, pred);
}

// round 15
// speedup vs baseline: 2.4759x; 1.0202x over previous
#include <cuda_runtime.h>
#include <cuda_bf16.h>
#include <math.h>
#include <stdint.h>

// Problem constants
#define B_  4
#define S_  256
#define V_  64
#define H_  128
#define NH_ 8
#define DH_ 16
#define LP1_ 11
#define NL_ 3
#define BT_ (B_ * S_)          // 1024
#define ZSZ (BT_ * V_ * H_)

// Scratch (device globals)
__device__ float g_adj[V_ * V_ * LP1_];
__device__ float g_zA[ZSZ];
__device__ float g_qb[ZSZ];
__device__ float g_kb[ZSZ];
__device__ float g_vb[ZSZ];
__device__ float g_ob[ZSZ];
// Pre-split weights: [pass 0..6][v][chunk 0..3][hi|lo] 10240-byte smem images
#define WIMG   10240
#define WVBLK  (4 * 2 * WIMG)    // 81920 bytes per (pass,v)
__device__ __align__(128) char g_Wc[7 * V_ * WVBLK];

extern __shared__ char SM[];

// ---------------------------------------------------------------------------
// mma.sync / ldmatrix helpers (validated R9-R14)
// ---------------------------------------------------------------------------
__device__ __forceinline__ uint32_t smem_u32(const void* p) {
    uint32_t a;
    asm("{ .reg .u64 t; cvta.to.shared.u64 t, %1; cvt.u32.u64 %0, t; }"
        : "=r"(a) : "l"(p));
    return a;
}
__device__ __forceinline__ void ldsm4(uint32_t& r0, uint32_t& r1,
                                      uint32_t& r2, uint32_t& r3, uint32_t addr) {
    asm volatile("ldmatrix.sync.aligned.m8n8.x4.shared.b16 {%0,%1,%2,%3}, [%4];"
                 : "=r"(r0), "=r"(r1), "=r"(r2), "=r"(r3) : "r"(addr));
}
__device__ __forceinline__ void mma16816(float* c, const uint32_t a[4],
                                         uint32_t b0, uint32_t b1) {
    asm volatile(
        "mma.sync.aligned.m16n8k16.row.col.f32.bf16.bf16.f32 "
        "{%0,%1,%2,%3}, {%4,%5,%6,%7}, {%8,%9}, {%0,%1,%2,%3};"
        : "+f"(c[0]), "+f"(c[1]), "+f"(c[2]), "+f"(c[3])
        : "r"(a[0]), "r"(a[1]), "r"(a[2]), "r"(a[3]), "r"(b0), "r"(b1));
}
__device__ __forceinline__ void split2(float x, float y,
                                       uint32_t& hi, uint32_t& lo) {
    __nv_bfloat162 h = __floats2bfloat162_rn(x, y);
    float rx = x - __bfloat162float(h.x);
    float ry = y - __bfloat162float(h.y);
    __nv_bfloat162 l = __floats2bfloat162_rn(rx, ry);
    hi = *(uint32_t*)&h;
    lo = *(uint32_t*)&l;
}

// ---------------------------------------------------------------------------
// Kernel 0: adj = sigmoid(adjacency_logits)
// ---------------------------------------------------------------------------
__global__ void sigmoid_kernel(const float* __restrict__ logits) {
    int i = blockIdx.x * 256 + threadIdx.x;
    if (i < V_ * V_ * LP1_) g_adj[i] = 1.0f / (1.0f + __expf(-logits[i]));
}

// ---------------------------------------------------------------------------
// Kernel P: split weights into per-chunk bf16 hi/lo smem images.
// ---------------------------------------------------------------------------
#define PREP_SMEM (128 * 132 * 4)
__global__ void prep_w_kernel(const float* __restrict__ mech_W,
                              const float* __restrict__ Wq,
                              const float* __restrict__ Wk,
                              const float* __restrict__ Wv,
                              const float* __restrict__ Wo) {
    float* Wt = (float*)SM;
    int pv = blockIdx.x;
    int pass = pv >> 6, v = pv & 63;
    const float* src;
    if (pass < 3)       src = mech_W + ((size_t)v * NL_ + pass) * H_ * H_;
    else if (pass == 3) src = Wq + (size_t)v * H_ * H_;
    else if (pass == 4) src = Wk + (size_t)v * H_ * H_;
    else if (pass == 5) src = Wv + (size_t)v * H_ * H_;
    else                src = Wo + (size_t)v * H_ * H_;

    int tid = threadIdx.x;
    for (int i = tid; i < 128 * 32; i += 256) {
        int r = i >> 5, c4 = i & 31;
        float4 a = *(const float4*)(src + (size_t)r * H_ + c4 * 4);
        *(float4*)(Wt + r * 132 + c4 * 4) = a;
    }
    __syncthreads();

    char* img = g_Wc + (size_t)pv * WVBLK;
    for (int task = tid; task < 4 * 128 * 16; task += 256) {
        int ch = task >> 11;
        int rem = task & 2047;
        int n = rem >> 4, kk2 = rem & 15;
        int k = ch * 32 + kk2 * 2;
        float w0 = Wt[k * 132 + n];
        float w1 = Wt[(k + 1) * 132 + n];
        uint32_t hi, lo;
        split2(w0, w1, hi, lo);
        *(uint32_t*)(img + (ch * 2 + 0) * WIMG + n * 80 + kk2 * 4) = hi;
        *(uint32_t*)(img + (ch * 2 + 1) * WIMG + n * 80 + kk2 * 4) = lo;
    }
}

// ---------------------------------------------------------------------------
// Kernel 1: causal input (R6 proven)
// ---------------------------------------------------------------------------
#define CAU_XW   0
#define CAU_ASM  (CAU_XW + LP1_ * 64)
#define CAU_BL   (CAU_ASM + 64 * 65)
#define CAU_VE   (CAU_BL + 64 * 12)
#define CAU_TE   (CAU_VE + 64 * 128)
#define CAU_SMEM ((CAU_TE + LP1_ * 128) * 4)

__global__ void causal_kernel(const float* __restrict__ x,
                              const float* __restrict__ var_emb,
                              const float* __restrict__ temp_emb,
                              float* __restrict__ zout) {
    float* cs = (float*)SM;
    float* xw  = cs + CAU_XW;
    float* Asm = cs + CAU_ASM;
    float* Bl  = cs + CAU_BL;
    float* ve  = cs + CAU_VE;
    float* te  = cs + CAU_TE;

    int bt = blockIdx.x;
    int b = bt / S_;
    int t = bt % S_;
    int tid = threadIdx.x;

    for (int e = tid; e < LP1_ * 64; e += 256) {
        int l = e >> 6, s2 = e & 63;
        int tt = t - l;
        xw[l * 64 + s2] = (tt >= 0) ? x[(b * S_ + tt) * V_ + s2] : 0.0f;
    }
    for (int e = tid; e < 64 * 128 / 4; e += 256)
        ((float4*)ve)[e] = ((const float4*)var_emb)[e];
    for (int e = tid; e < LP1_ * 128 / 4; e += 256)
        ((float4*)te)[e] = ((const float4*)temp_emb)[e];
    __syncthreads();

    for (int e = tid; e < 64 * 64; e += 256) {
        int i = e >> 6, s2 = e & 63;
        const float* ap = g_adj + (s2 * V_ + i) * LP1_;
        float acc = 0.0f;
#pragma unroll
        for (int l = 0; l < LP1_; l++) acc += xw[l * 64 + s2] * ap[l];
        Asm[i * 65 + s2] = acc;
    }
    for (int e = tid; e < 64 * LP1_; e += 256) {
        int i = e / LP1_, l = e % LP1_;
        float acc = 0.0f;
        for (int s2 = 0; s2 < 64; s2++)
            acc += xw[l * 64 + s2] * g_adj[(s2 * V_ + i) * LP1_ + l];
        Bl[i * 12 + l] = acc;
    }
    __syncthreads();

    int i = tid >> 2, q = tid & 3;
    float4 acc[8];
#pragma unroll
    for (int j = 0; j < 8; j++) acc[j] = make_float4(0.f, 0.f, 0.f, 0.f);

    for (int s2 = 0; s2 < 64; s2++) {
        float a = Asm[i * 65 + s2];
        const float* vr = ve + s2 * 128 + q * 4;
#pragma unroll
        for (int j = 0; j < 8; j++) {
            float4 vv = *(const float4*)(vr + j * 16);
            acc[j].x += a * vv.x; acc[j].y += a * vv.y;
            acc[j].z += a * vv.z; acc[j].w += a * vv.w;
        }
    }
#pragma unroll
    for (int l = 0; l < LP1_; l++) {
        float bl = Bl[i * 12 + l];
        const float* tr = te + l * 128 + q * 4;
#pragma unroll
        for (int j = 0; j < 8; j++) {
            float4 vv = *(const float4*)(tr + j * 16);
            acc[j].x += bl * vv.x; acc[j].y += bl * vv.y;
            acc[j].z += bl * vv.z; acc[j].w += bl * vv.w;
        }
    }
    float* zr = zout + ((size_t)i * BT_ + bt) * H_ + q * 4;
#pragma unroll
    for (int j = 0; j < 8; j++) *(float4*)(zr + j * 16) = acc[j];
}

// ---------------------------------------------------------------------------
// Kernel 2: MEGA mma v3 — 512 threads, W chunk register-prefetch.
// Per chunk: [store prefetched W regs] barrier [prefetch next W | mma] barrier.
// LDG latency overlaps the mma phase instead of serializing before it.
// smem: Z 81920 + W 20480 = 102400.
// ---------------------------------------------------------------------------
#define GAP 80
#define MZ_HI 0
#define MZ_LO 40960
#define MW_HI 81920
#define MW_LO 92160
#define MEGA_SMEM 102400

__global__ __launch_bounds__(512, 2) void mega_mma(
    const float* __restrict__ zin,
    const float* __restrict__ mech_b,
    const float* __restrict__ ln_g, const float* __restrict__ ln_b,
    const float* __restrict__ bq, const float* __restrict__ bk,
    const float* __restrict__ bv,
    float* __restrict__ qb, float* __restrict__ kb, float* __restrict__ vb) {
    char* smc = SM;
    uint32_t sb = smem_u32(smc);
    int tid = threadIdx.x;
    int v = blockIdx.y;
    int bt0 = blockIdx.x * 128;

    int wid = tid >> 5, lane = tid & 31;
    int ch2 = wid >> 3;       // column half
    int rg  = wid & 7;        // row group
    int g = lane >> 2, tg = lane & 3;
    int lr = lane & 7, lsel = (lane >> 3) & 1, khalf = lane >> 4;
    uint32_t aoff = (uint32_t)(rg * 16 + lr + lsel * 8) * GAP + khalf * 16;
    int r0 = rg * 16 + g;

    // W prefetch: 1280 uint4 per chunk image / 512 threads -> 3 regs (2.5 avg)
    // thread covers indices tid, tid+512, tid+1024 (last only if tid < 256)
    const uint4* wimg0 = (const uint4*)(g_Wc + (size_t)(0 * V_ + v) * WVBLK);
    uint4 wpre[3];

    // --- initial staging: zA (fp32) -> bf16 hi/lo chunk images ---
    const float* inp = zin + ((size_t)v * BT_ + bt0) * H_;
#pragma unroll
    for (int t = 0; t < 8; t++) {
        int idx = tid + t * 512;
        int r = idx >> 5, c4 = idx & 31;
        float4 a = *(const float4*)(inp + (size_t)r * H_ + c4 * 4);
        uint32_t h0, l0, h1, l1;
        split2(a.x, a.y, h0, l0);
        split2(a.z, a.w, h1, l1);
        uint32_t off = (uint32_t)(c4 >> 3) * WIMG + r * GAP + (c4 & 7) * 8;
        *(uint2*)(smc + MZ_HI + off) = make_uint2(h0, h1);
        *(uint2*)(smc + MZ_LO + off) = make_uint2(l0, l1);
    }
    // prefetch layer 0 chunk 0 while staging finishes
    wpre[0] = wimg0[tid];
    wpre[1] = wimg0[tid + 512];
    if (tid < 256) wpre[2] = wimg0[tid + 1024];
    __syncthreads();

    for (int layer = 0; layer < 6; layer++) {
        float c[8][4];
#pragma unroll
        for (int nt = 0; nt < 8; nt++)
#pragma unroll
            for (int e = 0; e < 4; e++) c[nt][e] = 0.0f;

        for (int ch = 0; ch < 4; ch++) {
            // store prefetched W regs
            uint4* dst = (uint4*)(smc + MW_HI);
            dst[tid] = wpre[0];
            dst[tid + 512] = wpre[1];
            if (tid < 256) dst[tid + 1024] = wpre[2];
            __syncthreads();

            // issue prefetch for next chunk (or next layer's chunk 0)
            {
                const uint4* nsrc;
                if (ch < 3) {
                    nsrc = (const uint4*)(g_Wc + (size_t)(layer * V_ + v) * WVBLK)
                         + (ch + 1) * 1280;
                } else if (layer < 5) {
                    nsrc = (const uint4*)(g_Wc + (size_t)((layer + 1) * V_ + v) * WVBLK);
                } else {
                    nsrc = nullptr;
                }
                if (nsrc) {
                    wpre[0] = nsrc[tid];
                    wpre[1] = nsrc[tid + 512];
                    if (tid < 256) wpre[2] = nsrc[tid + 1024];
                }
            }

            uint32_t azh = sb + MZ_HI + ch * WIMG;
            uint32_t azl = sb + MZ_LO + ch * WIMG;
#pragma unroll
            for (int sub = 0; sub < 2; sub++) {
                uint32_t ah[4], al[4];
                ldsm4(ah[0], ah[1], ah[2], ah[3], azh + aoff + sub * 32);
                ldsm4(al[0], al[1], al[2], al[3], azl + aoff + sub * 32);
#pragma unroll
                for (int bq8 = 0; bq8 < 4; bq8++) {
                    uint32_t bo = (uint32_t)(ch2 * 64 + bq8 * 16 + lr + khalf * 8) * GAP
                                + lsel * 16 + sub * 32;
                    uint32_t bh[4], bl[4];
                    ldsm4(bh[0], bh[1], bh[2], bh[3], sb + MW_HI + bo);
                    ldsm4(bl[0], bl[1], bl[2], bl[3], sb + MW_LO + bo);
                    mma16816(c[2 * bq8 + 0], ah, bh[0], bh[1]);
                    mma16816(c[2 * bq8 + 1], ah, bh[2], bh[3]);
                    mma16816(c[2 * bq8 + 0], ah, bl[0], bl[1]);
                    mma16816(c[2 * bq8 + 1], ah, bl[2], bl[3]);
                    mma16816(c[2 * bq8 + 0], al, bh[0], bh[1]);
                    mma16816(c[2 * bq8 + 1], al, bh[2], bh[3]);
                }
            }
            __syncthreads();   // W smem reads done before next store / red alias
        }

        if (layer < 3) {
            const float* bias = mech_b + ((size_t)v * NL_ + layer) * H_ + ch2 * 64;
            const float* gg = ln_g + ((size_t)v * NL_ + layer) * H_ + ch2 * 64;
            const float* nb = ln_b + ((size_t)v * NL_ + layer) * H_ + ch2 * 64;

            float sA = 0.0f, sB = 0.0f, qA = 0.0f, qB = 0.0f;
#pragma unroll
            for (int nt = 0; nt < 8; nt++) {
                float2 b2 = __ldg((const float2*)(bias + nt * 8 + 2 * tg));
                c[nt][0] += b2.x; c[nt][1] += b2.y;
                c[nt][2] += b2.x; c[nt][3] += b2.y;
                sA += c[nt][0] + c[nt][1];
                sB += c[nt][2] + c[nt][3];
                qA += c[nt][0] * c[nt][0] + c[nt][1] * c[nt][1];
                qB += c[nt][2] * c[nt][2] + c[nt][3] * c[nt][3];
            }
            sA += __shfl_xor_sync(~0u, sA, 1); sA += __shfl_xor_sync(~0u, sA, 2);
            sB += __shfl_xor_sync(~0u, sB, 1); sB += __shfl_xor_sync(~0u, sB, 2);
            qA += __shfl_xor_sync(~0u, qA, 1); qA += __shfl_xor_sync(~0u, qA, 2);
            qB += __shfl_xor_sync(~0u, qB, 1); qB += __shfl_xor_sync(~0u, qB, 2);

            // cross-warp combine via scratch in the W region (post-barrier safe)
            float2* red = (float2*)(smc + MW_HI);
            if (tg == 0) {
                red[ch2 * 128 + r0] = make_float2(sA, qA);
                red[ch2 * 128 + r0 + 8] = make_float2(sB, qB);
            }
            __syncthreads();
            float2 oA = red[(1 - ch2) * 128 + r0];
            float2 oB = red[(1 - ch2) * 128 + r0 + 8];
            float muA = (sA + oA.x) * (1.0f / H_);
            float muB = (sB + oB.x) * (1.0f / H_);
            float vA = (qA + oA.y) * (1.0f / H_) - muA * muA;
            float vB = (qB + oB.y) * (1.0f / H_) - muB * muB;
            float ivA = rsqrtf(vA + 1e-5f);
            float ivB = rsqrtf(vB + 1e-5f);

#pragma unroll
            for (int nt = 0; nt < 8; nt++) {
                float2 g2 = __ldg((const float2*)(gg + nt * 8 + 2 * tg));
                float2 n2 = __ldg((const float2*)(nb + nt * 8 + 2 * tg));
                float y0 = (c[nt][0] - muA) * ivA * g2.x + n2.x;
                float y1 = (c[nt][1] - muA) * ivA * g2.y + n2.y;
                float y2 = (c[nt][2] - muB) * ivB * g2.x + n2.x;
                float y3 = (c[nt][3] - muB) * ivB * g2.y + n2.y;
                y0 = y0 * 0.5f * (1.0f + erff(y0 * 0.70710678118654752f));
                y1 = y1 * 0.5f * (1.0f + erff(y1 * 0.70710678118654752f));
                y2 = y2 * 0.5f * (1.0f + erff(y2 * 0.70710678118654752f));
                y3 = y3 * 0.5f * (1.0f + erff(y3 * 0.70710678118654752f));
                uint32_t hiA, loA, hiB, loB;
                split2(y0, y1, hiA, loA);
                split2(y2, y3, hiB, loB);
                int ntp = ch2 * 8 + nt;
                uint32_t addr = (uint32_t)(ntp >> 2) * WIMG + r0 * GAP
                              + ((ntp & 3) * 4 + tg) * 4;
                *(uint32_t*)(smc + MZ_HI + addr) = hiA;
                *(uint32_t*)(smc + MZ_LO + addr) = loA;
                *(uint32_t*)(smc + MZ_HI + addr + 8 * GAP) = hiB;
                *(uint32_t*)(smc + MZ_LO + addr + 8 * GAP) = loB;
            }
            __syncthreads();   // red reads + Z writes done before next W store
        } else {
            const float* bias = (layer == 3 ? bq : layer == 4 ? bk : bv)
                              + (size_t)v * H_ + ch2 * 64;
            float* out = (layer == 3 ? qb : layer == 4 ? kb : vb);
            float* ob0 = out + ((size_t)v * BT_ + bt0 + r0) * H_ + ch2 * 64;
            float* ob1 = ob0 + 8 * H_;
#pragma unroll
            for (int nt = 0; nt < 8; nt++) {
                float2 b2 = __ldg((const float2*)(bias + nt * 8 + 2 * tg));
                *(float2*)(ob0 + nt * 8 + 2 * tg) =
                    make_float2(c[nt][0] + b2.x, c[nt][1] + b2.y);
                *(float2*)(ob1 + nt * 8 + 2 * tg) =
                    make_float2(c[nt][2] + b2.x, c[nt][3] + b2.y);
            }
        }
    }
}

// ---------------------------------------------------------------------------
// Kernel 2b: Wo GEMM + fused output head (R11/R13 proven, unchanged)
// ---------------------------------------------------------------------------
#define GB_HI 20480
#define GB_LO 30720
#define G2_SMEM 40960

__global__ __launch_bounds__(256, 2) void wo_head_mma(
    const float* __restrict__ in,
    const float* __restrict__ bo,
    const float* __restrict__ OW, const float* __restrict__ OB,
    float* __restrict__ PRED) {
    char* smc = SM;
    uint32_t sb = smem_u32(smc);
    int tid = threadIdx.x;
    int v = blockIdx.y;
    int bt0 = blockIdx.x * 128;

    const float* bias = bo + (size_t)v * H_;
    const float* inp = in + ((size_t)v * BT_ + bt0) * H_;
    const uint4* wimg = (const uint4*)(g_Wc + (size_t)(6 * V_ + v) * WVBLK);

    int wid = tid >> 5, lane = tid & 31;
    int g = lane >> 2, tg = lane & 3;
    int lr = lane & 7, lsel = (lane >> 3) & 1, khalf = lane >> 4;
    uint32_t aoff = (uint32_t)(wid * 16 + lr + lsel * 8) * GAP + khalf * 16;

    float c[16][4];
#pragma unroll
    for (int nt = 0; nt < 16; nt++)
#pragma unroll
        for (int e = 0; e < 4; e++) c[nt][e] = 0.0f;

    for (int ch = 0; ch < 4; ch++) {
#pragma unroll
        for (int t = 0; t < 4; t++) {
            int idx = tid + t * 256;
            int r = idx >> 3, c4 = idx & 7;
            float4 a = *(const float4*)(inp + (size_t)r * H_ + ch * 32 + c4 * 4);
            uint32_t h0, l0, h1, l1;
            split2(a.x, a.y, h0, l0);
            split2(a.z, a.w, h1, l1);
            *(uint2*)(smc + r * GAP + c4 * 8) = make_uint2(h0, h1);
            *(uint2*)(smc + 10240 + r * GAP + c4 * 8) = make_uint2(l0, l1);
        }
        {
            const uint4* src = wimg + ch * 1280;
            uint4* dst = (uint4*)(smc + GB_HI);
            for (int i = tid; i < 1280; i += 256) dst[i] = src[i];
        }
        __syncthreads();

#pragma unroll
        for (int sub = 0; sub < 2; sub++) {
            uint32_t ah[4], al[4];
            ldsm4(ah[0], ah[1], ah[2], ah[3], sb + aoff + sub * 32);
            ldsm4(al[0], al[1], al[2], al[3], sb + 10240 + aoff + sub * 32);
#pragma unroll
            for (int bq8 = 0; bq8 < 8; bq8++) {
                uint32_t bo2 = (uint32_t)(bq8 * 16 + lr + khalf * 8) * GAP
                             + lsel * 16 + sub * 32;
                uint32_t bh[4], bl[4];
                ldsm4(bh[0], bh[1], bh[2], bh[3], sb + GB_HI + bo2);
                ldsm4(bl[0], bl[1], bl[2], bl[3], sb + GB_LO + bo2);
                mma16816(c[2 * bq8 + 0], ah, bh[0], bh[1]);
                mma16816(c[2 * bq8 + 1], ah, bh[2], bh[3]);
                mma16816(c[2 * bq8 + 0], ah, bl[0], bl[1]);
                mma16816(c[2 * bq8 + 1], ah, bl[2], bl[3]);
                mma16816(c[2 * bq8 + 0], al, bh[0], bh[1]);
                mma16816(c[2 * bq8 + 1], al, bh[2], bh[3]);
            }
        }
        __syncthreads();
    }

    int r0 = bt0 + wid * 16 + g;
    const float* ow = OW + (size_t)v * H_;
    float s0 = 0.0f, s1 = 0.0f;
#pragma unroll
    for (int nt = 0; nt < 16; nt++) {
        float2 b2 = __ldg((const float2*)(bias + nt * 8 + 2 * tg));
        float2 w2 = __ldg((const float2*)(ow + nt * 8 + 2 * tg));
        s0 += (c[nt][0] + b2.x) * w2.x + (c[nt][1] + b2.y) * w2.y;
        s1 += (c[nt][2] + b2.x) * w2.x + (c[nt][3] + b2.y) * w2.y;
    }
    s0 += __shfl_xor_sync(~0u, s0, 1); s0 += __shfl_xor_sync(~0u, s0, 2);
    s1 += __shfl_xor_sync(~0u, s1, 1); s1 += __shfl_xor_sync(~0u, s1, 2);
    if (tg == 0) {
        float obv = OB[v];
        PRED[(size_t)r0 * V_ + v] = s0 + obv;
        PRED[(size_t)(r0 + 8) * V_ + v] = s1 + obv;
    }
}

// ---------------------------------------------------------------------------
// Kernel 3: tensor-core attention, online softmax + dual P.V accumulators
// (halves the dependent HMMA chain on the O accumulator).
// ---------------------------------------------------------------------------
#define AKHI 0
#define AKLO 24576
#define AVHI 49152
#define AVLO 66048
#define ATT_SMEM 82944
#define KHEAD 12288
#define VHEAD 8448

__global__ __launch_bounds__(256, 2) void attn_mma(
        const float* __restrict__ qg,
        const float* __restrict__ kg,
        const float* __restrict__ vg,
        float* __restrict__ og) {
    char* smc = SM;
    uint32_t sb = smem_u32(smc);
    int id = blockIdx.x;
    int hp = id & 3;
    int vv = (id >> 2) & 63;
    int b  = id >> 8;
    int tid = threadIdx.x;

    size_t vbase = ((size_t)vv * BT_ + b * S_) * H_;

    for (int i = tid; i < 8192; i += 256) {
        int col = i & 31;
        int key = i >> 5;
        int hh = col >> 4, d = col & 15;
        size_t gidx = vbase + (size_t)key * H_ + hp * 32 + col;
        float kv = kg[gidx];
        __nv_bfloat16 kh = __float2bfloat16(kv);
        __nv_bfloat16 kl = __float2bfloat16(kv - __bfloat162float(kh));
        *(__nv_bfloat16*)(smc + AKHI + hh * KHEAD + key * 48 + d * 2) = kh;
        *(__nv_bfloat16*)(smc + AKLO + hh * KHEAD + key * 48 + d * 2) = kl;
        float vvv = vg[gidx];
        __nv_bfloat16 vh = __float2bfloat16(vvv);
        __nv_bfloat16 vl = __float2bfloat16(vvv - __bfloat162float(vh));
        *(__nv_bfloat16*)(smc + AVHI + hh * VHEAD + d * 528 + key * 2) = vh;
        *(__nv_bfloat16*)(smc + AVLO + hh * VHEAD + d * 528 + key * 2) = vl;
    }
    __syncthreads();

    int wid = tid >> 5, lane = tid & 31;
    int hh = wid >> 2, wq = wid & 3;
    int g = lane >> 2, tg = lane & 3;
    int lr = lane & 7, lsel = (lane >> 3) & 1, khalf = lane >> 4;

    const float* qbase = qg + vbase + hp * 32 + hh * 16;
    float* obase = og + vbase + hp * 32 + hh * 16;

    uint32_t kbh = sb + AKHI + hh * KHEAD;
    uint32_t kbl = sb + AKLO + hh * KHEAD;
    uint32_t vbh = sb + AVHI + hh * VHEAD;
    uint32_t vbl = sb + AVLO + hh * VHEAD;
    uint32_t krow = (uint32_t)(lr + khalf * 8) * 48 + lsel * 16;
    uint32_t vrow = (uint32_t)(lr + khalf * 8) * 528 + lsel * 16;

    for (int s = 0; s < 4; s++) {
        int q0 = wq * 64 + s * 16;

        uint32_t ah[4], al[4];
        {
            float2 f0 = *(const float2*)(qbase + (size_t)(q0 + g) * H_ + 2 * tg);
            float2 f1 = *(const float2*)(qbase + (size_t)(q0 + g + 8) * H_ + 2 * tg);
            float2 f2 = *(const float2*)(qbase + (size_t)(q0 + g) * H_ + 8 + 2 * tg);
            float2 f3 = *(const float2*)(qbase + (size_t)(q0 + g + 8) * H_ + 8 + 2 * tg);
            split2(f0.x, f0.y, ah[0], al[0]);
            split2(f1.x, f1.y, ah[1], al[1]);
            split2(f2.x, f2.y, ah[2], al[2]);
            split2(f3.x, f3.y, ah[3], al[3]);
        }

        float o[8], o2[8];
#pragma unroll
        for (int e = 0; e < 8; e++) { o[e] = 0.0f; o2[e] = 0.0f; }
        float mA = -1e30f, mB = -1e30f, sA = 0.0f, sB = 0.0f;

        for (int kc = 0; kc < 4; kc++) {
            float cc[4][8];
#pragma unroll
            for (int kt = 0; kt < 4; kt++)
#pragma unroll
                for (int e = 0; e < 8; e++) cc[kt][e] = 0.0f;

#pragma unroll
            for (int kt = 0; kt < 4; kt++) {
                int kta = kc * 4 + kt;
                uint32_t bh[4], bl[4];
                ldsm4(bh[0], bh[1], bh[2], bh[3], kbh + kta * 768 + krow);
                ldsm4(bl[0], bl[1], bl[2], bl[3], kbl + kta * 768 + krow);
                mma16816(cc[kt], ah, bh[0], bh[1]);
                mma16816(cc[kt] + 4, ah, bh[2], bh[3]);
                mma16816(cc[kt], ah, bl[0], bl[1]);
                mma16816(cc[kt] + 4, ah, bl[2], bl[3]);
                mma16816(cc[kt], al, bh[0], bh[1]);
                mma16816(cc[kt] + 4, al, bh[2], bh[3]);
            }

            float cmA = -1e30f, cmB = -1e30f;
#pragma unroll
            for (int kt = 0; kt < 4; kt++)
#pragma unroll
                for (int t = 0; t < 2; t++) {
                    cmA = fmaxf(cmA, fmaxf(cc[kt][t * 4 + 0], cc[kt][t * 4 + 1]));
                    cmB = fmaxf(cmB, fmaxf(cc[kt][t * 4 + 2], cc[kt][t * 4 + 3]));
                }
            cmA = fmaxf(cmA, __shfl_xor_sync(~0u, cmA, 1));
            cmA = fmaxf(cmA, __shfl_xor_sync(~0u, cmA, 2));
            cmB = fmaxf(cmB, __shfl_xor_sync(~0u, cmB, 1));
            cmB = fmaxf(cmB, __shfl_xor_sync(~0u, cmB, 2));
            cmA *= 0.25f; cmB *= 0.25f;
            float mnA = fmaxf(mA, cmA), mnB = fmaxf(mB, cmB);
            float fA = __expf(mA - mnA), fB = __expf(mB - mnB);
            mA = mnA; mB = mnB;
            sA *= fA; sB *= fB;
#pragma unroll
            for (int t = 0; t < 2; t++) {
                o[t * 4 + 0] *= fA;  o[t * 4 + 1] *= fA;
                o[t * 4 + 2] *= fB;  o[t * 4 + 3] *= fB;
                o2[t * 4 + 0] *= fA; o2[t * 4 + 1] *= fA;
                o2[t * 4 + 2] *= fB; o2[t * 4 + 3] *= fB;
            }

#pragma unroll
            for (int kt = 0; kt < 4; kt++) {
                int kta = kc * 4 + kt;
                float* ot = (kt & 1) ? o2 : o;   // dual accumulators
                float p[8];
#pragma unroll
                for (int t = 0; t < 2; t++) {
                    p[t * 4 + 0] = __expf(cc[kt][t * 4 + 0] * 0.25f - mA);
                    p[t * 4 + 1] = __expf(cc[kt][t * 4 + 1] * 0.25f - mA);
                    p[t * 4 + 2] = __expf(cc[kt][t * 4 + 2] * 0.25f - mB);
                    p[t * 4 + 3] = __expf(cc[kt][t * 4 + 3] * 0.25f - mB);
                    sA += p[t * 4 + 0] + p[t * 4 + 1];
                    sB += p[t * 4 + 2] + p[t * 4 + 3];
                }
                uint32_t ph[4], pl[4];
                split2(p[0], p[1], ph[0], pl[0]);
                split2(p[2], p[3], ph[1], pl[1]);
                split2(p[4], p[5], ph[2], pl[2]);
                split2(p[6], p[7], ph[3], pl[3]);
                uint32_t vh[4], vl[4];
                ldsm4(vh[0], vh[1], vh[2], vh[3], vbh + vrow + kta * 32);
                ldsm4(vl[0], vl[1], vl[2], vl[3], vbl + vrow + kta * 32);
                mma16816(ot, ph, vh[0], vh[1]);
                mma16816(ot + 4, ph, vh[2], vh[3]);
                mma16816(ot, ph, vl[0], vl[1]);
                mma16816(ot + 4, ph, vl[2], vl[3]);
                mma16816(ot, pl, vh[0], vh[1]);
                mma16816(ot + 4, pl, vh[2], vh[3]);
            }
        }

        sA += __shfl_xor_sync(~0u, sA, 1);
        sA += __shfl_xor_sync(~0u, sA, 2);
        sB += __shfl_xor_sync(~0u, sB, 1);
        sB += __shfl_xor_sync(~0u, sB, 2);
        float invA = 1.0f / sA, invB = 1.0f / sB;
#pragma unroll
        for (int e = 0; e < 8; e++) o[e] += o2[e];

        *(float2*)(obase + (size_t)(q0 + g) * H_ + 2 * tg) =
            make_float2(o[0] * invA, o[1] * invA);
        *(float2*)(obase + (size_t)(q0 + g + 8) * H_ + 2 * tg) =
            make_float2(o[2] * invB, o[3] * invB);
        *(float2*)(obase + (size_t)(q0 + g) * H_ + 8 + 2 * tg) =
            make_float2(o[4] * invA, o[5] * invA);
        *(float2*)(obase + (size_t)(q0 + g + 8) * H_ + 8 + 2 * tg) =
            make_float2(o[6] * invB, o[7] * invB);
    }
}

// ---------------------------------------------------------------------------
// Launch
// ---------------------------------------------------------------------------
extern "C" void kernel_launch(void* const* d_in, const int* in_sizes, int n_in,
                              void* d_out, int out_size) {
    const float* x       = (const float*)d_in[0];
    const float* adj_l   = (const float*)d_in[1];
    const float* var_emb = (const float*)d_in[2];
    const float* temp_emb= (const float*)d_in[3];
    const float* mech_W  = (const float*)d_in[4];
    const float* mech_b  = (const float*)d_in[5];
    const float* ln_g    = (const float*)d_in[6];
    const float* ln_b    = (const float*)d_in[7];
    const float* Wq      = (const float*)d_in[8];
    const float* Wk      = (const float*)d_in[9];
    const float* Wv      = (const float*)d_in[10];
    const float* Wo      = (const float*)d_in[11];
    const float* bq      = (const float*)d_in[12];
    const float* bk      = (const float*)d_in[13];
    const float* bv      = (const float*)d_in[14];
    const float* bo      = (const float*)d_in[15];
    const float* out_W   = (const float*)d_in[16];
    const float* out_b   = (const float*)d_in[17];
    float* pred = (float*)d_out;

    float *zA, *qb, *kb, *vb, *ob;
    cudaGetSymbolAddress((void**)&zA, g_zA);
    cudaGetSymbolAddress((void**)&qb, g_qb);
    cudaGetSymbolAddress((void**)&kb, g_kb);
    cudaGetSymbolAddress((void**)&vb, g_vb);
    cudaGetSymbolAddress((void**)&ob, g_ob);

    cudaFuncSetAttribute((const void*)mega_mma,
                         cudaFuncAttributeMaxDynamicSharedMemorySize, MEGA_SMEM);
    cudaFuncSetAttribute((const void*)wo_head_mma,
                         cudaFuncAttributeMaxDynamicSharedMemorySize, G2_SMEM);
    cudaFuncSetAttribute((const void*)prep_w_kernel,
                         cudaFuncAttributeMaxDynamicSharedMemorySize, PREP_SMEM);
    cudaFuncSetAttribute((const void*)causal_kernel,
                         cudaFuncAttributeMaxDynamicSharedMemorySize, CAU_SMEM);
    cudaFuncSetAttribute((const void*)attn_mma,
                         cudaFuncAttributeMaxDynamicSharedMemorySize, ATT_SMEM);

    // 0. sigmoid + weight split
    sigmoid_kernel<<<(V_ * V_ * LP1_ + 255) / 256, 256>>>(adj_l);
    prep_w_kernel<<<7 * V_, 256, PREP_SMEM>>>(mech_W, Wq, Wk, Wv, Wo);

    // 1. causal input -> zA  ([v][bt][h])
    causal_kernel<<<BT_, 256, CAU_SMEM>>>(x, var_emb, temp_emb, zA);

    // 2. MEGA: mech0..2 + Q/K/V, activations resident in smem (512 threads)
    dim3 mgrid(BT_ / 128, V_);
    mega_mma<<<mgrid, 512, MEGA_SMEM>>>(zA, mech_b, ln_g, ln_b,
                                        bq, bk, bv, qb, kb, vb);

    // 3. tensor-core attention -> ob
    attn_mma<<<B_ * V_ * NH_ / 2, 256, ATT_SMEM>>>(qb, kb, vb, ob);

    // 4. Wo + fused output head -> pred
    wo_head_mma<<<mgrid, 256, G2_SMEM>>>(ob, bo, out_W, out_b, pred);
}